// round 1
// baseline (speedup 1.0000x reference)
#include <cuda_runtime.h>
#include <cstdint>

#define C_DIM 128
#define G_DIM 8
#define KNN   16
#define EPS_BN 1e-5f
#define N_CTX_MAX 131072
#define M_Q_MAX   16384

// ---------------- scratch (static device memory; no runtime allocation) -----
__device__ float g_v  [(size_t)N_CTX_MAX * C_DIM];   // v = cf@Wv + bv       (64 MB)
__device__ float g_kw [(size_t)N_CTX_MAX * G_DIM];   // relu(bn(cf@Wk))@Ww1  (4 MB)
__device__ float g_qw [(size_t)M_Q_MAX   * G_DIM];   // relu(bn(qf@Wq))@Ww1
__device__ float g_Wpw[C_DIM * G_DIM];               // Wp2 @ Ww1
__device__ float g_pwb[G_DIM];                       // bp2 @ Ww1

typedef unsigned long long ull;

__device__ __forceinline__ void ffma2(ull& d, ull a, ull b) {
    asm("fma.rn.f32x2 %0, %1, %2, %3;" : "=l"(d) : "l"(a), "l"(b), "l"(d));
}
__device__ __forceinline__ ull pack2(float x) {
    ull r; unsigned u = __float_as_uint(x);
    asm("mov.b64 %0, {%1, %1};" : "=l"(r) : "r"(u));
    return r;
}

// ---------------- K0: tiny prep (Wpw = Wp2@Ww1, pwb = bp2@Ww1) --------------
__global__ void k0_prep(const float* __restrict__ Wp2,
                        const float* __restrict__ Ww1,
                        const float* __restrict__ bp2) {
    int c = threadIdx.x;  // 128 threads
    float acc[G_DIM];
#pragma unroll
    for (int g = 0; g < G_DIM; g++) acc[g] = 0.f;
    for (int c2 = 0; c2 < C_DIM; c2++) {
        float a = Wp2[c * C_DIM + c2];
#pragma unroll
        for (int g = 0; g < G_DIM; g++) acc[g] = fmaf(a, Ww1[c2 * G_DIM + g], acc[g]);
    }
#pragma unroll
    for (int g = 0; g < G_DIM; g++) g_Wpw[c * G_DIM + g] = acc[g];
    if (c < G_DIM) {
        float s = 0.f;
        for (int c2 = 0; c2 < C_DIM; c2++) s = fmaf(bp2[c2], Ww1[c2 * G_DIM + c], s);
        g_pwb[c] = s;
    }
}

// ---------------- K1: context pass -----------------------------------------
// Per 64-row block: 64x256 GEMM (Wk | Wv) with f32x2 FMA, then fused
// relu(bn(.)) -> kw = k@Ww1 (reusing the A smem tile to hold k).
__launch_bounds__(256, 2)
__global__ void k1_context(const float* __restrict__ cf,
                           const float* __restrict__ Wk, const float* __restrict__ bk,
                           const float* __restrict__ gk, const float* __restrict__ betak,
                           const float* __restrict__ Wv, const float* __restrict__ bv,
                           const float* __restrict__ Ww1) {
    __shared__ float As[64][C_DIM];   // 32 KB (A tile, later k tile)
    __shared__ float Bs[16][256];     // 16 KB (B chunk: [Wk | Wv])
    const int tid = threadIdx.x;
    const int bm0 = blockIdx.x * 64;

    for (int i = tid; i < 64 * 32; i += 256) {
        int r = i >> 5, c4 = i & 31;
        *(float4*)&As[r][c4 * 4] = *(const float4*)&cf[(size_t)(bm0 + r) * C_DIM + c4 * 4];
    }
    const int tr = tid >> 5, tc = tid & 31;

    ull acc[8][4];
#pragma unroll
    for (int r = 0; r < 8; r++)
#pragma unroll
        for (int p = 0; p < 4; p++) acc[r][p] = 0ull;

    for (int kc = 0; kc < C_DIM; kc += 16) {
        if (kc) __syncthreads();
        for (int i = tid; i < 16 * 64; i += 256) {
            int kk = i >> 6, j4 = i & 63;
            const float* src = (j4 < 32) ? (Wk + (size_t)(kc + kk) * C_DIM + j4 * 4)
                                         : (Wv + (size_t)(kc + kk) * C_DIM + (j4 - 32) * 4);
            *(float4*)&Bs[kk][j4 * 4] = *(const float4*)src;
        }
        __syncthreads();
#pragma unroll
        for (int k4 = 0; k4 < 16; k4 += 4) {
            float4 a4[8];
#pragma unroll
            for (int r = 0; r < 8; r++) a4[r] = *(const float4*)&As[tr * 8 + r][kc + k4];
#pragma unroll
            for (int u = 0; u < 4; u++) {
                ull bp[4];
#pragma unroll
                for (int p = 0; p < 4; p++) bp[p] = *(const ull*)&Bs[k4 + u][tc * 8 + 2 * p];
#pragma unroll
                for (int r = 0; r < 8; r++) {
                    float av = (&a4[r].x)[u];
                    ull ap = pack2(av);
#pragma unroll
                    for (int p = 0; p < 4; p++) ffma2(acc[r][p], ap, bp[p]);
                }
            }
        }
    }
    __syncthreads();

    const float rs = rsqrtf(1.f + EPS_BN);
    if (tc < 16) {  // k half -> relu(bn) -> stash in As
#pragma unroll
        for (int r = 0; r < 8; r++) {
            int row = tr * 8 + r;
#pragma unroll
            for (int p = 0; p < 4; p++) {
                int j0 = tc * 8 + 2 * p;
                float lo = __uint_as_float((unsigned)acc[r][p]);
                float hi = __uint_as_float((unsigned)(acc[r][p] >> 32));
                As[row][j0]     = fmaxf(fmaf(lo + bk[j0],     gk[j0]     * rs, betak[j0]),     0.f);
                As[row][j0 + 1] = fmaxf(fmaf(hi + bk[j0 + 1], gk[j0 + 1] * rs, betak[j0 + 1]), 0.f);
            }
        }
    } else {        // v half -> + bv -> global
#pragma unroll
        for (int r = 0; r < 8; r++) {
            int row = bm0 + tr * 8 + r;
#pragma unroll
            for (int p = 0; p < 4; p++) {
                int vc = (tc - 16) * 8 + 2 * p;
                float lo = __uint_as_float((unsigned)acc[r][p]);
                float hi = __uint_as_float((unsigned)(acc[r][p] >> 32));
                float2 o; o.x = lo + bv[vc]; o.y = hi + bv[vc + 1];
                *(float2*)&g_v[(size_t)row * C_DIM + vc] = o;
            }
        }
    }
    __syncthreads();

    // kw = k @ Ww1  (64 rows x 8 groups; k in As)
#pragma unroll
    for (int s2 = 0; s2 < 2; s2++) {
        int task = tid + s2 * 256;
        int row = task >> 3, g = task & 7;
        float a = 0.f;
#pragma unroll 8
        for (int c = 0; c < C_DIM; c++) a = fmaf(As[row][c], Ww1[c * G_DIM + g], a);
        g_kw[(size_t)(bm0 + row) * G_DIM + g] = a;
    }
}

// ---------------- K2: query pass (qw only) ----------------------------------
__launch_bounds__(256, 2)
__global__ void k2_query(const float* __restrict__ qf,
                         const float* __restrict__ Wq, const float* __restrict__ bq,
                         const float* __restrict__ gq, const float* __restrict__ betaq,
                         const float* __restrict__ Ww1) {
    __shared__ float As[64][C_DIM];   // 32 KB
    __shared__ float Bs[16][C_DIM];   //  8 KB
    const int tid = threadIdx.x;
    const int bm0 = blockIdx.x * 64;

    for (int i = tid; i < 64 * 32; i += 256) {
        int r = i >> 5, c4 = i & 31;
        *(float4*)&As[r][c4 * 4] = *(const float4*)&qf[(size_t)(bm0 + r) * C_DIM + c4 * 4];
    }
    const int tr = tid >> 4, tc = tid & 15;

    ull acc[4][4];
#pragma unroll
    for (int r = 0; r < 4; r++)
#pragma unroll
        for (int p = 0; p < 4; p++) acc[r][p] = 0ull;

    for (int kc = 0; kc < C_DIM; kc += 16) {
        if (kc) __syncthreads();
        for (int i = tid; i < 16 * 32; i += 256) {
            int kk = i >> 5, j4 = i & 31;
            *(float4*)&Bs[kk][j4 * 4] = *(const float4*)&Wq[(size_t)(kc + kk) * C_DIM + j4 * 4];
        }
        __syncthreads();
#pragma unroll
        for (int k4 = 0; k4 < 16; k4 += 4) {
            float4 a4[4];
#pragma unroll
            for (int r = 0; r < 4; r++) a4[r] = *(const float4*)&As[tr * 4 + r][kc + k4];
#pragma unroll
            for (int u = 0; u < 4; u++) {
                ull bp[4];
#pragma unroll
                for (int p = 0; p < 4; p++) bp[p] = *(const ull*)&Bs[k4 + u][tc * 8 + 2 * p];
#pragma unroll
                for (int r = 0; r < 4; r++) {
                    ull ap = pack2((&a4[r].x)[u]);
#pragma unroll
                    for (int p = 0; p < 4; p++) ffma2(acc[r][p], ap, bp[p]);
                }
            }
        }
    }
    __syncthreads();

    const float rs = rsqrtf(1.f + EPS_BN);
#pragma unroll
    for (int r = 0; r < 4; r++) {
        int row = tr * 4 + r;
#pragma unroll
        for (int p = 0; p < 4; p++) {
            int j0 = tc * 8 + 2 * p;
            float lo = __uint_as_float((unsigned)acc[r][p]);
            float hi = __uint_as_float((unsigned)(acc[r][p] >> 32));
            As[row][j0]     = fmaxf(fmaf(lo + bq[j0],     gq[j0]     * rs, betaq[j0]),     0.f);
            As[row][j0 + 1] = fmaxf(fmaf(hi + bq[j0 + 1], gq[j0 + 1] * rs, betaq[j0 + 1]), 0.f);
        }
    }
    __syncthreads();
#pragma unroll
    for (int s2 = 0; s2 < 2; s2++) {
        int task = tid + s2 * 256;
        int row = task >> 3, g = task & 7;
        float a = 0.f;
#pragma unroll 8
        for (int c = 0; c < C_DIM; c++) a = fmaf(As[row][c], Ww1[c * G_DIM + g], a);
        g_qw[(size_t)(bm0 + row) * G_DIM + g] = a;
    }
}

// ---------------- K3: attention + pooled output ------------------------------
struct S3 {
    float Wp2s[C_DIM * C_DIM];   // 64 KB
    float Wpws[C_DIM * G_DIM];   // 4 KB
    float hs[KNN * 132];         // h, padded stride vs bank conflicts
    float Hs[G_DIM * 132];       // Hsum[g][c]
    float pos[KNN * 4];
    float kwg[KNN * G_DIM];
    float ts[KNN * G_DIM];
    float lg[KNN * G_DIM];
    float ws[KNN * G_DIM];
    float qw[G_DIM];
    float wsum[G_DIM];
    float msk[KNN];
    int   idx[KNN];
};

__launch_bounds__(128, 2)
__global__ void k3_attn(const float* __restrict__ qcoord, const float* __restrict__ ccoord,
                        const int*   __restrict__ knn,
                        const float* __restrict__ Wp1, const float* __restrict__ bp1,
                        const float* __restrict__ gp1, const float* __restrict__ betap1,
                        const float* __restrict__ Wp2, const float* __restrict__ bp2,
                        const float* __restrict__ bw1, const float* __restrict__ gw1,
                        const float* __restrict__ betaw1,
                        const float* __restrict__ Ww2, const float* __restrict__ bw2,
                        float* __restrict__ out) {
    extern __shared__ char raw[];
    S3* s = (S3*)raw;
    const int tid = threadIdx.x;
    const int c = tid, gc = c >> 4;          // role A: channel owner
    const int kB = tid >> 3, gB = tid & 7;   // role B: (neighbor, group)

    for (int i = tid; i < C_DIM * C_DIM; i += 128) s->Wp2s[i] = Wp2[i];
    for (int i = tid; i < C_DIM * G_DIM; i += 128) s->Wpws[i] = g_Wpw[i];

    const float rs  = rsqrtf(1.f + EPS_BN);
    const float sp1 = gp1[c] * rs;
    const float wf0 = Wp1[c] * sp1, wf1 = Wp1[C_DIM + c] * sp1, wf2 = Wp1[2 * C_DIM + c] * sp1;
    const float hb  = fmaf(bp1[c], sp1, betap1[c]);
    const float bp2c = bp2[c];
    const float sw1  = gw1[gB] * rs;
    const float wb1f = fmaf(bw1[gB], sw1, betaw1[gB]);
    const float pwbB = g_pwb[gB];
    float ww2r[G_DIM];
#pragma unroll
    for (int g2 = 0; g2 < G_DIM; g2++) ww2r[g2] = Ww2[g2 * G_DIM + gB];
    const float bw2B = bw2[gB];
    __syncthreads();

    for (int qi = 0; qi < 8; qi++) {
        const int m = blockIdx.x * 8 + qi;
        __syncthreads();
        if (tid < KNN) {
            int k = tid;
            int id = knn[(size_t)m * KNN + k];
            float mk = id >= 0 ? 1.f : 0.f;
            int id0 = id >= 0 ? id : 0;
            s->idx[k] = id0; s->msk[k] = mk;
            float qx = qcoord[m * 3 + 0], qy = qcoord[m * 3 + 1], qz = qcoord[m * 3 + 2];
            s->pos[k * 4 + 0] = (ccoord[(size_t)id0 * 3 + 0] - qx) * mk;
            s->pos[k * 4 + 1] = (ccoord[(size_t)id0 * 3 + 1] - qy) * mk;
            s->pos[k * 4 + 2] = (ccoord[(size_t)id0 * 3 + 2] - qz) * mk;
            const float4* kwp = (const float4*)&g_kw[(size_t)id0 * G_DIM];
            float4 a = kwp[0], b = kwp[1];
            s->kwg[k * 8 + 0] = a.x * mk; s->kwg[k * 8 + 1] = a.y * mk;
            s->kwg[k * 8 + 2] = a.z * mk; s->kwg[k * 8 + 3] = a.w * mk;
            s->kwg[k * 8 + 4] = b.x * mk; s->kwg[k * 8 + 5] = b.y * mk;
            s->kwg[k * 8 + 6] = b.z * mk; s->kwg[k * 8 + 7] = b.w * mk;
        }
        if (tid < G_DIM) s->qw[tid] = g_qw[(size_t)m * G_DIM + tid];
        __syncthreads();

        // early v-gather prefetch (hide L2 latency under compute)
        float vpre[KNN];
#pragma unroll
        for (int k = 0; k < KNN; k++) vpre[k] = g_v[(size_t)s->idx[k] * C_DIM + c];

        // h = relu(bn(pos @ Wp1))  -- folded
        float hreg[KNN];
#pragma unroll
        for (int k = 0; k < KNN; k++) {
            const float* pp = &s->pos[k * 4];
            float d = fmaf(wf0, pp[0], fmaf(wf1, pp[1], fmaf(wf2, pp[2], hb)));
            float h = fmaxf(d, 0.f);
            hreg[k] = h;
            s->hs[k * 132 + c] = h;
        }
        __syncthreads();

        // t = relu(bn(rel@Ww1 + bw1)) via decomposition
        {
            float a = s->kwg[tid] - s->qw[gB] + pwbB;
            const float* hr = &s->hs[kB * 132];
#pragma unroll 8
            for (int c2 = 0; c2 < C_DIM; c2++) a = fmaf(hr[c2], s->Wpws[c2 * G_DIM + gB], a);
            s->ts[tid] = fmaxf(fmaf(a, sw1, wb1f), 0.f);
        }
        __syncthreads();
        {
            float a = bw2B;
#pragma unroll
            for (int g2 = 0; g2 < G_DIM; g2++) a = fmaf(s->ts[kB * 8 + g2], ww2r[g2], a);
            s->lg[tid] = a;
        }
        __syncthreads();

        // softmax over K per group, then mask
        if (tid < G_DIM) {
            float mx = -1e30f;
#pragma unroll
            for (int k = 0; k < KNN; k++) mx = fmaxf(mx, s->lg[k * 8 + tid]);
            float e[KNN], sum = 0.f;
#pragma unroll
            for (int k = 0; k < KNN; k++) { e[k] = __expf(s->lg[k * 8 + tid] - mx); sum += e[k]; }
            float inv = 1.f / sum, wsm = 0.f;
#pragma unroll
            for (int k = 0; k < KNN; k++) {
                float w = e[k] * inv * s->msk[k];
                s->ws[k * 8 + tid] = w; wsm += w;
            }
            s->wsum[tid] = wsm;
        }
        __syncthreads();

        // out = sum_k v*w  +  Hsum @ Wp2 col  +  bp2 * wsum
        float accv = 0.f;
#pragma unroll
        for (int k = 0; k < KNN; k++) accv = fmaf(vpre[k], s->ws[k * 8 + gc], accv);

        float hh[G_DIM];
#pragma unroll
        for (int g2 = 0; g2 < G_DIM; g2++) hh[g2] = 0.f;
#pragma unroll
        for (int k = 0; k < KNN; k++) {
            float h = hreg[k];
#pragma unroll
            for (int g2 = 0; g2 < G_DIM; g2++) hh[g2] = fmaf(h, s->ws[k * 8 + g2], hh[g2]);
        }
#pragma unroll
        for (int g2 = 0; g2 < G_DIM; g2++) s->Hs[g2 * 132 + c] = hh[g2];
        __syncthreads();

        float accp = bp2c * s->wsum[gc];
        const float* hsr = &s->Hs[gc * 132];
#pragma unroll 8
        for (int c2 = 0; c2 < C_DIM; c2++) accp = fmaf(hsr[c2], s->Wp2s[c2 * C_DIM + c], accp);

        out[(size_t)m * C_DIM + c] = accv + accp;
    }
}

// ---------------- launch -----------------------------------------------------
extern "C" void kernel_launch(void* const* d_in, const int* in_sizes, int n_in,
                              void* d_out, int out_size) {
    const float* qf     = (const float*)d_in[0];
    const float* cf     = (const float*)d_in[1];
    const float* qc     = (const float*)d_in[2];
    const float* cc     = (const float*)d_in[3];
    const float* Wq     = (const float*)d_in[4];
    const float* bq     = (const float*)d_in[5];
    const float* gq     = (const float*)d_in[6];
    const float* betaq  = (const float*)d_in[7];
    const float* Wk     = (const float*)d_in[8];
    const float* bk     = (const float*)d_in[9];
    const float* gk     = (const float*)d_in[10];
    const float* betak  = (const float*)d_in[11];
    const float* Wv     = (const float*)d_in[12];
    const float* bv     = (const float*)d_in[13];
    const float* Wp1    = (const float*)d_in[14];
    const float* bp1    = (const float*)d_in[15];
    const float* gp1    = (const float*)d_in[16];
    const float* betap1 = (const float*)d_in[17];
    const float* Wp2    = (const float*)d_in[18];
    const float* bp2    = (const float*)d_in[19];
    const float* Ww1    = (const float*)d_in[20];
    const float* bw1    = (const float*)d_in[21];
    const float* gw1    = (const float*)d_in[22];
    const float* betaw1 = (const float*)d_in[23];
    const float* Ww2    = (const float*)d_in[24];
    const float* bw2    = (const float*)d_in[25];
    const int*   knn    = (const int*)d_in[26];
    float* out = (float*)d_out;

    const int M = in_sizes[0] / C_DIM;
    const int N = in_sizes[1] / C_DIM;

    k0_prep<<<1, 128>>>(Wp2, Ww1, bp2);
    k1_context<<<N / 64, 256>>>(cf, Wk, bk, gk, betak, Wv, bv, Ww1);
    k2_query<<<M / 64, 256>>>(qf, Wq, bq, gq, betaq, Ww1);

    int smem3 = (int)sizeof(S3);
    cudaFuncSetAttribute(k3_attn, cudaFuncAttributeMaxDynamicSharedMemorySize, smem3);
    k3_attn<<<M / 8, 128, smem3>>>(qc, cc, knn, Wp1, bp1, gp1, betap1,
                                   Wp2, bp2, bw1, gw1, betaw1, Ww2, bw2, out);
}

// round 2
// speedup vs baseline: 1.1805x; 1.1805x over previous
#include <cuda_runtime.h>
#include <cstdint>

#define C_DIM 128
#define G_DIM 8
#define KNN   16
#define EPS_BN 1e-5f
#define N_CTX_MAX 131072
#define M_Q_MAX   16384

// ---------------- scratch (static device memory; no runtime allocation) -----
__device__ float g_v   [(size_t)N_CTX_MAX * C_DIM];   // v = cf@Wv + bv       (64 MB)
__device__ float g_kw  [(size_t)N_CTX_MAX * G_DIM];   // relu(bn(cf@Wk))@Ww1  (4 MB)
__device__ float g_qw  [(size_t)M_Q_MAX   * G_DIM];   // relu(bn(qf@Wq))@Ww1
__device__ float g_WpwT[G_DIM * C_DIM];               // [g][c2] = (Wp2@Ww1)[c2][g]
__device__ float g_Wp2T[C_DIM * C_DIM];               // [c][c2] = Wp2[c2][c]
__device__ float g_pwb [G_DIM];                       // bp2 @ Ww1

typedef unsigned long long ull;

__device__ __forceinline__ void ffma2(ull& d, ull a, ull b) {
    asm("fma.rn.f32x2 %0, %1, %2, %3;" : "=l"(d) : "l"(a), "l"(b), "l"(d));
}
__device__ __forceinline__ ull pack2(float x) {
    ull r; unsigned u = __float_as_uint(x);
    asm("mov.b64 %0, {%1, %1};" : "=l"(r) : "r"(u));
    return r;
}

// ---------------- K0: tiny prep ---------------------------------------------
__global__ void k0_prep(const float* __restrict__ Wp2,
                        const float* __restrict__ Ww1,
                        const float* __restrict__ bp2) {
    int c = threadIdx.x;  // 128 threads
    float acc[G_DIM];
#pragma unroll
    for (int g = 0; g < G_DIM; g++) acc[g] = 0.f;
    for (int c2 = 0; c2 < C_DIM; c2++) {
        float a = Wp2[c * C_DIM + c2];
#pragma unroll
        for (int g = 0; g < G_DIM; g++) acc[g] = fmaf(a, Ww1[c2 * G_DIM + g], acc[g]);
    }
#pragma unroll
    for (int g = 0; g < G_DIM; g++) g_WpwT[g * C_DIM + c] = acc[g];
    for (int c2 = 0; c2 < C_DIM; c2++)
        g_Wp2T[c * C_DIM + c2] = Wp2[c2 * C_DIM + c];
    if (c < G_DIM) {
        float s = 0.f;
        for (int c2 = 0; c2 < C_DIM; c2++) s = fmaf(bp2[c2], Ww1[c2 * G_DIM + c], s);
        g_pwb[c] = s;
    }
}

// ---------------- K1: context pass (unchanged, near FFMA2 roofline) ----------
__launch_bounds__(256, 2)
__global__ void k1_context(const float* __restrict__ cf,
                           const float* __restrict__ Wk, const float* __restrict__ bk,
                           const float* __restrict__ gk, const float* __restrict__ betak,
                           const float* __restrict__ Wv, const float* __restrict__ bv,
                           const float* __restrict__ Ww1) {
    __shared__ float As[64][C_DIM];
    __shared__ float Bs[16][256];
    const int tid = threadIdx.x;
    const int bm0 = blockIdx.x * 64;

    for (int i = tid; i < 64 * 32; i += 256) {
        int r = i >> 5, c4 = i & 31;
        *(float4*)&As[r][c4 * 4] = *(const float4*)&cf[(size_t)(bm0 + r) * C_DIM + c4 * 4];
    }
    const int tr = tid >> 5, tc = tid & 31;

    ull acc[8][4];
#pragma unroll
    for (int r = 0; r < 8; r++)
#pragma unroll
        for (int p = 0; p < 4; p++) acc[r][p] = 0ull;

    for (int kc = 0; kc < C_DIM; kc += 16) {
        if (kc) __syncthreads();
        for (int i = tid; i < 16 * 64; i += 256) {
            int kk = i >> 6, j4 = i & 63;
            const float* src = (j4 < 32) ? (Wk + (size_t)(kc + kk) * C_DIM + j4 * 4)
                                         : (Wv + (size_t)(kc + kk) * C_DIM + (j4 - 32) * 4);
            *(float4*)&Bs[kk][j4 * 4] = *(const float4*)src;
        }
        __syncthreads();
#pragma unroll
        for (int k4 = 0; k4 < 16; k4 += 4) {
            float4 a4[8];
#pragma unroll
            for (int r = 0; r < 8; r++) a4[r] = *(const float4*)&As[tr * 8 + r][kc + k4];
#pragma unroll
            for (int u = 0; u < 4; u++) {
                ull bp[4];
#pragma unroll
                for (int p = 0; p < 4; p++) bp[p] = *(const ull*)&Bs[k4 + u][tc * 8 + 2 * p];
#pragma unroll
                for (int r = 0; r < 8; r++) {
                    float av = (&a4[r].x)[u];
                    ull ap = pack2(av);
#pragma unroll
                    for (int p = 0; p < 4; p++) ffma2(acc[r][p], ap, bp[p]);
                }
            }
        }
    }
    __syncthreads();

    const float rs = rsqrtf(1.f + EPS_BN);
    if (tc < 16) {
#pragma unroll
        for (int r = 0; r < 8; r++) {
            int row = tr * 8 + r;
#pragma unroll
            for (int p = 0; p < 4; p++) {
                int j0 = tc * 8 + 2 * p;
                float lo = __uint_as_float((unsigned)acc[r][p]);
                float hi = __uint_as_float((unsigned)(acc[r][p] >> 32));
                As[row][j0]     = fmaxf(fmaf(lo + bk[j0],     gk[j0]     * rs, betak[j0]),     0.f);
                As[row][j0 + 1] = fmaxf(fmaf(hi + bk[j0 + 1], gk[j0 + 1] * rs, betak[j0 + 1]), 0.f);
            }
        }
    } else {
#pragma unroll
        for (int r = 0; r < 8; r++) {
            int row = bm0 + tr * 8 + r;
#pragma unroll
            for (int p = 0; p < 4; p++) {
                int vc = (tc - 16) * 8 + 2 * p;
                float lo = __uint_as_float((unsigned)acc[r][p]);
                float hi = __uint_as_float((unsigned)(acc[r][p] >> 32));
                float2 o; o.x = lo + bv[vc]; o.y = hi + bv[vc + 1];
                *(float2*)&g_v[(size_t)row * C_DIM + vc] = o;
            }
        }
    }
    __syncthreads();

#pragma unroll
    for (int s2 = 0; s2 < 2; s2++) {
        int task = tid + s2 * 256;
        int row = task >> 3, g = task & 7;
        float a = 0.f;
#pragma unroll 8
        for (int c = 0; c < C_DIM; c++) a = fmaf(As[row][c], Ww1[c * G_DIM + g], a);
        g_kw[(size_t)(bm0 + row) * G_DIM + g] = a;
    }
}

// ---------------- K2: query pass (unchanged) ---------------------------------
__launch_bounds__(256, 2)
__global__ void k2_query(const float* __restrict__ qf,
                         const float* __restrict__ Wq, const float* __restrict__ bq,
                         const float* __restrict__ gq, const float* __restrict__ betaq,
                         const float* __restrict__ Ww1) {
    __shared__ float As[64][C_DIM];
    __shared__ float Bs[16][C_DIM];
    const int tid = threadIdx.x;
    const int bm0 = blockIdx.x * 64;

    for (int i = tid; i < 64 * 32; i += 256) {
        int r = i >> 5, c4 = i & 31;
        *(float4*)&As[r][c4 * 4] = *(const float4*)&qf[(size_t)(bm0 + r) * C_DIM + c4 * 4];
    }
    const int tr = tid >> 4, tc = tid & 15;

    ull acc[4][4];
#pragma unroll
    for (int r = 0; r < 4; r++)
#pragma unroll
        for (int p = 0; p < 4; p++) acc[r][p] = 0ull;

    for (int kc = 0; kc < C_DIM; kc += 16) {
        if (kc) __syncthreads();
        for (int i = tid; i < 16 * 32; i += 256) {
            int kk = i >> 5, j4 = i & 31;
            *(float4*)&Bs[kk][j4 * 4] = *(const float4*)&Wq[(size_t)(kc + kk) * C_DIM + j4 * 4];
        }
        __syncthreads();
#pragma unroll
        for (int k4 = 0; k4 < 16; k4 += 4) {
            float4 a4[4];
#pragma unroll
            for (int r = 0; r < 4; r++) a4[r] = *(const float4*)&As[tr * 4 + r][kc + k4];
#pragma unroll
            for (int u = 0; u < 4; u++) {
                ull bp[4];
#pragma unroll
                for (int p = 0; p < 4; p++) bp[p] = *(const ull*)&Bs[k4 + u][tc * 8 + 2 * p];
#pragma unroll
                for (int r = 0; r < 4; r++) {
                    ull ap = pack2((&a4[r].x)[u]);
#pragma unroll
                    for (int p = 0; p < 4; p++) ffma2(acc[r][p], ap, bp[p]);
                }
            }
        }
    }
    __syncthreads();

    const float rs = rsqrtf(1.f + EPS_BN);
#pragma unroll
    for (int r = 0; r < 4; r++) {
        int row = tr * 4 + r;
#pragma unroll
        for (int p = 0; p < 4; p++) {
            int j0 = tc * 8 + 2 * p;
            float lo = __uint_as_float((unsigned)acc[r][p]);
            float hi = __uint_as_float((unsigned)(acc[r][p] >> 32));
            As[row][j0]     = fmaxf(fmaf(lo + bq[j0],     gq[j0]     * rs, betaq[j0]),     0.f);
            As[row][j0 + 1] = fmaxf(fmaf(hi + bq[j0 + 1], gq[j0 + 1] * rs, betaq[j0 + 1]), 0.f);
        }
    }
    __syncthreads();
#pragma unroll
    for (int s2 = 0; s2 < 2; s2++) {
        int task = tid + s2 * 256;
        int row = task >> 3, g = task & 7;
        float a = 0.f;
#pragma unroll 8
        for (int c = 0; c < C_DIM; c++) a = fmaf(As[row][c], Ww1[c * G_DIM + g], a);
        g_qw[(size_t)(bm0 + row) * G_DIM + g] = a;
    }
}

// ---------------- K3: attention + pooled output (v2) -------------------------
// 256 threads = 2 query slots of 128 threads; 8 sequential queries per slot.
// 3 __syncthreads per query; ILP-4 float4 dots; shuffle-based group mixing;
// next-query gather chain software-pipelined into current P2.
struct S3Slot {
    float hs[KNN * 132];        // 8448  h per (k, c)
    float Hs[G_DIM * 132];      // 4224  unnormalized Hsum[g][c]
    float e_s[KNN * G_DIM];     // 512   exp(logits)
    float psum[4 * G_DIM];      // 128   per-warp partial exp sums
    float wsum[G_DIM];          // 32    unnormalized masked weight sums
    float pos[2][KNN * 4];      // 512   (double-buffered gather)
    float kwg[2][KNN * G_DIM];  // 1024
    float qw[2][G_DIM];         // 64
    float msk[2][KNN];          // 128
    int   idx[2][KNN];          // 128
};
struct S3 {
    float Wp2T[C_DIM * 132];    // 67584  Wp2 transposed, padded rows
    float WpwT[G_DIM * 132];    // 4224
    float ww2s[G_DIM * G_DIM];  // 256
    S3Slot sl[2];               // 2 x 15200
};

__device__ __forceinline__ void gatherK(S3Slot* sl, const int* __restrict__ knn,
                                        const float* __restrict__ qcoord,
                                        const float* __restrict__ ccoord,
                                        int m, int p, int k) {
    int id = knn[(size_t)m * KNN + k];
    float mk = id >= 0 ? 1.f : 0.f;
    int id0 = id >= 0 ? id : 0;
    sl->idx[p][k] = id0;
    sl->msk[p][k] = mk;
    float qx = qcoord[m * 3 + 0], qy = qcoord[m * 3 + 1], qz = qcoord[m * 3 + 2];
    sl->pos[p][k * 4 + 0] = (ccoord[(size_t)id0 * 3 + 0] - qx) * mk;
    sl->pos[p][k * 4 + 1] = (ccoord[(size_t)id0 * 3 + 1] - qy) * mk;
    sl->pos[p][k * 4 + 2] = (ccoord[(size_t)id0 * 3 + 2] - qz) * mk;
    const float4* kwp = (const float4*)&g_kw[(size_t)id0 * G_DIM];
    float4 a = kwp[0], b = kwp[1];
    float* kd = &sl->kwg[p][k * 8];
    kd[0] = a.x * mk; kd[1] = a.y * mk; kd[2] = a.z * mk; kd[3] = a.w * mk;
    kd[4] = b.x * mk; kd[5] = b.y * mk; kd[6] = b.z * mk; kd[7] = b.w * mk;
}

__launch_bounds__(256, 2)
__global__ void k3_attn(const float* __restrict__ qcoord, const float* __restrict__ ccoord,
                        const int*   __restrict__ knn,
                        const float* __restrict__ Wp1, const float* __restrict__ bp1,
                        const float* __restrict__ gp1, const float* __restrict__ betap1,
                        const float* __restrict__ bp2,
                        const float* __restrict__ bw1, const float* __restrict__ gw1,
                        const float* __restrict__ betaw1,
                        const float* __restrict__ Ww2, const float* __restrict__ bw2,
                        float* __restrict__ out) {
    extern __shared__ char raw[];
    S3* s = (S3*)raw;
    const int tid  = threadIdx.x;
    const int slot = tid >> 7;
    const int t    = tid & 127;
    S3Slot* sl = &s->sl[slot];
    const int c  = t, gc = t >> 4;          // role A: channel owner
    const int kB = t >> 3, gB = t & 7;      // role B: (neighbor, group)
    const int w4 = t >> 5;                  // warp within slot
    const int lane  = t & 31;
    const int lbase = lane & ~7;

    for (int i = tid; i < C_DIM * C_DIM; i += 256) {
        int r = i >> 7, cc2 = i & 127;
        s->Wp2T[r * 132 + cc2] = g_Wp2T[i];
    }
    for (int i = tid; i < G_DIM * C_DIM; i += 256) {
        int r = i >> 7, cc2 = i & 127;
        s->WpwT[r * 132 + cc2] = g_WpwT[i];
    }
    if (tid < G_DIM * G_DIM) s->ww2s[tid] = Ww2[tid];

    const float rs  = rsqrtf(1.f + EPS_BN);
    const float sp1 = gp1[c] * rs;
    const float wf0 = Wp1[c] * sp1, wf1 = Wp1[C_DIM + c] * sp1, wf2 = Wp1[2 * C_DIM + c] * sp1;
    const float hb  = fmaf(bp1[c], sp1, betap1[c]);
    const float bp2c = bp2[c];
    const float sw1  = gw1[gB] * rs;
    const float wb1f = fmaf(bw1[gB], sw1, betaw1[gB]);
    const float pwbB = g_pwb[gB];
    const float bw2B = bw2[gB];

    const int mb = blockIdx.x * 16 + slot;

    // prologue: gather query 0 of this slot
    if (t < KNN)   gatherK(sl, knn, qcoord, ccoord, mb, 0, t);
    if (t < G_DIM) sl->qw[0][t] = g_qw[(size_t)mb * G_DIM + t];
    __syncthreads();

    for (int qi = 0; qi < 8; qi++) {
        const int p = qi & 1;
        const int m = mb + qi * 2;

        // ---- P2: pipeline next gather; v prefetch; h compute ----
        if (qi < 7) {
            if (t < KNN)   gatherK(sl, knn, qcoord, ccoord, m + 2, p ^ 1, t);
            if (t < G_DIM) sl->qw[p ^ 1][t] = g_qw[(size_t)(m + 2) * G_DIM + t];
        }

        float vpre[KNN];
        {
            const int* ix = sl->idx[p];
#pragma unroll
            for (int k = 0; k < KNN; k++) vpre[k] = g_v[(size_t)ix[k] * C_DIM + c];
        }

        float hreg[KNN];
#pragma unroll
        for (int k = 0; k < KNN; k++) {
            const float* pp = &sl->pos[p][k * 4];
            float h = fmaxf(fmaf(wf0, pp[0], fmaf(wf1, pp[1], fmaf(wf2, pp[2], hb))), 0.f);
            hreg[k] = h;
            sl->hs[k * 132 + c] = h;
        }
        __syncthreads();

        // ---- P3: logits, exp, partial sums (role B) ----
        {
            float a0 = sl->kwg[p][t] - sl->qw[p][gB] + pwbB;
            float a1 = 0.f, a2 = 0.f, a3 = 0.f;
            const float4* hr = (const float4*)&sl->hs[kB * 132];
            const float4* wr = (const float4*)&s->WpwT[gB * 132];
#pragma unroll
            for (int j = 0; j < 32; j += 4) {
                float4 h0 = hr[j],     w0 = wr[j];
                float4 h1 = hr[j + 1], w1 = wr[j + 1];
                float4 h2 = hr[j + 2], w2 = wr[j + 2];
                float4 h3 = hr[j + 3], w3 = wr[j + 3];
                a0 = fmaf(h0.x, w0.x, fmaf(h0.y, w0.y, fmaf(h0.z, w0.z, fmaf(h0.w, w0.w, a0))));
                a1 = fmaf(h1.x, w1.x, fmaf(h1.y, w1.y, fmaf(h1.z, w1.z, fmaf(h1.w, w1.w, a1))));
                a2 = fmaf(h2.x, w2.x, fmaf(h2.y, w2.y, fmaf(h2.z, w2.z, fmaf(h2.w, w2.w, a2))));
                a3 = fmaf(h3.x, w3.x, fmaf(h3.y, w3.y, fmaf(h3.z, w3.z, fmaf(h3.w, w3.w, a3))));
            }
            float ts = fmaxf(fmaf((a0 + a1) + (a2 + a3), sw1, wb1f), 0.f);

            float lg = bw2B;
#pragma unroll
            for (int g2 = 0; g2 < G_DIM; g2++)
                lg = fmaf(__shfl_sync(0xffffffffu, ts, lbase + g2), s->ww2s[g2 * G_DIM + gB], lg);

            float e = __expf(lg);   // logits are O(1): exact softmax, no max shift needed
            sl->e_s[kB * 8 + gB] = e;
            float es = e;
            es += __shfl_xor_sync(0xffffffffu, es, 8);
            es += __shfl_xor_sync(0xffffffffu, es, 16);
            if (lane < 8) sl->psum[w4 * 8 + gB] = es;
        }
        __syncthreads();

        // ---- P4: weighted sums (role A) ----
        float sums = sl->psum[gc] + sl->psum[8 + gc] + sl->psum[16 + gc] + sl->psum[24 + gc];
        float inv = 1.f / sums;
        float accv = 0.f;
        float hh[G_DIM];
#pragma unroll
        for (int g2 = 0; g2 < G_DIM; g2++) hh[g2] = 0.f;
#pragma unroll
        for (int k = 0; k < KNN; k++) {
            float mk = sl->msk[p][k];
            float ev = sl->e_s[k * 8 + gc];
            accv = fmaf(vpre[k] * mk, ev, accv);
            float hm = hreg[k] * mk;
            float4 ea = *(const float4*)&sl->e_s[k * 8];
            float4 eb = *(const float4*)&sl->e_s[k * 8 + 4];
            hh[0] = fmaf(hm, ea.x, hh[0]); hh[1] = fmaf(hm, ea.y, hh[1]);
            hh[2] = fmaf(hm, ea.z, hh[2]); hh[3] = fmaf(hm, ea.w, hh[3]);
            hh[4] = fmaf(hm, eb.x, hh[4]); hh[5] = fmaf(hm, eb.y, hh[5]);
            hh[6] = fmaf(hm, eb.z, hh[6]); hh[7] = fmaf(hm, eb.w, hh[7]);
        }
#pragma unroll
        for (int g2 = 0; g2 < G_DIM; g2++) sl->Hs[g2 * 132 + c] = hh[g2];
        if (t < G_DIM) {
            float ws = 0.f;
#pragma unroll
            for (int k = 0; k < KNN; k++) ws += sl->e_s[k * 8 + t] * sl->msk[p][k];
            sl->wsum[t] = ws;
        }
        __syncthreads();

        // ---- P5: epilogue contraction ----
        {
            float b0 = 0.f, b1 = 0.f, b2 = 0.f, b3 = 0.f;
            const float4* hr = (const float4*)&sl->Hs[gc * 132];
            const float4* wr = (const float4*)&s->Wp2T[c * 132];
#pragma unroll
            for (int j = 0; j < 32; j += 4) {
                float4 h0 = hr[j],     w0 = wr[j];
                float4 h1 = hr[j + 1], w1 = wr[j + 1];
                float4 h2 = hr[j + 2], w2 = wr[j + 2];
                float4 h3 = hr[j + 3], w3 = wr[j + 3];
                b0 = fmaf(h0.x, w0.x, fmaf(h0.y, w0.y, fmaf(h0.z, w0.z, fmaf(h0.w, w0.w, b0))));
                b1 = fmaf(h1.x, w1.x, fmaf(h1.y, w1.y, fmaf(h1.z, w1.z, fmaf(h1.w, w1.w, b1))));
                b2 = fmaf(h2.x, w2.x, fmaf(h2.y, w2.y, fmaf(h2.z, w2.z, fmaf(h2.w, w2.w, b2))));
                b3 = fmaf(h3.x, w3.x, fmaf(h3.y, w3.y, fmaf(h3.z, w3.z, fmaf(h3.w, w3.w, b3))));
            }
            float accp = (b0 + b1) + (b2 + b3);
            out[(size_t)m * C_DIM + c] = inv * (accv + accp + bp2c * sl->wsum[gc]);
        }
        // no trailing sync needed: next P2's smem writes are fenced by this
        // iteration's Hs-sync + next P2/P3 syncs relative to all readers.
    }
}

// ---------------- launch -----------------------------------------------------
extern "C" void kernel_launch(void* const* d_in, const int* in_sizes, int n_in,
                              void* d_out, int out_size) {
    const float* qf     = (const float*)d_in[0];
    const float* cf     = (const float*)d_in[1];
    const float* qc     = (const float*)d_in[2];
    const float* cc     = (const float*)d_in[3];
    const float* Wq     = (const float*)d_in[4];
    const float* bq     = (const float*)d_in[5];
    const float* gq     = (const float*)d_in[6];
    const float* betaq  = (const float*)d_in[7];
    const float* Wk     = (const float*)d_in[8];
    const float* bk     = (const float*)d_in[9];
    const float* gk     = (const float*)d_in[10];
    const float* betak  = (const float*)d_in[11];
    const float* Wv     = (const float*)d_in[12];
    const float* bv     = (const float*)d_in[13];
    const float* Wp1    = (const float*)d_in[14];
    const float* bp1    = (const float*)d_in[15];
    const float* gp1    = (const float*)d_in[16];
    const float* betap1 = (const float*)d_in[17];
    const float* Wp2    = (const float*)d_in[18];
    const float* bp2    = (const float*)d_in[19];
    const float* Ww1    = (const float*)d_in[20];
    const float* bw1    = (const float*)d_in[21];
    const float* gw1    = (const float*)d_in[22];
    const float* betaw1 = (const float*)d_in[23];
    const float* Ww2    = (const float*)d_in[24];
    const float* bw2    = (const float*)d_in[25];
    const int*   knn    = (const int*)d_in[26];
    float* out = (float*)d_out;

    const int M = in_sizes[0] / C_DIM;
    const int N = in_sizes[1] / C_DIM;

    k0_prep<<<1, 128>>>(Wp2, Ww1, bp2);
    k1_context<<<N / 64, 256>>>(cf, Wk, bk, gk, betak, Wv, bv, Ww1);
    k2_query<<<M / 64, 256>>>(qf, Wq, bq, gq, betaq, Ww1);

    int smem3 = (int)sizeof(S3);
    cudaFuncSetAttribute(k3_attn, cudaFuncAttributeMaxDynamicSharedMemorySize, smem3);
    k3_attn<<<M / 16, 256, smem3>>>(qc, cc, knn, Wp1, bp1, gp1, betap1,
                                    bp2, bw1, gw1, betaw1, Ww2, bw2, out);
}

// round 3
// speedup vs baseline: 1.3911x; 1.1784x over previous
#include <cuda_runtime.h>
#include <cstdint>

#define C_DIM 128
#define G_DIM 8
#define KNN   16
#define EPS_BN 1e-5f
#define N_CTX_MAX 131072
#define M_Q_MAX   16384

// ---------------- scratch (static device memory; no runtime allocation) -----
__device__ float g_kw  [(size_t)N_CTX_MAX * G_DIM];      // relu(bn(cf@Wk))@Ww1  (4 MB)
__device__ float g_qw  [(size_t)M_Q_MAX   * G_DIM];      // relu(bn(qf@Wq))@Ww1
__device__ float g_WpwT[G_DIM * C_DIM];                  // [g][c2] = (Wp2@Ww1)[c2][g]
__device__ float g_pwb [G_DIM];                          // bp2 @ Ww1
__device__ float g_Hs2 [(size_t)M_Q_MAX * G_DIM * 256];  // [m][g][0:128]=U, [128:256]=H (128 MB)
__device__ float g_sums[(size_t)M_Q_MAX * G_DIM];        // raw softmax denominators
__device__ float g_wsr [(size_t)M_Q_MAX * G_DIM];        // raw masked weight sums

typedef unsigned long long ull;

__device__ __forceinline__ void ffma2(ull& d, ull a, ull b) {
    asm("fma.rn.f32x2 %0, %1, %2, %3;" : "=l"(d) : "l"(a), "l"(b), "l"(d));
}
__device__ __forceinline__ ull pack2(float x) {
    ull r; unsigned u = __float_as_uint(x);
    asm("mov.b64 %0, {%1, %1};" : "=l"(r) : "r"(u));
    return r;
}

// ---------------- K0: tiny prep ---------------------------------------------
__global__ void k0_prep(const float* __restrict__ Wp2,
                        const float* __restrict__ Ww1,
                        const float* __restrict__ bp2) {
    int c = threadIdx.x;  // 128 threads
    float acc[G_DIM];
#pragma unroll
    for (int g = 0; g < G_DIM; g++) acc[g] = 0.f;
    for (int c2 = 0; c2 < C_DIM; c2++) {
        float a = Wp2[c * C_DIM + c2];
#pragma unroll
        for (int g = 0; g < G_DIM; g++) acc[g] = fmaf(a, Ww1[c2 * G_DIM + g], acc[g]);
    }
#pragma unroll
    for (int g = 0; g < G_DIM; g++) g_WpwT[g * C_DIM + c] = acc[g];
    if (c < G_DIM) {
        float s = 0.f;
        for (int c2 = 0; c2 < C_DIM; c2++) s = fmaf(bp2[c2], Ww1[c2 * G_DIM + c], s);
        g_pwb[c] = s;
    }
}

// ---------------- K1: context pass: kw only (double-buffered) ----------------
// 128x128 tile, 256 threads, 8x8 per thread, f32x2 FMA; then fused
// relu(bn) -> kw = k@Ww1.
__launch_bounds__(256, 2)
__global__ void k1_context(const float* __restrict__ cf,
                           const float* __restrict__ Wk, const float* __restrict__ bk,
                           const float* __restrict__ gk, const float* __restrict__ betak,
                           const float* __restrict__ Ww1) {
    __shared__ float As[128][132];          // 67.6 KB (A tile, later k tile)
    __shared__ float Bs[2][16][C_DIM];      // 16 KB double-buffered
    __shared__ float Ws1[C_DIM * G_DIM];    // 4 KB
    const int tid = threadIdx.x;
    const int bm0 = blockIdx.x * 128;

    for (int i = tid; i < 128 * 32; i += 256) {
        int r = i >> 5, c4 = i & 31;
        *(float4*)&As[r][c4 * 4] = *(const float4*)&cf[(size_t)(bm0 + r) * C_DIM + c4 * 4];
    }
    for (int i = tid; i < C_DIM * G_DIM; i += 256) Ws1[i] = Ww1[i];
    for (int i = tid; i < 512; i += 256) {
        int kk = i >> 5, j4 = i & 31;
        *(float4*)&Bs[0][kk][j4 * 4] = *(const float4*)&Wk[(size_t)kk * C_DIM + j4 * 4];
    }
    __syncthreads();

    const int tr = tid >> 4, tc = tid & 15;
    ull acc[8][4];
#pragma unroll
    for (int r = 0; r < 8; r++)
#pragma unroll
        for (int p = 0; p < 4; p++) acc[r][p] = 0ull;

    for (int chunk = 0; chunk < 8; chunk++) {
        const int buf = chunk & 1;
        if (chunk < 7) {
            for (int i = tid; i < 512; i += 256) {
                int kk = i >> 5, j4 = i & 31;
                *(float4*)&Bs[buf ^ 1][kk][j4 * 4] =
                    *(const float4*)&Wk[(size_t)(chunk * 16 + 16 + kk) * C_DIM + j4 * 4];
            }
        }
        const int kc = chunk * 16;
#pragma unroll
        for (int k4 = 0; k4 < 16; k4 += 4) {
            float4 a4[8];
#pragma unroll
            for (int r = 0; r < 8; r++) a4[r] = *(const float4*)&As[tr * 8 + r][kc + k4];
#pragma unroll
            for (int u = 0; u < 4; u++) {
                float4 bA = *(const float4*)&Bs[buf][k4 + u][tc * 8];
                float4 bB = *(const float4*)&Bs[buf][k4 + u][tc * 8 + 4];
                ull b0 = ((const ull*)&bA)[0], b1 = ((const ull*)&bA)[1];
                ull b2 = ((const ull*)&bB)[0], b3 = ((const ull*)&bB)[1];
#pragma unroll
                for (int r = 0; r < 8; r++) {
                    ull ap = pack2((&a4[r].x)[u]);
                    ffma2(acc[r][0], ap, b0);
                    ffma2(acc[r][1], ap, b1);
                    ffma2(acc[r][2], ap, b2);
                    ffma2(acc[r][3], ap, b3);
                }
            }
        }
        __syncthreads();
    }

    // relu(bn) -> overwrite As with k
    const float rs = rsqrtf(1.f + EPS_BN);
#pragma unroll
    for (int r = 0; r < 8; r++) {
        int row = tr * 8 + r;
#pragma unroll
        for (int p = 0; p < 4; p++) {
            int j0 = tc * 8 + 2 * p;
            float lo = __uint_as_float((unsigned)acc[r][p]);
            float hi = __uint_as_float((unsigned)(acc[r][p] >> 32));
            As[row][j0]     = fmaxf(fmaf(lo + bk[j0],     gk[j0]     * rs, betak[j0]),     0.f);
            As[row][j0 + 1] = fmaxf(fmaf(hi + bk[j0 + 1], gk[j0 + 1] * rs, betak[j0 + 1]), 0.f);
        }
    }
    __syncthreads();

    // kw = k @ Ww1 : 128 rows x 8 groups, 4 tasks/thread, ILP-4 dot
#pragma unroll
    for (int s2 = 0; s2 < 4; s2++) {
        int task = tid + s2 * 256;
        int row = task >> 3, g = task & 7;
        float a0 = 0.f, a1 = 0.f, a2 = 0.f, a3 = 0.f;
#pragma unroll 8
        for (int c = 0; c < C_DIM; c += 4) {
            a0 = fmaf(As[row][c],     Ws1[(c)     * G_DIM + g], a0);
            a1 = fmaf(As[row][c + 1], Ws1[(c + 1) * G_DIM + g], a1);
            a2 = fmaf(As[row][c + 2], Ws1[(c + 2) * G_DIM + g], a2);
            a3 = fmaf(As[row][c + 3], Ws1[(c + 3) * G_DIM + g], a3);
        }
        g_kw[(size_t)(bm0 + row) * G_DIM + g] = (a0 + a1) + (a2 + a3);
    }
}

// ---------------- K2: query pass (qw only) -----------------------------------
__launch_bounds__(256, 2)
__global__ void k2_query(const float* __restrict__ qf,
                         const float* __restrict__ Wq, const float* __restrict__ bq,
                         const float* __restrict__ gq, const float* __restrict__ betaq,
                         const float* __restrict__ Ww1) {
    __shared__ float As[64][C_DIM];
    __shared__ float Bs[16][C_DIM];
    const int tid = threadIdx.x;
    const int bm0 = blockIdx.x * 64;

    for (int i = tid; i < 64 * 32; i += 256) {
        int r = i >> 5, c4 = i & 31;
        *(float4*)&As[r][c4 * 4] = *(const float4*)&qf[(size_t)(bm0 + r) * C_DIM + c4 * 4];
    }
    const int tr = tid >> 4, tc = tid & 15;

    ull acc[4][4];
#pragma unroll
    for (int r = 0; r < 4; r++)
#pragma unroll
        for (int p = 0; p < 4; p++) acc[r][p] = 0ull;

    for (int kc = 0; kc < C_DIM; kc += 16) {
        if (kc) __syncthreads();
        for (int i = tid; i < 16 * 32; i += 256) {
            int kk = i >> 5, j4 = i & 31;
            *(float4*)&Bs[kk][j4 * 4] = *(const float4*)&Wq[(size_t)(kc + kk) * C_DIM + j4 * 4];
        }
        __syncthreads();
#pragma unroll
        for (int k4 = 0; k4 < 16; k4 += 4) {
            float4 a4[4];
#pragma unroll
            for (int r = 0; r < 4; r++) a4[r] = *(const float4*)&As[tr * 4 + r][kc + k4];
#pragma unroll
            for (int u = 0; u < 4; u++) {
                ull bp[4];
#pragma unroll
                for (int p = 0; p < 4; p++) bp[p] = *(const ull*)&Bs[k4 + u][tc * 8 + 2 * p];
#pragma unroll
                for (int r = 0; r < 4; r++) {
                    ull ap = pack2((&a4[r].x)[u]);
#pragma unroll
                    for (int p = 0; p < 4; p++) ffma2(acc[r][p], ap, bp[p]);
                }
            }
        }
    }
    __syncthreads();

    const float rs = rsqrtf(1.f + EPS_BN);
#pragma unroll
    for (int r = 0; r < 4; r++) {
        int row = tr * 4 + r;
#pragma unroll
        for (int p = 0; p < 4; p++) {
            int j0 = tc * 8 + 2 * p;
            float lo = __uint_as_float((unsigned)acc[r][p]);
            float hi = __uint_as_float((unsigned)(acc[r][p] >> 32));
            As[row][j0]     = fmaxf(fmaf(lo + bq[j0],     gq[j0]     * rs, betaq[j0]),     0.f);
            As[row][j0 + 1] = fmaxf(fmaf(hi + bq[j0 + 1], gq[j0 + 1] * rs, betaq[j0 + 1]), 0.f);
        }
    }
    __syncthreads();
#pragma unroll
    for (int s2 = 0; s2 < 2; s2++) {
        int task = tid + s2 * 256;
        int row = task >> 3, g = task & 7;
        float a = 0.f;
#pragma unroll 8
        for (int c = 0; c < C_DIM; c++) a = fmaf(As[row][c], Ww1[c * G_DIM + g], a);
        g_qw[(size_t)(bm0 + row) * G_DIM + g] = a;
    }
}

// ---------------- K3: attention weights + U/H accumulation -------------------
// 128 threads, 8 queries/block, 3-stage pipeline, 2 syncs/query.
struct S3 {
    float WpwT[G_DIM * 132];    // 4224
    float ww2s[G_DIM * G_DIM];  // 256
    float hs[2][KNN * 132];     // 16896 (double-buffered)
    float e_s[KNN * G_DIM];     // 512   masked exp(logits)
    float psum[4 * G_DIM];      // raw per-warp partial exp sums
    float wpsum[4 * G_DIM];     // masked per-warp partial sums
    float pos[2][KNN * 4];
    float kwg[2][KNN * G_DIM];
    float qw[2][G_DIM];
    float msk[2][KNN];
    int   idx[2][KNN];
};

__device__ __forceinline__ void gatherK(S3* s, const int* __restrict__ knn,
                                        const float* __restrict__ qcoord,
                                        const float* __restrict__ ccoord,
                                        int m, int p, int k) {
    int id = knn[(size_t)m * KNN + k];
    float mk = id >= 0 ? 1.f : 0.f;
    int id0 = id >= 0 ? id : 0;
    s->idx[p][k] = id0;
    s->msk[p][k] = mk;
    float qx = qcoord[m * 3 + 0], qy = qcoord[m * 3 + 1], qz = qcoord[m * 3 + 2];
    s->pos[p][k * 4 + 0] = (ccoord[(size_t)id0 * 3 + 0] - qx) * mk;
    s->pos[p][k * 4 + 1] = (ccoord[(size_t)id0 * 3 + 1] - qy) * mk;
    s->pos[p][k * 4 + 2] = (ccoord[(size_t)id0 * 3 + 2] - qz) * mk;
    const float4* kwp = (const float4*)&g_kw[(size_t)id0 * G_DIM];
    float4 a = kwp[0], b = kwp[1];
    float* kd = &s->kwg[p][k * 8];
    kd[0] = a.x * mk; kd[1] = a.y * mk; kd[2] = a.z * mk; kd[3] = a.w * mk;
    kd[4] = b.x * mk; kd[5] = b.y * mk; kd[6] = b.z * mk; kd[7] = b.w * mk;
}

__launch_bounds__(128, 4)
__global__ void k3_attn(const float* __restrict__ qcoord, const float* __restrict__ ccoord,
                        const int*   __restrict__ knn, const float* __restrict__ cf,
                        const float* __restrict__ Wp1, const float* __restrict__ bp1,
                        const float* __restrict__ gp1, const float* __restrict__ betap1,
                        const float* __restrict__ bw1, const float* __restrict__ gw1,
                        const float* __restrict__ betaw1,
                        const float* __restrict__ Ww2, const float* __restrict__ bw2) {
    __shared__ S3 s;
    const int t = threadIdx.x;
    const int c = t, gc = t >> 4;
    const int kB = t >> 3, gB = t & 7;
    const int w4 = t >> 5;
    const int lane = t & 31;
    const int lbase = lane & ~7;

    for (int i = t; i < G_DIM * C_DIM; i += 128) {
        int r = i >> 7, cc2 = i & 127;
        s.WpwT[r * 132 + cc2] = g_WpwT[i];
    }
    if (t < G_DIM * G_DIM) s.ww2s[t] = Ww2[t];

    const float rs  = rsqrtf(1.f + EPS_BN);
    const float sp1 = gp1[c] * rs;
    const float wf0 = Wp1[c] * sp1, wf1 = Wp1[C_DIM + c] * sp1, wf2 = Wp1[2 * C_DIM + c] * sp1;
    const float hb  = fmaf(bp1[c], sp1, betap1[c]);
    const float sw1  = gw1[gB] * rs;
    const float wb1f = fmaf(bw1[gB], sw1, betaw1[gB]);
    const float pwbB = g_pwb[gB];
    const float bw2B = bw2[gB];

    const int mb = blockIdx.x * 8;
    float cfpre[KNN];

    // prologue
    if (t < KNN)   gatherK(&s, knn, qcoord, ccoord, mb, 0, t);
    if (t < G_DIM) s.qw[0][t] = g_qw[(size_t)mb * G_DIM + t];
    __syncthreads();

    for (int qi = 0; qi < 8; qi++) {
        const int b = qi & 1;
        const int m = mb + qi;

        // ---- region A: h(qi); gather(qi+1); P4(qi-1) ----
        {
#pragma unroll
            for (int k = 0; k < KNN; k++) {
                const float* pp = &s.pos[b][k * 4];
                s.hs[b][k * 132 + c] =
                    fmaxf(fmaf(wf0, pp[0], fmaf(wf1, pp[1], fmaf(wf2, pp[2], hb))), 0.f);
            }
            if (qi < 7) {
                if (t < KNN)   gatherK(&s, knn, qcoord, ccoord, m + 1, b ^ 1, t);
                if (t < G_DIM) s.qw[b ^ 1][t] = g_qw[(size_t)(m + 1) * G_DIM + t];
            }
            if (qi > 0) {  // P4(qi-1)
                const int bp = b ^ 1;
                const int mp = m - 1;
                float hh[G_DIM], uu[G_DIM];
#pragma unroll
                for (int g2 = 0; g2 < G_DIM; g2++) { hh[g2] = 0.f; uu[g2] = 0.f; }
#pragma unroll
                for (int k = 0; k < KNN; k++) {
                    float hk = s.hs[bp][k * 132 + c];
                    float cv = cfpre[k];
                    float4 ea = *(const float4*)&s.e_s[k * 8];
                    float4 eb = *(const float4*)&s.e_s[k * 8 + 4];
                    uu[0] = fmaf(cv, ea.x, uu[0]); hh[0] = fmaf(hk, ea.x, hh[0]);
                    uu[1] = fmaf(cv, ea.y, uu[1]); hh[1] = fmaf(hk, ea.y, hh[1]);
                    uu[2] = fmaf(cv, ea.z, uu[2]); hh[2] = fmaf(hk, ea.z, hh[2]);
                    uu[3] = fmaf(cv, ea.w, uu[3]); hh[3] = fmaf(hk, ea.w, hh[3]);
                    uu[4] = fmaf(cv, eb.x, uu[4]); hh[4] = fmaf(hk, eb.x, hh[4]);
                    uu[5] = fmaf(cv, eb.y, uu[5]); hh[5] = fmaf(hk, eb.y, hh[5]);
                    uu[6] = fmaf(cv, eb.z, uu[6]); hh[6] = fmaf(hk, eb.z, hh[6]);
                    uu[7] = fmaf(cv, eb.w, uu[7]); hh[7] = fmaf(hk, eb.w, hh[7]);
                }
                float* base = &g_Hs2[(size_t)mp * (G_DIM * 256)];
#pragma unroll
                for (int g2 = 0; g2 < G_DIM; g2++) {
                    base[g2 * 256 + c]       = uu[g2];
                    base[g2 * 256 + 128 + c] = hh[g2];
                }
                if (t < G_DIM) {
                    g_sums[(size_t)mp * G_DIM + t] =
                        s.psum[t] + s.psum[8 + t] + s.psum[16 + t] + s.psum[24 + t];
                    g_wsr[(size_t)mp * G_DIM + t] =
                        s.wpsum[t] + s.wpsum[8 + t] + s.wpsum[16 + t] + s.wpsum[24 + t];
                }
            }
        }
        __syncthreads();

        // ---- region B: P3(qi) + cfpre(qi) issue ----
        {
            float a0 = s.kwg[b][t] - s.qw[b][gB] + pwbB;
            float a1 = 0.f, a2 = 0.f, a3 = 0.f;
            const float4* hr = (const float4*)&s.hs[b][kB * 132];
            const float4* wr = (const float4*)&s.WpwT[gB * 132];
#pragma unroll
            for (int j = 0; j < 32; j += 4) {
                float4 h0 = hr[j],     w0 = wr[j];
                float4 h1 = hr[j + 1], w1 = wr[j + 1];
                float4 h2 = hr[j + 2], w2 = wr[j + 2];
                float4 h3 = hr[j + 3], w3 = wr[j + 3];
                a0 = fmaf(h0.x, w0.x, fmaf(h0.y, w0.y, fmaf(h0.z, w0.z, fmaf(h0.w, w0.w, a0))));
                a1 = fmaf(h1.x, w1.x, fmaf(h1.y, w1.y, fmaf(h1.z, w1.z, fmaf(h1.w, w1.w, a1))));
                a2 = fmaf(h2.x, w2.x, fmaf(h2.y, w2.y, fmaf(h2.z, w2.z, fmaf(h2.w, w2.w, a2))));
                a3 = fmaf(h3.x, w3.x, fmaf(h3.y, w3.y, fmaf(h3.z, w3.z, fmaf(h3.w, w3.w, a3))));
            }
            float ts = fmaxf(fmaf((a0 + a1) + (a2 + a3), sw1, wb1f), 0.f);

            float lg = bw2B;
#pragma unroll
            for (int g2 = 0; g2 < G_DIM; g2++)
                lg = fmaf(__shfl_sync(0xffffffffu, ts, lbase + g2), s.ww2s[g2 * G_DIM + gB], lg);

            float e  = __expf(lg);
            float mk = s.msk[b][kB];
            float em = e * mk;
            s.e_s[t] = em;
            float es = e;
            es += __shfl_xor_sync(0xffffffffu, es, 8);
            es += __shfl_xor_sync(0xffffffffu, es, 16);
            float esm = em;
            esm += __shfl_xor_sync(0xffffffffu, esm, 8);
            esm += __shfl_xor_sync(0xffffffffu, esm, 16);
            if (lane < 8) { s.psum[w4 * 8 + gB] = es; s.wpsum[w4 * 8 + gB] = esm; }

            // cf prefetch for P4(qi)
            const int* ix = s.idx[b];
#pragma unroll
            for (int k = 0; k < KNN; k++) cfpre[k] = cf[(size_t)ix[k] * C_DIM + c];
        }
        __syncthreads();
    }

    // final P4(7)
    {
        const int bp = 1;
        const int mp = mb + 7;
        float hh[G_DIM], uu[G_DIM];
#pragma unroll
        for (int g2 = 0; g2 < G_DIM; g2++) { hh[g2] = 0.f; uu[g2] = 0.f; }
#pragma unroll
        for (int k = 0; k < KNN; k++) {
            float hk = s.hs[bp][k * 132 + c];
            float cv = cfpre[k];
            float4 ea = *(const float4*)&s.e_s[k * 8];
            float4 eb = *(const float4*)&s.e_s[k * 8 + 4];
            uu[0] = fmaf(cv, ea.x, uu[0]); hh[0] = fmaf(hk, ea.x, hh[0]);
            uu[1] = fmaf(cv, ea.y, uu[1]); hh[1] = fmaf(hk, ea.y, hh[1]);
            uu[2] = fmaf(cv, ea.z, uu[2]); hh[2] = fmaf(hk, ea.z, hh[2]);
            uu[3] = fmaf(cv, ea.w, uu[3]); hh[3] = fmaf(hk, ea.w, hh[3]);
            uu[4] = fmaf(cv, eb.x, uu[4]); hh[4] = fmaf(hk, eb.x, hh[4]);
            uu[5] = fmaf(cv, eb.y, uu[5]); hh[5] = fmaf(hk, eb.y, hh[5]);
            uu[6] = fmaf(cv, eb.z, uu[6]); hh[6] = fmaf(hk, eb.z, hh[6]);
            uu[7] = fmaf(cv, eb.w, uu[7]); hh[7] = fmaf(hk, eb.w, hh[7]);
        }
        float* base = &g_Hs2[(size_t)mp * (G_DIM * 256)];
#pragma unroll
        for (int g2 = 0; g2 < G_DIM; g2++) {
            base[g2 * 256 + c]       = uu[g2];
            base[g2 * 256 + 128 + c] = hh[g2];
        }
        if (t < G_DIM) {
            g_sums[(size_t)mp * G_DIM + t] =
                s.psum[t] + s.psum[8 + t] + s.psum[16 + t] + s.psum[24 + t];
            g_wsr[(size_t)mp * G_DIM + t] =
                s.wpsum[t] + s.wpsum[8 + t] + s.wpsum[16 + t] + s.wpsum[24 + t];
        }
    }
}

// ---------------- K4: grouped epilogue GEMM ----------------------------------
// out[m, g*16+cc] = (1/sums) * ( Hs2[m,g,:] . [Wv;Wp2][:, c] + (bv+bp2)[c]*wsr )
__launch_bounds__(256, 6)
__global__ void k4_out(const float* __restrict__ Wv, const float* __restrict__ Wp2,
                       const float* __restrict__ bv, const float* __restrict__ bp2,
                       float* __restrict__ out) {
    __shared__ float As[16][260];     // 16 m-rows x 256 features
    __shared__ float BsT[16][260];    // 16 cols x 256 features
    const int m0 = blockIdx.x * 16;
    const int g  = blockIdx.y;
    const int tid = threadIdx.x;

    for (int i = tid; i < 1024; i += 256) {
        int r = i >> 6, j4 = i & 63;
        *(float4*)&As[r][j4 * 4] =
            *(const float4*)&g_Hs2[(size_t)(m0 + r) * (G_DIM * 256) + g * 256 + j4 * 4];
    }
    for (int i = tid; i < 4096; i += 256) {
        int j = i >> 4, cc0 = i & 15;
        float v = (j < 128) ? Wv[(size_t)j * C_DIM + g * 16 + cc0]
                            : Wp2[(size_t)(j - 128) * C_DIM + g * 16 + cc0];
        BsT[cc0][j] = v;
    }
    __syncthreads();

    const int r = tid >> 4, cc = tid & 15;
    float a0 = 0.f, a1 = 0.f, a2 = 0.f, a3 = 0.f;
    const float4* ar = (const float4*)&As[r][0];
    const float4* br = (const float4*)&BsT[cc][0];
#pragma unroll
    for (int j = 0; j < 64; j += 4) {
        float4 x0 = ar[j],     y0 = br[j];
        float4 x1 = ar[j + 1], y1 = br[j + 1];
        float4 x2 = ar[j + 2], y2 = br[j + 2];
        float4 x3 = ar[j + 3], y3 = br[j + 3];
        a0 = fmaf(x0.x, y0.x, fmaf(x0.y, y0.y, fmaf(x0.z, y0.z, fmaf(x0.w, y0.w, a0))));
        a1 = fmaf(x1.x, y1.x, fmaf(x1.y, y1.y, fmaf(x1.z, y1.z, fmaf(x1.w, y1.w, a1))));
        a2 = fmaf(x2.x, y2.x, fmaf(x2.y, y2.y, fmaf(x2.z, y2.z, fmaf(x2.w, y2.w, a2))));
        a3 = fmaf(x3.x, y3.x, fmaf(x3.y, y3.y, fmaf(x3.z, y3.z, fmaf(x3.w, y3.w, a3))));
    }
    float acc = (a0 + a1) + (a2 + a3);
    const int m = m0 + r;
    const int c = g * 16 + cc;
    float inv = 1.f / g_sums[(size_t)m * G_DIM + g];
    float wsr = g_wsr[(size_t)m * G_DIM + g];
    out[(size_t)m * C_DIM + c] = (acc + (bv[c] + bp2[c]) * wsr) * inv;
}

// ---------------- launch -----------------------------------------------------
extern "C" void kernel_launch(void* const* d_in, const int* in_sizes, int n_in,
                              void* d_out, int out_size) {
    const float* qf     = (const float*)d_in[0];
    const float* cf     = (const float*)d_in[1];
    const float* qc     = (const float*)d_in[2];
    const float* cc     = (const float*)d_in[3];
    const float* Wq     = (const float*)d_in[4];
    const float* bq     = (const float*)d_in[5];
    const float* gq     = (const float*)d_in[6];
    const float* betaq  = (const float*)d_in[7];
    const float* Wk     = (const float*)d_in[8];
    const float* bk     = (const float*)d_in[9];
    const float* gk     = (const float*)d_in[10];
    const float* betak  = (const float*)d_in[11];
    const float* Wv     = (const float*)d_in[12];
    const float* bv     = (const float*)d_in[13];
    const float* Wp1    = (const float*)d_in[14];
    const float* bp1    = (const float*)d_in[15];
    const float* gp1    = (const float*)d_in[16];
    const float* betap1 = (const float*)d_in[17];
    const float* Wp2    = (const float*)d_in[18];
    const float* bp2    = (const float*)d_in[19];
    const float* Ww1    = (const float*)d_in[20];
    const float* bw1    = (const float*)d_in[21];
    const float* gw1    = (const float*)d_in[22];
    const float* betaw1 = (const float*)d_in[23];
    const float* Ww2    = (const float*)d_in[24];
    const float* bw2    = (const float*)d_in[25];
    const int*   knn    = (const int*)d_in[26];
    float* out = (float*)d_out;

    const int M = in_sizes[0] / C_DIM;
    const int N = in_sizes[1] / C_DIM;

    k0_prep<<<1, 128>>>(Wp2, Ww1, bp2);
    k1_context<<<N / 128, 256>>>(cf, Wk, bk, gk, betak, Ww1);
    k2_query<<<M / 64, 256>>>(qf, Wq, bq, gq, betaq, Ww1);
    k3_attn<<<M / 8, 128>>>(qc, cc, knn, cf, Wp1, bp1, gp1, betap1,
                            bw1, gw1, betaw1, Ww2, bw2);
    dim3 g4(M / 16, G_DIM);
    k4_out<<<g4, 256>>>(Wv, Wp2, bv, bp2, out);
}

// round 5
// speedup vs baseline: 1.4076x; 1.0119x over previous
#include <cuda_runtime.h>
#include <cuda_bf16.h>
#include <cstdint>

#define C_DIM 128
#define G_DIM 8
#define KNN   16
#define EPS_BN 1e-5f
#define N_CTX_MAX 131072
#define M_Q_MAX   16384

// ---------------- scratch (static device memory; no runtime allocation) -----
__device__ float g_kw  [(size_t)N_CTX_MAX * G_DIM];      // relu(bn(cf@Wk))@Ww1  (4 MB)
__device__ float g_qw  [(size_t)M_Q_MAX   * G_DIM];      // relu(bn(qf@Wq))@Ww1
__device__ float g_WpwT[G_DIM * C_DIM];                  // [g][c2] = (Wp2@Ww1)[c2][g]
__device__ float g_pwb [G_DIM];                          // bp2 @ Ww1
__device__ float g_Hs2 [(size_t)M_Q_MAX * G_DIM * 256];  // [m][g][0:128]=U, [128:256]=H
__device__ float g_sums[(size_t)M_Q_MAX * G_DIM];        // raw softmax denominators
__device__ float g_wsr [(size_t)M_Q_MAX * G_DIM];        // raw masked weight sums

typedef unsigned long long ull;

__device__ __forceinline__ void ffma2(ull& d, ull a, ull b) {
    asm("fma.rn.f32x2 %0, %1, %2, %3;" : "=l"(d) : "l"(a), "l"(b), "l"(d));
}
__device__ __forceinline__ ull pack2(float x) {
    ull r; unsigned u = __float_as_uint(x);
    asm("mov.b64 %0, {%1, %1};" : "=l"(r) : "r"(u));
    return r;
}

// bf16 HMMA m16n8k16 (sm_80+ PTX; no arch-suffix features)
__device__ __forceinline__ void mma_bf16(float* d, uint32_t a0, uint32_t a1,
                                         uint32_t a2, uint32_t a3,
                                         uint32_t b0, uint32_t b1) {
    asm volatile(
        "mma.sync.aligned.m16n8k16.row.col.f32.bf16.bf16.f32 "
        "{%0,%1,%2,%3}, {%4,%5,%6,%7}, {%8,%9}, {%0,%1,%2,%3};"
        : "+f"(d[0]), "+f"(d[1]), "+f"(d[2]), "+f"(d[3])
        : "r"(a0), "r"(a1), "r"(a2), "r"(a3), "r"(b0), "r"(b1));
}

// ---------------- K0: tiny prep ---------------------------------------------
__global__ void k0_prep(const float* __restrict__ Wp2,
                        const float* __restrict__ Ww1,
                        const float* __restrict__ bp2) {
    int c = threadIdx.x;  // 128 threads
    float acc[G_DIM];
#pragma unroll
    for (int g = 0; g < G_DIM; g++) acc[g] = 0.f;
    for (int c2 = 0; c2 < C_DIM; c2++) {
        float a = Wp2[c * C_DIM + c2];
#pragma unroll
        for (int g = 0; g < G_DIM; g++) acc[g] = fmaf(a, Ww1[c2 * G_DIM + g], acc[g]);
    }
#pragma unroll
    for (int g = 0; g < G_DIM; g++) g_WpwT[g * C_DIM + c] = acc[g];
    if (c < G_DIM) {
        float s = 0.f;
        for (int c2 = 0; c2 < C_DIM; c2++) s = fmaf(bp2[c2], Ww1[c2 * G_DIM + c], s);
        g_pwb[c] = s;
    }
}

// ---------------- K1: context pass via bf16-split HMMA -----------------------
// Tile layout: per row, k-pairs packed so one 64-bit LDS yields a whole
// fragment half: pair p=k/2 -> byte (p&3)*8 + ((p>>2)&1)*4 within 32B k16 group.
#define K1_ROWB 272      // bytes per row (136 bf16)
__device__ __forceinline__ uint32_t k1_off(int row, int k) {  // k even
    int p = k >> 1;
    return (uint32_t)row * K1_ROWB + (uint32_t)(k >> 4) * 32
         + (uint32_t)(p & 3) * 8 + (uint32_t)((p >> 2) & 1) * 4;
}

#define SM_AH  0
#define SM_AL  34816
#define SM_BH  69632
#define SM_BL  104448
#define SM_PAR 139264    // float4[128]: (bk, gk*rs, betak, 0)
#define SM_W1  141312    // float[128*8] Ww1
#define SM_KS  0         // float[128][130] k tile (reuses A region post-MMA)
#define SMEM_K1_TOTAL 145408

__launch_bounds__(256, 1)
__global__ void k1_context(const float* __restrict__ cf,
                           const float* __restrict__ Wk, const float* __restrict__ bk,
                           const float* __restrict__ gk, const float* __restrict__ betak,
                           const float* __restrict__ Ww1) {
    extern __shared__ char smem[];
    const int tid = threadIdx.x;
    const int wid = tid >> 5;
    const int lane = tid & 31;
    const int grp = lane >> 2, tig = lane & 3;
    const int bm0 = blockIdx.x * 128;

    // ---- fill A tiles (cf rows, hi/lo bf16 split) ----
    {
        const int row = tid >> 1, half = tid & 1;
        const float4* src = (const float4*)&cf[(size_t)(bm0 + row) * C_DIM + half * 64];
#pragma unroll
        for (int j = 0; j < 16; j++) {
            float4 x = src[j];
            int c0 = half * 64 + j * 4;
#pragma unroll
            for (int p = 0; p < 2; p++) {
                float a0 = (&x.x)[2 * p], a1 = (&x.x)[2 * p + 1];
                __nv_bfloat16 h0 = __float2bfloat16(a0), h1 = __float2bfloat16(a1);
                __nv_bfloat16 l0 = __float2bfloat16(a0 - __bfloat162float(h0));
                __nv_bfloat16 l1 = __float2bfloat16(a1 - __bfloat162float(h1));
                uint32_t off = k1_off(row, c0 + 2 * p);
                *(__nv_bfloat162*)(smem + SM_AH + off) = __nv_bfloat162(h0, h1);
                *(__nv_bfloat162*)(smem + SM_AL + off) = __nv_bfloat162(l0, l1);
            }
        }
    }
    // ---- fill B tiles: B[n][k] = Wk[k][n] (transposed), hi/lo split ----
    for (int i = tid; i < 8192; i += 256) {
        int n = i & 127, p = i >> 7, k = 2 * p;
        float v0 = Wk[(size_t)k * C_DIM + n];
        float v1 = Wk[(size_t)(k + 1) * C_DIM + n];
        __nv_bfloat16 h0 = __float2bfloat16(v0), h1 = __float2bfloat16(v1);
        __nv_bfloat16 l0 = __float2bfloat16(v0 - __bfloat162float(h0));
        __nv_bfloat16 l1 = __float2bfloat16(v1 - __bfloat162float(h1));
        uint32_t off = k1_off(n, k);
        *(__nv_bfloat162*)(smem + SM_BH + off) = __nv_bfloat162(h0, h1);
        *(__nv_bfloat162*)(smem + SM_BL + off) = __nv_bfloat162(l0, l1);
    }
    // ---- params ----
    const float rs = rsqrtf(1.f + EPS_BN);
    if (tid < C_DIM) {
        float4 pp; pp.x = bk[tid]; pp.y = gk[tid] * rs; pp.z = betak[tid]; pp.w = 0.f;
        *(float4*)(smem + SM_PAR + tid * 16) = pp;
    }
    *(float4*)(smem + SM_W1 + tid * 16) = *(const float4*)&Ww1[tid * 4];
    __syncthreads();

    // ---- MMA mainloop: warp w owns rows [w*16, w*16+16) x all 128 cols ----
    const int rbase = wid * 16;
    float acc[16][4];
#pragma unroll
    for (int nt = 0; nt < 16; nt++)
#pragma unroll
        for (int q = 0; q < 4; q++) acc[nt][q] = 0.f;

    const uint32_t aoff_lo = k1_off(rbase + grp, 0) + tig * 8;
    const uint32_t aoff_hi = k1_off(rbase + grp + 8, 0) + tig * 8;

#pragma unroll
    for (int ks = 0; ks < 8; ks++) {
        const uint32_t kb = ks * 32;
        ull alo_h = *(const ull*)(smem + SM_AH + aoff_lo + kb);
        ull ahi_h = *(const ull*)(smem + SM_AH + aoff_hi + kb);
        ull alo_l = *(const ull*)(smem + SM_AL + aoff_lo + kb);
        ull ahi_l = *(const ull*)(smem + SM_AL + aoff_hi + kb);
        uint32_t a0h = (uint32_t)alo_h, a2h = (uint32_t)(alo_h >> 32);
        uint32_t a1h = (uint32_t)ahi_h, a3h = (uint32_t)(ahi_h >> 32);
        uint32_t a0l = (uint32_t)alo_l, a2l = (uint32_t)(alo_l >> 32);
        uint32_t a1l = (uint32_t)ahi_l, a3l = (uint32_t)(ahi_l >> 32);
#pragma unroll
        for (int nt = 0; nt < 16; nt++) {
            uint32_t boff = (uint32_t)(nt * 8 + grp) * K1_ROWB + kb + tig * 8;
            ull bh = *(const ull*)(smem + SM_BH + boff);
            ull bl = *(const ull*)(smem + SM_BL + boff);
            uint32_t b0h = (uint32_t)bh, b1h = (uint32_t)(bh >> 32);
            uint32_t b0l = (uint32_t)bl, b1l = (uint32_t)(bl >> 32);
            mma_bf16(acc[nt], a0h, a1h, a2h, a3h, b0h, b1h);
            mma_bf16(acc[nt], a0h, a1h, a2h, a3h, b0l, b1l);
            mma_bf16(acc[nt], a0l, a1l, a2l, a3l, b0h, b1h);
        }
    }
    __syncthreads();   // A/B smem dead; reuse for k tile

    // ---- epilogue: relu(bn) -> k tile in smem ----
    {
        float* ks_s = (float*)(smem + SM_KS);
        const float4* par = (const float4*)(smem + SM_PAR);
        const int r0 = rbase + grp, r1 = r0 + 8;
#pragma unroll
        for (int nt = 0; nt < 16; nt++) {
            int col = nt * 8 + tig * 2;
            float4 p0 = par[col], p1 = par[col + 1];
            float2 lo, hi;
            lo.x = fmaxf(fmaf(acc[nt][0] + p0.x, p0.y, p0.z), 0.f);
            lo.y = fmaxf(fmaf(acc[nt][1] + p1.x, p1.y, p1.z), 0.f);
            hi.x = fmaxf(fmaf(acc[nt][2] + p0.x, p0.y, p0.z), 0.f);
            hi.y = fmaxf(fmaf(acc[nt][3] + p1.x, p1.y, p1.z), 0.f);
            *(float2*)&ks_s[r0 * 130 + col] = lo;
            *(float2*)&ks_s[r1 * 130 + col] = hi;
        }
    }
    __syncthreads();

    // ---- kw = k @ Ww1 -> g_kw ----
    {
        const float* ks_s = (const float*)(smem + SM_KS);
        const float* W1   = (const float*)(smem + SM_W1);
#pragma unroll
        for (int s2 = 0; s2 < 4; s2++) {
            int task = tid + s2 * 256;
            int row = task >> 3, g = task & 7;
            const float* kr = &ks_s[row * 130];
            float a0 = 0.f, a1 = 0.f, a2 = 0.f, a3 = 0.f;
#pragma unroll 8
            for (int c = 0; c < C_DIM; c += 4) {
                a0 = fmaf(kr[c],     W1[(c)     * G_DIM + g], a0);
                a1 = fmaf(kr[c + 1], W1[(c + 1) * G_DIM + g], a1);
                a2 = fmaf(kr[c + 2], W1[(c + 2) * G_DIM + g], a2);
                a3 = fmaf(kr[c + 3], W1[(c + 3) * G_DIM + g], a3);
            }
            g_kw[(size_t)(bm0 + row) * G_DIM + g] = (a0 + a1) + (a2 + a3);
        }
    }
}

// ---------------- K2: query pass (qw only) -----------------------------------
__launch_bounds__(256, 2)
__global__ void k2_query(const float* __restrict__ qf,
                         const float* __restrict__ Wq, const float* __restrict__ bq,
                         const float* __restrict__ gq, const float* __restrict__ betaq,
                         const float* __restrict__ Ww1) {
    __shared__ float As[64][C_DIM];
    __shared__ float Bs[16][C_DIM];
    const int tid = threadIdx.x;
    const int bm0 = blockIdx.x * 64;

    for (int i = tid; i < 64 * 32; i += 256) {
        int r = i >> 5, c4 = i & 31;
        *(float4*)&As[r][c4 * 4] = *(const float4*)&qf[(size_t)(bm0 + r) * C_DIM + c4 * 4];
    }
    const int tr = tid >> 4, tc = tid & 15;

    ull acc[4][4];
#pragma unroll
    for (int r = 0; r < 4; r++)
#pragma unroll
        for (int p = 0; p < 4; p++) acc[r][p] = 0ull;

    for (int kc = 0; kc < C_DIM; kc += 16) {
        if (kc) __syncthreads();
        for (int i = tid; i < 16 * 32; i += 256) {
            int kk = i >> 5, j4 = i & 31;
            *(float4*)&Bs[kk][j4 * 4] = *(const float4*)&Wq[(size_t)(kc + kk) * C_DIM + j4 * 4];
        }
        __syncthreads();
#pragma unroll
        for (int k4 = 0; k4 < 16; k4 += 4) {
            float4 a4[4];
#pragma unroll
            for (int r = 0; r < 4; r++) a4[r] = *(const float4*)&As[tr * 4 + r][kc + k4];
#pragma unroll
            for (int u = 0; u < 4; u++) {
                ull bp[4];
#pragma unroll
                for (int p = 0; p < 4; p++) bp[p] = *(const ull*)&Bs[k4 + u][tc * 8 + 2 * p];
#pragma unroll
                for (int r = 0; r < 4; r++) {
                    ull ap = pack2((&a4[r].x)[u]);
#pragma unroll
                    for (int p = 0; p < 4; p++) ffma2(acc[r][p], ap, bp[p]);
                }
            }
        }
    }
    __syncthreads();

    const float rs = rsqrtf(1.f + EPS_BN);
#pragma unroll
    for (int r = 0; r < 4; r++) {
        int row = tr * 4 + r;
#pragma unroll
        for (int p = 0; p < 4; p++) {
            int j0 = tc * 8 + 2 * p;
            float lo = __uint_as_float((unsigned)acc[r][p]);
            float hi = __uint_as_float((unsigned)(acc[r][p] >> 32));
            As[row][j0]     = fmaxf(fmaf(lo + bq[j0],     gq[j0]     * rs, betaq[j0]),     0.f);
            As[row][j0 + 1] = fmaxf(fmaf(hi + bq[j0 + 1], gq[j0 + 1] * rs, betaq[j0 + 1]), 0.f);
        }
    }
    __syncthreads();
#pragma unroll
    for (int s2 = 0; s2 < 2; s2++) {
        int task = tid + s2 * 256;
        int row = task >> 3, g = task & 7;
        float a = 0.f;
#pragma unroll 8
        for (int c = 0; c < C_DIM; c++) a = fmaf(As[row][c], Ww1[c * G_DIM + g], a);
        g_qw[(size_t)(bm0 + row) * G_DIM + g] = a;
    }
}

// ---------------- K3: attention weights + U/H accumulation -------------------
struct S3 {
    float WpwT[G_DIM * 132];
    float ww2s[G_DIM * G_DIM];
    float hs[2][KNN * 132];
    float e_s[KNN * G_DIM];
    float psum[4 * G_DIM];
    float wpsum[4 * G_DIM];
    float pos[2][KNN * 4];
    float kwg[2][KNN * G_DIM];
    float qw[2][G_DIM];
    float msk[2][KNN];
    int   idx[2][KNN];
};

__device__ __forceinline__ void gatherK(S3* s, const int* __restrict__ knn,
                                        const float* __restrict__ qcoord,
                                        const float* __restrict__ ccoord,
                                        int m, int p, int k) {
    int id = knn[(size_t)m * KNN + k];
    float mk = id >= 0 ? 1.f : 0.f;
    int id0 = id >= 0 ? id : 0;
    s->idx[p][k] = id0;
    s->msk[p][k] = mk;
    float qx = qcoord[m * 3 + 0], qy = qcoord[m * 3 + 1], qz = qcoord[m * 3 + 2];
    s->pos[p][k * 4 + 0] = (ccoord[(size_t)id0 * 3 + 0] - qx) * mk;
    s->pos[p][k * 4 + 1] = (ccoord[(size_t)id0 * 3 + 1] - qy) * mk;
    s->pos[p][k * 4 + 2] = (ccoord[(size_t)id0 * 3 + 2] - qz) * mk;
    const float4* kwp = (const float4*)&g_kw[(size_t)id0 * G_DIM];
    float4 a = kwp[0], b = kwp[1];
    float* kd = &s->kwg[p][k * 8];
    kd[0] = a.x * mk; kd[1] = a.y * mk; kd[2] = a.z * mk; kd[3] = a.w * mk;
    kd[4] = b.x * mk; kd[5] = b.y * mk; kd[6] = b.z * mk; kd[7] = b.w * mk;
}

__launch_bounds__(128, 4)
__global__ void k3_attn(const float* __restrict__ qcoord, const float* __restrict__ ccoord,
                        const int*   __restrict__ knn, const float* __restrict__ cf,
                        const float* __restrict__ Wp1, const float* __restrict__ bp1,
                        const float* __restrict__ gp1, const float* __restrict__ betap1,
                        const float* __restrict__ bw1, const float* __restrict__ gw1,
                        const float* __restrict__ betaw1,
                        const float* __restrict__ Ww2, const float* __restrict__ bw2) {
    __shared__ S3 s;
    const int t = threadIdx.x;
    const int c = t, gc = t >> 4;
    const int kB = t >> 3, gB = t & 7;
    const int w4 = t >> 5;
    const int lane = t & 31;
    const int lbase = lane & ~7;

    for (int i = t; i < G_DIM * C_DIM; i += 128) {
        int r = i >> 7, cc2 = i & 127;
        s.WpwT[r * 132 + cc2] = g_WpwT[i];
    }
    if (t < G_DIM * G_DIM) s.ww2s[t] = Ww2[t];

    const float rs  = rsqrtf(1.f + EPS_BN);
    const float sp1 = gp1[c] * rs;
    const float wf0 = Wp1[c] * sp1, wf1 = Wp1[C_DIM + c] * sp1, wf2 = Wp1[2 * C_DIM + c] * sp1;
    const float hb  = fmaf(bp1[c], sp1, betap1[c]);
    const float sw1  = gw1[gB] * rs;
    const float wb1f = fmaf(bw1[gB], sw1, betaw1[gB]);
    const float pwbB = g_pwb[gB];
    const float bw2B = bw2[gB];

    const int mb = blockIdx.x * 8;
    float cfpre[KNN];

    if (t < KNN)   gatherK(&s, knn, qcoord, ccoord, mb, 0, t);
    if (t < G_DIM) s.qw[0][t] = g_qw[(size_t)mb * G_DIM + t];
    __syncthreads();

    for (int qi = 0; qi < 8; qi++) {
        const int b = qi & 1;
        const int m = mb + qi;

        {
#pragma unroll
            for (int k = 0; k < KNN; k++) {
                const float* pp = &s.pos[b][k * 4];
                s.hs[b][k * 132 + c] =
                    fmaxf(fmaf(wf0, pp[0], fmaf(wf1, pp[1], fmaf(wf2, pp[2], hb))), 0.f);
            }
            if (qi < 7) {
                if (t < KNN)   gatherK(&s, knn, qcoord, ccoord, m + 1, b ^ 1, t);
                if (t < G_DIM) s.qw[b ^ 1][t] = g_qw[(size_t)(m + 1) * G_DIM + t];
            }
            if (qi > 0) {
                const int bp = b ^ 1;
                const int mp = m - 1;
                float hh[G_DIM], uu[G_DIM];
#pragma unroll
                for (int g2 = 0; g2 < G_DIM; g2++) { hh[g2] = 0.f; uu[g2] = 0.f; }
#pragma unroll
                for (int k = 0; k < KNN; k++) {
                    float hk = s.hs[bp][k * 132 + c];
                    float cv = cfpre[k];
                    float4 ea = *(const float4*)&s.e_s[k * 8];
                    float4 eb = *(const float4*)&s.e_s[k * 8 + 4];
                    uu[0] = fmaf(cv, ea.x, uu[0]); hh[0] = fmaf(hk, ea.x, hh[0]);
                    uu[1] = fmaf(cv, ea.y, uu[1]); hh[1] = fmaf(hk, ea.y, hh[1]);
                    uu[2] = fmaf(cv, ea.z, uu[2]); hh[2] = fmaf(hk, ea.z, hh[2]);
                    uu[3] = fmaf(cv, ea.w, uu[3]); hh[3] = fmaf(hk, ea.w, hh[3]);
                    uu[4] = fmaf(cv, eb.x, uu[4]); hh[4] = fmaf(hk, eb.x, hh[4]);
                    uu[5] = fmaf(cv, eb.y, uu[5]); hh[5] = fmaf(hk, eb.y, hh[5]);
                    uu[6] = fmaf(cv, eb.z, uu[6]); hh[6] = fmaf(hk, eb.z, hh[6]);
                    uu[7] = fmaf(cv, eb.w, uu[7]); hh[7] = fmaf(hk, eb.w, hh[7]);
                }
                float* base = &g_Hs2[(size_t)mp * (G_DIM * 256)];
#pragma unroll
                for (int g2 = 0; g2 < G_DIM; g2++) {
                    base[g2 * 256 + c]       = uu[g2];
                    base[g2 * 256 + 128 + c] = hh[g2];
                }
                if (t < G_DIM) {
                    g_sums[(size_t)mp * G_DIM + t] =
                        s.psum[t] + s.psum[8 + t] + s.psum[16 + t] + s.psum[24 + t];
                    g_wsr[(size_t)mp * G_DIM + t] =
                        s.wpsum[t] + s.wpsum[8 + t] + s.wpsum[16 + t] + s.wpsum[24 + t];
                }
            }
        }
        __syncthreads();

        {
            float a0 = s.kwg[b][t] - s.qw[b][gB] + pwbB;
            float a1 = 0.f, a2 = 0.f, a3 = 0.f;
            const float4* hr = (const float4*)&s.hs[b][kB * 132];
            const float4* wr = (const float4*)&s.WpwT[gB * 132];
#pragma unroll
            for (int j = 0; j < 32; j += 4) {
                float4 h0 = hr[j],     w0 = wr[j];
                float4 h1 = hr[j + 1], w1 = wr[j + 1];
                float4 h2 = hr[j + 2], w2 = wr[j + 2];
                float4 h3 = hr[j + 3], w3 = wr[j + 3];
                a0 = fmaf(h0.x, w0.x, fmaf(h0.y, w0.y, fmaf(h0.z, w0.z, fmaf(h0.w, w0.w, a0))));
                a1 = fmaf(h1.x, w1.x, fmaf(h1.y, w1.y, fmaf(h1.z, w1.z, fmaf(h1.w, w1.w, a1))));
                a2 = fmaf(h2.x, w2.x, fmaf(h2.y, w2.y, fmaf(h2.z, w2.z, fmaf(h2.w, w2.w, a2))));
                a3 = fmaf(h3.x, w3.x, fmaf(h3.y, w3.y, fmaf(h3.z, w3.z, fmaf(h3.w, w3.w, a3))));
            }
            float ts = fmaxf(fmaf((a0 + a1) + (a2 + a3), sw1, wb1f), 0.f);

            float lg = bw2B;
#pragma unroll
            for (int g2 = 0; g2 < G_DIM; g2++)
                lg = fmaf(__shfl_sync(0xffffffffu, ts, lbase + g2), s.ww2s[g2 * G_DIM + gB], lg);

            float e  = __expf(lg);
            float mk = s.msk[b][kB];
            float em = e * mk;
            s.e_s[t] = em;
            float es = e;
            es += __shfl_xor_sync(0xffffffffu, es, 8);
            es += __shfl_xor_sync(0xffffffffu, es, 16);
            float esm = em;
            esm += __shfl_xor_sync(0xffffffffu, esm, 8);
            esm += __shfl_xor_sync(0xffffffffu, esm, 16);
            if (lane < 8) { s.psum[w4 * 8 + gB] = es; s.wpsum[w4 * 8 + gB] = esm; }

            const int* ix = s.idx[b];
#pragma unroll
            for (int k = 0; k < KNN; k++) cfpre[k] = cf[(size_t)ix[k] * C_DIM + c];
        }
        __syncthreads();
    }

    {
        const int bp = 1;
        const int mp = mb + 7;
        float hh[G_DIM], uu[G_DIM];
#pragma unroll
        for (int g2 = 0; g2 < G_DIM; g2++) { hh[g2] = 0.f; uu[g2] = 0.f; }
#pragma unroll
        for (int k = 0; k < KNN; k++) {
            float hk = s.hs[bp][k * 132 + c];
            float cv = cfpre[k];
            float4 ea = *(const float4*)&s.e_s[k * 8];
            float4 eb = *(const float4*)&s.e_s[k * 8 + 4];
            uu[0] = fmaf(cv, ea.x, uu[0]); hh[0] = fmaf(hk, ea.x, hh[0]);
            uu[1] = fmaf(cv, ea.y, uu[1]); hh[1] = fmaf(hk, ea.y, hh[1]);
            uu[2] = fmaf(cv, ea.z, uu[2]); hh[2] = fmaf(hk, ea.z, hh[2]);
            uu[3] = fmaf(cv, ea.w, uu[3]); hh[3] = fmaf(hk, ea.w, hh[3]);
            uu[4] = fmaf(cv, eb.x, uu[4]); hh[4] = fmaf(hk, eb.x, hh[4]);
            uu[5] = fmaf(cv, eb.y, uu[5]); hh[5] = fmaf(hk, eb.y, hh[5]);
            uu[6] = fmaf(cv, eb.z, uu[6]); hh[6] = fmaf(hk, eb.z, hh[6]);
            uu[7] = fmaf(cv, eb.w, uu[7]); hh[7] = fmaf(hk, eb.w, hh[7]);
        }
        float* base = &g_Hs2[(size_t)mp * (G_DIM * 256)];
#pragma unroll
        for (int g2 = 0; g2 < G_DIM; g2++) {
            base[g2 * 256 + c]       = uu[g2];
            base[g2 * 256 + 128 + c] = hh[g2];
        }
        if (t < G_DIM) {
            g_sums[(size_t)mp * G_DIM + t] =
                s.psum[t] + s.psum[8 + t] + s.psum[16 + t] + s.psum[24 + t];
            g_wsr[(size_t)mp * G_DIM + t] =
                s.wpsum[t] + s.wpsum[8 + t] + s.wpsum[16 + t] + s.wpsum[24 + t];
        }
    }
}

// ---------------- K4: grouped epilogue GEMM ----------------------------------
__launch_bounds__(256, 6)
__global__ void k4_out(const float* __restrict__ Wv, const float* __restrict__ Wp2,
                       const float* __restrict__ bv, const float* __restrict__ bp2,
                       float* __restrict__ out) {
    __shared__ float As[16][260];
    __shared__ float BsT[16][260];
    const int m0 = blockIdx.x * 16;
    const int g  = blockIdx.y;
    const int tid = threadIdx.x;

    for (int i = tid; i < 1024; i += 256) {
        int r = i >> 6, j4 = i & 63;
        *(float4*)&As[r][j4 * 4] =
            *(const float4*)&g_Hs2[(size_t)(m0 + r) * (G_DIM * 256) + g * 256 + j4 * 4];
    }
    for (int i = tid; i < 4096; i += 256) {
        int j = i >> 4, cc0 = i & 15;
        float v = (j < 128) ? Wv[(size_t)j * C_DIM + g * 16 + cc0]
                            : Wp2[(size_t)(j - 128) * C_DIM + g * 16 + cc0];
        BsT[cc0][j] = v;
    }
    __syncthreads();

    const int r = tid >> 4, cc = tid & 15;
    float a0 = 0.f, a1 = 0.f, a2 = 0.f, a3 = 0.f;
    const float4* ar = (const float4*)&As[r][0];
    const float4* br = (const float4*)&BsT[cc][0];
#pragma unroll
    for (int j = 0; j < 64; j += 4) {
        float4 x0 = ar[j],     y0 = br[j];
        float4 x1 = ar[j + 1], y1 = br[j + 1];
        float4 x2 = ar[j + 2], y2 = br[j + 2];
        float4 x3 = ar[j + 3], y3 = br[j + 3];
        a0 = fmaf(x0.x, y0.x, fmaf(x0.y, y0.y, fmaf(x0.z, y0.z, fmaf(x0.w, y0.w, a0))));
        a1 = fmaf(x1.x, y1.x, fmaf(x1.y, y1.y, fmaf(x1.z, y1.z, fmaf(x1.w, y1.w, a1))));
        a2 = fmaf(x2.x, y2.x, fmaf(x2.y, y2.y, fmaf(x2.z, y2.z, fmaf(x2.w, y2.w, a2))));
        a3 = fmaf(x3.x, y3.x, fmaf(x3.y, y3.y, fmaf(x3.z, y3.z, fmaf(x3.w, y3.w, a3))));
    }
    float acc = (a0 + a1) + (a2 + a3);
    const int m = m0 + r;
    const int c = g * 16 + cc;
    float inv = 1.f / g_sums[(size_t)m * G_DIM + g];
    float wsr = g_wsr[(size_t)m * G_DIM + g];
    out[(size_t)m * C_DIM + c] = (acc + (bv[c] + bp2[c]) * wsr) * inv;
}

// ---------------- launch -----------------------------------------------------
extern "C" void kernel_launch(void* const* d_in, const int* in_sizes, int n_in,
                              void* d_out, int out_size) {
    const float* qf     = (const float*)d_in[0];
    const float* cf     = (const float*)d_in[1];
    const float* qc     = (const float*)d_in[2];
    const float* cc     = (const float*)d_in[3];
    const float* Wq     = (const float*)d_in[4];
    const float* bq     = (const float*)d_in[5];
    const float* gq     = (const float*)d_in[6];
    const float* betaq  = (const float*)d_in[7];
    const float* Wk     = (const float*)d_in[8];
    const float* bk     = (const float*)d_in[9];
    const float* gk     = (const float*)d_in[10];
    const float* betak  = (const float*)d_in[11];
    const float* Wv     = (const float*)d_in[12];
    const float* bv     = (const float*)d_in[13];
    const float* Wp1    = (const float*)d_in[14];
    const float* bp1    = (const float*)d_in[15];
    const float* gp1    = (const float*)d_in[16];
    const float* betap1 = (const float*)d_in[17];
    const float* Wp2    = (const float*)d_in[18];
    const float* bp2    = (const float*)d_in[19];
    const float* Ww1    = (const float*)d_in[20];
    const float* bw1    = (const float*)d_in[21];
    const float* gw1    = (const float*)d_in[22];
    const float* betaw1 = (const float*)d_in[23];
    const float* Ww2    = (const float*)d_in[24];
    const float* bw2    = (const float*)d_in[25];
    const int*   knn    = (const int*)d_in[26];
    float* out = (float*)d_out;

    const int M = in_sizes[0] / C_DIM;
    const int N = in_sizes[1] / C_DIM;

    k0_prep<<<1, 128>>>(Wp2, Ww1, bp2);

    cudaFuncSetAttribute(k1_context, cudaFuncAttributeMaxDynamicSharedMemorySize,
                         SMEM_K1_TOTAL);
    k1_context<<<N / 128, 256, SMEM_K1_TOTAL>>>(cf, Wk, bk, gk, betak, Ww1);

    k2_query<<<M / 64, 256>>>(qf, Wq, bq, gq, betaq, Ww1);
    k3_attn<<<M / 8, 128>>>(qc, cc, knn, cf, Wp1, bp1, gp1, betap1,
                            bw1, gw1, betaw1, Ww2, bw2);
    dim3 g4(M / 16, G_DIM);
    k4_out<<<g4, 256>>>(Wv, Wp2, bv, bp2, out);
}

// round 6
// speedup vs baseline: 1.5195x; 1.0795x over previous
#include <cuda_runtime.h>
#include <cuda_bf16.h>
#include <cstdint>

#define C_DIM 128
#define G_DIM 8
#define KNN   16
#define EPS_BN 1e-5f
#define N_CTX_MAX 131072
#define M_Q_MAX   16384

// ---------------- scratch (static device memory; no runtime allocation) -----
__device__ float g_kw  [(size_t)N_CTX_MAX * G_DIM];      // relu(bn(cf@Wk))@Ww1
__device__ float g_qw  [(size_t)M_Q_MAX   * G_DIM];      // relu(bn(qf@Wq))@Ww1
__device__ float g_WpwT[G_DIM * C_DIM];                  // [g][c2] = (Wp2@Ww1)[c2][g]
__device__ float g_pwb [G_DIM];                          // bp2 @ Ww1
__device__ float g_Hs2 [(size_t)M_Q_MAX * G_DIM * 256];  // [m][g][0:128]=U, [128:256]=H
__device__ float g_sums[(size_t)M_Q_MAX * G_DIM];        // raw softmax denominators
__device__ float g_wsr [(size_t)M_Q_MAX * G_DIM];        // raw masked weight sums

typedef unsigned long long ull;

// bf16 HMMA m16n8k16 (sm_80+ PTX; no arch-suffix features)
__device__ __forceinline__ void mma_bf16(float* d, uint32_t a0, uint32_t a1,
                                         uint32_t a2, uint32_t a3,
                                         uint32_t b0, uint32_t b1) {
    asm volatile(
        "mma.sync.aligned.m16n8k16.row.col.f32.bf16.bf16.f32 "
        "{%0,%1,%2,%3}, {%4,%5,%6,%7}, {%8,%9}, {%0,%1,%2,%3};"
        : "+f"(d[0]), "+f"(d[1]), "+f"(d[2]), "+f"(d[3])
        : "r"(a0), "r"(a1), "r"(a2), "r"(a3), "r"(b0), "r"(b1));
}

// ---------------- K0: tiny prep ---------------------------------------------
__global__ void k0_prep(const float* __restrict__ Wp2,
                        const float* __restrict__ Ww1,
                        const float* __restrict__ bp2) {
    int c = threadIdx.x;  // 128 threads
    float acc[G_DIM];
#pragma unroll
    for (int g = 0; g < G_DIM; g++) acc[g] = 0.f;
    for (int c2 = 0; c2 < C_DIM; c2++) {
        float a = Wp2[c * C_DIM + c2];
#pragma unroll
        for (int g = 0; g < G_DIM; g++) acc[g] = fmaf(a, Ww1[c2 * G_DIM + g], acc[g]);
    }
#pragma unroll
    for (int g = 0; g < G_DIM; g++) g_WpwT[g * C_DIM + c] = acc[g];
    if (c < G_DIM) {
        float s = 0.f;
        for (int c2 = 0; c2 < C_DIM; c2++) s = fmaf(bp2[c2], Ww1[c2 * G_DIM + c], s);
        g_pwb[c] = s;
    }
}

// ---------------- K12: fused context+query pass (bf16-split HMMA, occ 2) -----
// blocks [0, NB): context rows (cf, Wk) -> g_kw
// blocks [NB, NB+MB): query rows (qf, Wq) -> g_qw
// 64-row A tile; B = W^T full 128x128. smem 108 KB -> 2 CTAs/SM.
#define K1_ROWB 272      // bytes per row (136 bf16), fragment-packed
__device__ __forceinline__ uint32_t k1_off(int row, int k) {  // k even
    int p = k >> 1;
    return (uint32_t)row * K1_ROWB + (uint32_t)(k >> 4) * 32
         + (uint32_t)(p & 3) * 8 + (uint32_t)((p >> 2) & 1) * 4;
}

#define SM_AH   0          // 17408
#define SM_AL   17408      // 17408
#define SM_BH   34816      // 34816
#define SM_BL   69632      // 34816
#define SM_PAR  104448     // float4[128]: (b, g*rs, beta, 0)
#define SM_W1   106496     // float[128*8] Ww1
#define SM_KS   0          // float[64][130] k tile (reuses A region post-MMA)
#define SMEM_K12_TOTAL 110592

__launch_bounds__(256, 2)
__global__ void k12_proj(const float* __restrict__ cf, const float* __restrict__ qf,
                         const float* __restrict__ Wk, const float* __restrict__ bk,
                         const float* __restrict__ gk, const float* __restrict__ betak,
                         const float* __restrict__ Wq, const float* __restrict__ bq,
                         const float* __restrict__ gq, const float* __restrict__ betaq,
                         const float* __restrict__ Ww1, int NB) {
    extern __shared__ char smem[];
    const int tid = threadIdx.x;
    const int wid = tid >> 5;
    const int lane = tid & 31;
    const int grp = lane >> 2, tig = lane & 3;

    const bool ctx = (int)blockIdx.x < NB;
    const int bm0 = (ctx ? (int)blockIdx.x : (int)blockIdx.x - NB) * 64;
    const float* feat = ctx ? cf : qf;
    const float* W    = ctx ? Wk : Wq;
    const float* bb   = ctx ? bk : bq;
    const float* gg   = ctx ? gk : gq;
    const float* be   = ctx ? betak : betaq;
    float* dst        = ctx ? g_kw : g_qw;

    // ---- fill A tile (64 rows, hi/lo bf16 split) ----
    {
        const int row = tid >> 2, q = tid & 3;   // 32 cols per thread
        const float4* src = (const float4*)&feat[(size_t)(bm0 + row) * C_DIM + q * 32];
#pragma unroll
        for (int j = 0; j < 8; j++) {
            float4 x = src[j];
            int c0 = q * 32 + j * 4;
#pragma unroll
            for (int p = 0; p < 2; p++) {
                float a0 = (&x.x)[2 * p], a1 = (&x.x)[2 * p + 1];
                __nv_bfloat16 h0 = __float2bfloat16(a0), h1 = __float2bfloat16(a1);
                __nv_bfloat16 l0 = __float2bfloat16(a0 - __bfloat162float(h0));
                __nv_bfloat16 l1 = __float2bfloat16(a1 - __bfloat162float(h1));
                uint32_t off = k1_off(row, c0 + 2 * p);
                *(__nv_bfloat162*)(smem + SM_AH + off) = __nv_bfloat162(h0, h1);
                *(__nv_bfloat162*)(smem + SM_AL + off) = __nv_bfloat162(l0, l1);
            }
        }
    }
    // ---- fill B tile: B[n][k] = W[k][n], hi/lo split ----
    for (int i = tid; i < 8192; i += 256) {
        int n = i & 127, p = i >> 7, k = 2 * p;
        float v0 = W[(size_t)k * C_DIM + n];
        float v1 = W[(size_t)(k + 1) * C_DIM + n];
        __nv_bfloat16 h0 = __float2bfloat16(v0), h1 = __float2bfloat16(v1);
        __nv_bfloat16 l0 = __float2bfloat16(v0 - __bfloat162float(h0));
        __nv_bfloat16 l1 = __float2bfloat16(v1 - __bfloat162float(h1));
        uint32_t off = k1_off(n, k);
        *(__nv_bfloat162*)(smem + SM_BH + off) = __nv_bfloat162(h0, h1);
        *(__nv_bfloat162*)(smem + SM_BL + off) = __nv_bfloat162(l0, l1);
    }
    // ---- params ----
    const float rs = rsqrtf(1.f + EPS_BN);
    if (tid < C_DIM) {
        float4 pp; pp.x = bb[tid]; pp.y = gg[tid] * rs; pp.z = be[tid]; pp.w = 0.f;
        *(float4*)(smem + SM_PAR + tid * 16) = pp;
    }
    *(float4*)(smem + SM_W1 + tid * 16) = *(const float4*)&Ww1[tid * 4];
    __syncthreads();

    // ---- MMA: warp (wid&3) owns rows (wid&3)*16..+16; (wid>>2) picks col half
    const int rbase = (wid & 3) * 16;
    const int cbase = (wid >> 2) * 64;
    float acc[8][4];
#pragma unroll
    for (int nt = 0; nt < 8; nt++)
#pragma unroll
        for (int q = 0; q < 4; q++) acc[nt][q] = 0.f;

    const uint32_t aoff_lo = k1_off(rbase + grp, 0) + tig * 8;
    const uint32_t aoff_hi = k1_off(rbase + grp + 8, 0) + tig * 8;

#pragma unroll
    for (int ks = 0; ks < 8; ks++) {
        const uint32_t kb = ks * 32;
        ull alo_h = *(const ull*)(smem + SM_AH + aoff_lo + kb);
        ull ahi_h = *(const ull*)(smem + SM_AH + aoff_hi + kb);
        ull alo_l = *(const ull*)(smem + SM_AL + aoff_lo + kb);
        ull ahi_l = *(const ull*)(smem + SM_AL + aoff_hi + kb);
        uint32_t a0h = (uint32_t)alo_h, a2h = (uint32_t)(alo_h >> 32);
        uint32_t a1h = (uint32_t)ahi_h, a3h = (uint32_t)(ahi_h >> 32);
        uint32_t a0l = (uint32_t)alo_l, a2l = (uint32_t)(alo_l >> 32);
        uint32_t a1l = (uint32_t)ahi_l, a3l = (uint32_t)(ahi_l >> 32);
#pragma unroll
        for (int nt = 0; nt < 8; nt++) {
            uint32_t boff = (uint32_t)(cbase + nt * 8 + grp) * K1_ROWB + kb + tig * 8;
            ull bh = *(const ull*)(smem + SM_BH + boff);
            ull bl = *(const ull*)(smem + SM_BL + boff);
            uint32_t b0h = (uint32_t)bh, b1h = (uint32_t)(bh >> 32);
            uint32_t b0l = (uint32_t)bl, b1l = (uint32_t)(bl >> 32);
            mma_bf16(acc[nt], a0h, a1h, a2h, a3h, b0h, b1h);
            mma_bf16(acc[nt], a0h, a1h, a2h, a3h, b0l, b1l);
            mma_bf16(acc[nt], a0l, a1l, a2l, a3l, b0h, b1h);
        }
    }
    __syncthreads();   // A smem dead; reuse for k tile

    // ---- epilogue: relu(bn) -> k tile in smem ----
    {
        float* ks_s = (float*)(smem + SM_KS);
        const float4* par = (const float4*)(smem + SM_PAR);
        const int r0 = rbase + grp, r1 = r0 + 8;
#pragma unroll
        for (int nt = 0; nt < 8; nt++) {
            int col = cbase + nt * 8 + tig * 2;
            float4 p0 = par[col], p1 = par[col + 1];
            float2 lo, hi;
            lo.x = fmaxf(fmaf(acc[nt][0] + p0.x, p0.y, p0.z), 0.f);
            lo.y = fmaxf(fmaf(acc[nt][1] + p1.x, p1.y, p1.z), 0.f);
            hi.x = fmaxf(fmaf(acc[nt][2] + p0.x, p0.y, p0.z), 0.f);
            hi.y = fmaxf(fmaf(acc[nt][3] + p1.x, p1.y, p1.z), 0.f);
            *(float2*)&ks_s[r0 * 130 + col] = lo;
            *(float2*)&ks_s[r1 * 130 + col] = hi;
        }
    }
    __syncthreads();

    // ---- kw = k @ Ww1 -> dst (64 rows x 8 g = 512 tasks, 2 per thread) ----
    {
        const float* ks_s = (const float*)(smem + SM_KS);
        const float* W1   = (const float*)(smem + SM_W1);
#pragma unroll
        for (int s2 = 0; s2 < 2; s2++) {
            int task = tid + s2 * 256;
            int row = task >> 3, g = task & 7;
            const float* kr = &ks_s[row * 130];
            float a0 = 0.f, a1 = 0.f, a2 = 0.f, a3 = 0.f;
#pragma unroll 8
            for (int c = 0; c < C_DIM; c += 4) {
                a0 = fmaf(kr[c],     W1[(c)     * G_DIM + g], a0);
                a1 = fmaf(kr[c + 1], W1[(c + 1) * G_DIM + g], a1);
                a2 = fmaf(kr[c + 2], W1[(c + 2) * G_DIM + g], a2);
                a3 = fmaf(kr[c + 3], W1[(c + 3) * G_DIM + g], a3);
            }
            dst[(size_t)(bm0 + row) * G_DIM + g] = (a0 + a1) + (a2 + a3);
        }
    }
}

// ---------------- K3: attention weights + U/H accumulation -------------------
struct S3 {
    float WpwT[G_DIM * 132];
    float ww2s[G_DIM * G_DIM];
    float hs[2][KNN * 132];
    float e_s[KNN * G_DIM];
    float psum[4 * G_DIM];
    float wpsum[4 * G_DIM];
    float pos[2][KNN * 4];
    float kwg[2][KNN * G_DIM];
    float qw[2][G_DIM];
    float msk[2][KNN];
    int   idx[2][KNN];
};

__device__ __forceinline__ void gatherK(S3* s, const int* __restrict__ knn,
                                        const float* __restrict__ qcoord,
                                        const float* __restrict__ ccoord,
                                        int m, int p, int k) {
    int id = knn[(size_t)m * KNN + k];
    float mk = id >= 0 ? 1.f : 0.f;
    int id0 = id >= 0 ? id : 0;
    s->idx[p][k] = id0;
    s->msk[p][k] = mk;
    float qx = qcoord[m * 3 + 0], qy = qcoord[m * 3 + 1], qz = qcoord[m * 3 + 2];
    s->pos[p][k * 4 + 0] = (ccoord[(size_t)id0 * 3 + 0] - qx) * mk;
    s->pos[p][k * 4 + 1] = (ccoord[(size_t)id0 * 3 + 1] - qy) * mk;
    s->pos[p][k * 4 + 2] = (ccoord[(size_t)id0 * 3 + 2] - qz) * mk;
    const float4* kwp = (const float4*)&g_kw[(size_t)id0 * G_DIM];
    float4 a = kwp[0], b = kwp[1];
    float* kd = &s->kwg[p][k * 8];
    kd[0] = a.x * mk; kd[1] = a.y * mk; kd[2] = a.z * mk; kd[3] = a.w * mk;
    kd[4] = b.x * mk; kd[5] = b.y * mk; kd[6] = b.z * mk; kd[7] = b.w * mk;
}

__launch_bounds__(128, 4)
__global__ void k3_attn(const float* __restrict__ qcoord, const float* __restrict__ ccoord,
                        const int*   __restrict__ knn, const float* __restrict__ cf,
                        const float* __restrict__ Wp1, const float* __restrict__ bp1,
                        const float* __restrict__ gp1, const float* __restrict__ betap1,
                        const float* __restrict__ bw1, const float* __restrict__ gw1,
                        const float* __restrict__ betaw1,
                        const float* __restrict__ Ww2, const float* __restrict__ bw2) {
    __shared__ S3 s;
    const int t = threadIdx.x;
    const int c = t, gc = t >> 4;
    const int kB = t >> 3, gB = t & 7;
    const int w4 = t >> 5;
    const int lane = t & 31;
    const int lbase = lane & ~7;

    for (int i = t; i < G_DIM * C_DIM; i += 128) {
        int r = i >> 7, cc2 = i & 127;
        s.WpwT[r * 132 + cc2] = g_WpwT[i];
    }
    if (t < G_DIM * G_DIM) s.ww2s[t] = Ww2[t];

    const float rs  = rsqrtf(1.f + EPS_BN);
    const float sp1 = gp1[c] * rs;
    const float wf0 = Wp1[c] * sp1, wf1 = Wp1[C_DIM + c] * sp1, wf2 = Wp1[2 * C_DIM + c] * sp1;
    const float hb  = fmaf(bp1[c], sp1, betap1[c]);
    const float sw1  = gw1[gB] * rs;
    const float wb1f = fmaf(bw1[gB], sw1, betaw1[gB]);
    const float pwbB = g_pwb[gB];
    const float bw2B = bw2[gB];

    const int mb = blockIdx.x * 8;
    float cfpre[KNN];

    if (t < KNN)   gatherK(&s, knn, qcoord, ccoord, mb, 0, t);
    if (t < G_DIM) s.qw[0][t] = g_qw[(size_t)mb * G_DIM + t];
    __syncthreads();

    for (int qi = 0; qi < 8; qi++) {
        const int b = qi & 1;
        const int m = mb + qi;

        {
#pragma unroll
            for (int k = 0; k < KNN; k++) {
                const float* pp = &s.pos[b][k * 4];
                s.hs[b][k * 132 + c] =
                    fmaxf(fmaf(wf0, pp[0], fmaf(wf1, pp[1], fmaf(wf2, pp[2], hb))), 0.f);
            }
            if (qi < 7) {
                if (t < KNN)   gatherK(&s, knn, qcoord, ccoord, m + 1, b ^ 1, t);
                if (t < G_DIM) s.qw[b ^ 1][t] = g_qw[(size_t)(m + 1) * G_DIM + t];
            }
            if (qi > 0) {
                const int bp = b ^ 1;
                const int mp = m - 1;
                float hh[G_DIM], uu[G_DIM];
#pragma unroll
                for (int g2 = 0; g2 < G_DIM; g2++) { hh[g2] = 0.f; uu[g2] = 0.f; }
#pragma unroll
                for (int k = 0; k < KNN; k++) {
                    float hk = s.hs[bp][k * 132 + c];
                    float cv = cfpre[k];
                    float4 ea = *(const float4*)&s.e_s[k * 8];
                    float4 eb = *(const float4*)&s.e_s[k * 8 + 4];
                    uu[0] = fmaf(cv, ea.x, uu[0]); hh[0] = fmaf(hk, ea.x, hh[0]);
                    uu[1] = fmaf(cv, ea.y, uu[1]); hh[1] = fmaf(hk, ea.y, hh[1]);
                    uu[2] = fmaf(cv, ea.z, uu[2]); hh[2] = fmaf(hk, ea.z, hh[2]);
                    uu[3] = fmaf(cv, ea.w, uu[3]); hh[3] = fmaf(hk, ea.w, hh[3]);
                    uu[4] = fmaf(cv, eb.x, uu[4]); hh[4] = fmaf(hk, eb.x, hh[4]);
                    uu[5] = fmaf(cv, eb.y, uu[5]); hh[5] = fmaf(hk, eb.y, hh[5]);
                    uu[6] = fmaf(cv, eb.z, uu[6]); hh[6] = fmaf(hk, eb.z, hh[6]);
                    uu[7] = fmaf(cv, eb.w, uu[7]); hh[7] = fmaf(hk, eb.w, hh[7]);
                }
                float* base = &g_Hs2[(size_t)mp * (G_DIM * 256)];
#pragma unroll
                for (int g2 = 0; g2 < G_DIM; g2++) {
                    base[g2 * 256 + c]       = uu[g2];
                    base[g2 * 256 + 128 + c] = hh[g2];
                }
                if (t < G_DIM) {
                    g_sums[(size_t)mp * G_DIM + t] =
                        s.psum[t] + s.psum[8 + t] + s.psum[16 + t] + s.psum[24 + t];
                    g_wsr[(size_t)mp * G_DIM + t] =
                        s.wpsum[t] + s.wpsum[8 + t] + s.wpsum[16 + t] + s.wpsum[24 + t];
                }
            }
        }
        __syncthreads();

        {
            float a0 = s.kwg[b][t] - s.qw[b][gB] + pwbB;
            float a1 = 0.f, a2 = 0.f, a3 = 0.f;
            const float4* hr = (const float4*)&s.hs[b][kB * 132];
            const float4* wr = (const float4*)&s.WpwT[gB * 132];
#pragma unroll
            for (int j = 0; j < 32; j += 4) {
                float4 h0 = hr[j],     w0 = wr[j];
                float4 h1 = hr[j + 1], w1 = wr[j + 1];
                float4 h2 = hr[j + 2], w2 = wr[j + 2];
                float4 h3 = hr[j + 3], w3 = wr[j + 3];
                a0 = fmaf(h0.x, w0.x, fmaf(h0.y, w0.y, fmaf(h0.z, w0.z, fmaf(h0.w, w0.w, a0))));
                a1 = fmaf(h1.x, w1.x, fmaf(h1.y, w1.y, fmaf(h1.z, w1.z, fmaf(h1.w, w1.w, a1))));
                a2 = fmaf(h2.x, w2.x, fmaf(h2.y, w2.y, fmaf(h2.z, w2.z, fmaf(h2.w, w2.w, a2))));
                a3 = fmaf(h3.x, w3.x, fmaf(h3.y, w3.y, fmaf(h3.z, w3.z, fmaf(h3.w, w3.w, a3))));
            }
            float ts = fmaxf(fmaf((a0 + a1) + (a2 + a3), sw1, wb1f), 0.f);

            float lg = bw2B;
#pragma unroll
            for (int g2 = 0; g2 < G_DIM; g2++)
                lg = fmaf(__shfl_sync(0xffffffffu, ts, lbase + g2), s.ww2s[g2 * G_DIM + gB], lg);

            float e  = __expf(lg);
            float mk = s.msk[b][kB];
            float em = e * mk;
            s.e_s[t] = em;
            float es = e;
            es += __shfl_xor_sync(0xffffffffu, es, 8);
            es += __shfl_xor_sync(0xffffffffu, es, 16);
            float esm = em;
            esm += __shfl_xor_sync(0xffffffffu, esm, 8);
            esm += __shfl_xor_sync(0xffffffffu, esm, 16);
            if (lane < 8) { s.psum[w4 * 8 + gB] = es; s.wpsum[w4 * 8 + gB] = esm; }

            const int* ix = s.idx[b];
#pragma unroll
            for (int k = 0; k < KNN; k++) cfpre[k] = cf[(size_t)ix[k] * C_DIM + c];
        }
        __syncthreads();
    }

    {
        const int bp = 1;
        const int mp = mb + 7;
        float hh[G_DIM], uu[G_DIM];
#pragma unroll
        for (int g2 = 0; g2 < G_DIM; g2++) { hh[g2] = 0.f; uu[g2] = 0.f; }
#pragma unroll
        for (int k = 0; k < KNN; k++) {
            float hk = s.hs[bp][k * 132 + c];
            float cv = cfpre[k];
            float4 ea = *(const float4*)&s.e_s[k * 8];
            float4 eb = *(const float4*)&s.e_s[k * 8 + 4];
            uu[0] = fmaf(cv, ea.x, uu[0]); hh[0] = fmaf(hk, ea.x, hh[0]);
            uu[1] = fmaf(cv, ea.y, uu[1]); hh[1] = fmaf(hk, ea.y, hh[1]);
            uu[2] = fmaf(cv, ea.z, uu[2]); hh[2] = fmaf(hk, ea.z, hh[2]);
            uu[3] = fmaf(cv, ea.w, uu[3]); hh[3] = fmaf(hk, ea.w, hh[3]);
            uu[4] = fmaf(cv, eb.x, uu[4]); hh[4] = fmaf(hk, eb.x, hh[4]);
            uu[5] = fmaf(cv, eb.y, uu[5]); hh[5] = fmaf(hk, eb.y, hh[5]);
            uu[6] = fmaf(cv, eb.z, uu[6]); hh[6] = fmaf(hk, eb.z, hh[6]);
            uu[7] = fmaf(cv, eb.w, uu[7]); hh[7] = fmaf(hk, eb.w, hh[7]);
        }
        float* base = &g_Hs2[(size_t)mp * (G_DIM * 256)];
#pragma unroll
        for (int g2 = 0; g2 < G_DIM; g2++) {
            base[g2 * 256 + c]       = uu[g2];
            base[g2 * 256 + 128 + c] = hh[g2];
        }
        if (t < G_DIM) {
            g_sums[(size_t)mp * G_DIM + t] =
                s.psum[t] + s.psum[8 + t] + s.psum[16 + t] + s.psum[24 + t];
            g_wsr[(size_t)mp * G_DIM + t] =
                s.wpsum[t] + s.wpsum[8 + t] + s.wpsum[16 + t] + s.wpsum[24 + t];
        }
    }
}

// ---------------- K4: grouped epilogue GEMM ----------------------------------
__launch_bounds__(256, 6)
__global__ void k4_out(const float* __restrict__ Wv, const float* __restrict__ Wp2,
                       const float* __restrict__ bv, const float* __restrict__ bp2,
                       float* __restrict__ out) {
    __shared__ float As[16][260];
    __shared__ float BsT[16][260];
    const int m0 = blockIdx.x * 16;
    const int g  = blockIdx.y;
    const int tid = threadIdx.x;

    for (int i = tid; i < 1024; i += 256) {
        int r = i >> 6, j4 = i & 63;
        *(float4*)&As[r][j4 * 4] =
            *(const float4*)&g_Hs2[(size_t)(m0 + r) * (G_DIM * 256) + g * 256 + j4 * 4];
    }
    // weights via float4 (coalesced), transposed store to BsT
    for (int i = tid; i < 1024; i += 256) {
        int j = i >> 2, q = i & 3;
        const float* src = (j < 128) ? &Wv[(size_t)j * C_DIM + g * 16 + q * 4]
                                     : &Wp2[(size_t)(j - 128) * C_DIM + g * 16 + q * 4];
        float4 v = *(const float4*)src;
        BsT[q * 4 + 0][j] = v.x;
        BsT[q * 4 + 1][j] = v.y;
        BsT[q * 4 + 2][j] = v.z;
        BsT[q * 4 + 3][j] = v.w;
    }
    __syncthreads();

    const int r = tid >> 4, cc = tid & 15;
    float a0 = 0.f, a1 = 0.f, a2 = 0.f, a3 = 0.f;
    const float4* ar = (const float4*)&As[r][0];
    const float4* br = (const float4*)&BsT[cc][0];
#pragma unroll
    for (int j = 0; j < 64; j += 4) {
        float4 x0 = ar[j],     y0 = br[j];
        float4 x1 = ar[j + 1], y1 = br[j + 1];
        float4 x2 = ar[j + 2], y2 = br[j + 2];
        float4 x3 = ar[j + 3], y3 = br[j + 3];
        a0 = fmaf(x0.x, y0.x, fmaf(x0.y, y0.y, fmaf(x0.z, y0.z, fmaf(x0.w, y0.w, a0))));
        a1 = fmaf(x1.x, y1.x, fmaf(x1.y, y1.y, fmaf(x1.z, y1.z, fmaf(x1.w, y1.w, a1))));
        a2 = fmaf(x2.x, y2.x, fmaf(x2.y, y2.y, fmaf(x2.z, y2.z, fmaf(x2.w, y2.w, a2))));
        a3 = fmaf(x3.x, y3.x, fmaf(x3.y, y3.y, fmaf(x3.z, y3.z, fmaf(x3.w, y3.w, a3))));
    }
    float acc = (a0 + a1) + (a2 + a3);
    const int m = m0 + r;
    const int c = g * 16 + cc;
    float inv = 1.f / g_sums[(size_t)m * G_DIM + g];
    float wsr = g_wsr[(size_t)m * G_DIM + g];
    out[(size_t)m * C_DIM + c] = (acc + (bv[c] + bp2[c]) * wsr) * inv;
}

// ---------------- launch -----------------------------------------------------
extern "C" void kernel_launch(void* const* d_in, const int* in_sizes, int n_in,
                              void* d_out, int out_size) {
    const float* qf     = (const float*)d_in[0];
    const float* cf     = (const float*)d_in[1];
    const float* qc     = (const float*)d_in[2];
    const float* cc     = (const float*)d_in[3];
    const float* Wq     = (const float*)d_in[4];
    const float* bq     = (const float*)d_in[5];
    const float* gq     = (const float*)d_in[6];
    const float* betaq  = (const float*)d_in[7];
    const float* Wk     = (const float*)d_in[8];
    const float* bk     = (const float*)d_in[9];
    const float* gk     = (const float*)d_in[10];
    const float* betak  = (const float*)d_in[11];
    const float* Wv     = (const float*)d_in[12];
    const float* bv     = (const float*)d_in[13];
    const float* Wp1    = (const float*)d_in[14];
    const float* bp1    = (const float*)d_in[15];
    const float* gp1    = (const float*)d_in[16];
    const float* betap1 = (const float*)d_in[17];
    const float* Wp2    = (const float*)d_in[18];
    const float* bp2    = (const float*)d_in[19];
    const float* Ww1    = (const float*)d_in[20];
    const float* bw1    = (const float*)d_in[21];
    const float* gw1    = (const float*)d_in[22];
    const float* betaw1 = (const float*)d_in[23];
    const float* Ww2    = (const float*)d_in[24];
    const float* bw2    = (const float*)d_in[25];
    const int*   knn    = (const int*)d_in[26];
    float* out = (float*)d_out;

    const int M = in_sizes[0] / C_DIM;
    const int N = in_sizes[1] / C_DIM;
    const int NB = N / 64, MB = M / 64;

    k0_prep<<<1, 128>>>(Wp2, Ww1, bp2);

    cudaFuncSetAttribute(k12_proj, cudaFuncAttributeMaxDynamicSharedMemorySize,
                         SMEM_K12_TOTAL);
    k12_proj<<<NB + MB, 256, SMEM_K12_TOTAL>>>(cf, qf, Wk, bk, gk, betak,
                                               Wq, bq, gq, betaq, Ww1, NB);

    k3_attn<<<M / 8, 128>>>(qc, cc, knn, cf, Wp1, bp1, gp1, betap1,
                            bw1, gw1, betaw1, Ww2, bw2);
    dim3 g4(M / 16, G_DIM);
    k4_out<<<g4, 256>>>(Wv, Wp2, bv, bp2, out);
}

// round 7
// speedup vs baseline: 1.6025x; 1.0546x over previous
#include <cuda_runtime.h>
#include <cuda_bf16.h>
#include <cstdint>

#define C_DIM 128
#define G_DIM 8
#define KNN   16
#define EPS_BN 1e-5f
#define N_CTX_MAX 131072
#define M_Q_MAX   16384

// ---------------- scratch (static device memory; no runtime allocation) -----
__device__ float g_kw  [(size_t)N_CTX_MAX * G_DIM];      // relu(bn(cf@Wk))@Ww1
__device__ float g_qw  [(size_t)M_Q_MAX   * G_DIM];      // relu(bn(qf@Wq))@Ww1
__device__ float g_WpwT[G_DIM * C_DIM];                  // [g][c2] = (Wp2@Ww1)[c2][g]
__device__ float g_pwb [G_DIM];                          // bp2 @ Ww1
__device__ float g_Hs2 [(size_t)M_Q_MAX * G_DIM * 256];  // [m][g][0:128]=U, [128:256]=H
__device__ float g_sums[(size_t)M_Q_MAX * G_DIM];        // raw softmax denominators
__device__ float g_wsr [(size_t)M_Q_MAX * G_DIM];        // raw masked weight sums

typedef unsigned long long ull;

// bf16 HMMA m16n8k16 (sm_80+ PTX; no arch-suffix features)
__device__ __forceinline__ void mma_bf16(float* d, uint32_t a0, uint32_t a1,
                                         uint32_t a2, uint32_t a3,
                                         uint32_t b0, uint32_t b1) {
    asm volatile(
        "mma.sync.aligned.m16n8k16.row.col.f32.bf16.bf16.f32 "
        "{%0,%1,%2,%3}, {%4,%5,%6,%7}, {%8,%9}, {%0,%1,%2,%3};"
        : "+f"(d[0]), "+f"(d[1]), "+f"(d[2]), "+f"(d[3])
        : "r"(a0), "r"(a1), "r"(a2), "r"(a3), "r"(b0), "r"(b1));
}

// ---------------- K0: tiny prep (coalesced, smem-staged) ---------------------
#define SMEM_K0_TOTAL ((128 * 132 + 1024) * 4)
__global__ void k0_prep(const float* __restrict__ Wp2,
                        const float* __restrict__ Ww1,
                        const float* __restrict__ bp2) {
    extern __shared__ float sp[];
    float* WpS = sp;                  // [128][132]
    float* W1s = sp + 128 * 132;      // [128*8]
    const int tid = threadIdx.x;      // 256
    for (int i = tid; i < 4096; i += 256) {
        int r = i >> 5, q = i & 31;
        *(float4*)&WpS[r * 132 + q * 4] = *(const float4*)&Wp2[r * C_DIM + q * 4];
    }
    if (tid < 256) *(float4*)&W1s[tid * 4] = *(const float4*)&Ww1[tid * 4];
    __syncthreads();

    if (tid < 128) {
        const int c = tid;
        float acc[G_DIM];
#pragma unroll
        for (int g = 0; g < G_DIM; g++) acc[g] = 0.f;
        const float* wr = &WpS[c * 132];
#pragma unroll 8
        for (int c2 = 0; c2 < C_DIM; c2++) {
            float a = wr[c2];
#pragma unroll
            for (int g = 0; g < G_DIM; g++) acc[g] = fmaf(a, W1s[c2 * G_DIM + g], acc[g]);
        }
#pragma unroll
        for (int g = 0; g < G_DIM; g++) g_WpwT[g * C_DIM + c] = acc[g];
    } else if (tid < 128 + G_DIM) {
        const int g = tid - 128;
        float s = 0.f;
        for (int c2 = 0; c2 < C_DIM; c2++) s = fmaf(bp2[c2], W1s[c2 * G_DIM + g], s);
        g_pwb[g] = s;
    }
}

// ---------------- K12: fused context+query pass (bf16-split HMMA, occ 2) -----
#define K1_ROWB 272      // bytes per row (136 bf16), fragment-packed
__device__ __forceinline__ uint32_t k1_off(int row, int k) {  // k even
    int p = k >> 1;
    return (uint32_t)row * K1_ROWB + (uint32_t)(k >> 4) * 32
         + (uint32_t)(p & 3) * 8 + (uint32_t)((p >> 2) & 1) * 4;
}

#define SM_AH   0          // 17408
#define SM_AL   17408      // 17408
#define SM_BH   34816      // 34816
#define SM_BL   69632      // 34816
#define SM_PAR  104448     // float4[128]: (b, g*rs, beta, 0)
#define SM_W1   106496     // float[128*8] Ww1
#define SM_KS   0          // float[64][130] k tile (reuses A region post-MMA)
#define SMEM_K12_TOTAL 110592

__launch_bounds__(256, 2)
__global__ void k12_proj(const float* __restrict__ cf, const float* __restrict__ qf,
                         const float* __restrict__ Wk, const float* __restrict__ bk,
                         const float* __restrict__ gk, const float* __restrict__ betak,
                         const float* __restrict__ Wq, const float* __restrict__ bq,
                         const float* __restrict__ gq, const float* __restrict__ betaq,
                         const float* __restrict__ Ww1, int NB) {
    extern __shared__ char smem[];
    const int tid = threadIdx.x;
    const int wid = tid >> 5;
    const int lane = tid & 31;
    const int grp = lane >> 2, tig = lane & 3;

    const bool ctx = (int)blockIdx.x < NB;
    const int bm0 = (ctx ? (int)blockIdx.x : (int)blockIdx.x - NB) * 64;
    const float* feat = ctx ? cf : qf;
    const float* W    = ctx ? Wk : Wq;
    const float* bb   = ctx ? bk : bq;
    const float* gg   = ctx ? gk : gq;
    const float* be   = ctx ? betak : betaq;
    float* dst        = ctx ? g_kw : g_qw;

    {
        const int row = tid >> 2, q = tid & 3;
        const float4* src = (const float4*)&feat[(size_t)(bm0 + row) * C_DIM + q * 32];
#pragma unroll
        for (int j = 0; j < 8; j++) {
            float4 x = src[j];
            int c0 = q * 32 + j * 4;
#pragma unroll
            for (int p = 0; p < 2; p++) {
                float a0 = (&x.x)[2 * p], a1 = (&x.x)[2 * p + 1];
                __nv_bfloat16 h0 = __float2bfloat16(a0), h1 = __float2bfloat16(a1);
                __nv_bfloat16 l0 = __float2bfloat16(a0 - __bfloat162float(h0));
                __nv_bfloat16 l1 = __float2bfloat16(a1 - __bfloat162float(h1));
                uint32_t off = k1_off(row, c0 + 2 * p);
                *(__nv_bfloat162*)(smem + SM_AH + off) = __nv_bfloat162(h0, h1);
                *(__nv_bfloat162*)(smem + SM_AL + off) = __nv_bfloat162(l0, l1);
            }
        }
    }
    for (int i = tid; i < 8192; i += 256) {
        int n = i & 127, p = i >> 7, k = 2 * p;
        float v0 = W[(size_t)k * C_DIM + n];
        float v1 = W[(size_t)(k + 1) * C_DIM + n];
        __nv_bfloat16 h0 = __float2bfloat16(v0), h1 = __float2bfloat16(v1);
        __nv_bfloat16 l0 = __float2bfloat16(v0 - __bfloat162float(h0));
        __nv_bfloat16 l1 = __float2bfloat16(v1 - __bfloat162float(h1));
        uint32_t off = k1_off(n, k);
        *(__nv_bfloat162*)(smem + SM_BH + off) = __nv_bfloat162(h0, h1);
        *(__nv_bfloat162*)(smem + SM_BL + off) = __nv_bfloat162(l0, l1);
    }
    const float rs = rsqrtf(1.f + EPS_BN);
    if (tid < C_DIM) {
        float4 pp; pp.x = bb[tid]; pp.y = gg[tid] * rs; pp.z = be[tid]; pp.w = 0.f;
        *(float4*)(smem + SM_PAR + tid * 16) = pp;
    }
    *(float4*)(smem + SM_W1 + tid * 16) = *(const float4*)&Ww1[tid * 4];
    __syncthreads();

    const int rbase = (wid & 3) * 16;
    const int cbase = (wid >> 2) * 64;
    float acc[8][4];
#pragma unroll
    for (int nt = 0; nt < 8; nt++)
#pragma unroll
        for (int q = 0; q < 4; q++) acc[nt][q] = 0.f;

    const uint32_t aoff_lo = k1_off(rbase + grp, 0) + tig * 8;
    const uint32_t aoff_hi = k1_off(rbase + grp + 8, 0) + tig * 8;

#pragma unroll
    for (int ks = 0; ks < 8; ks++) {
        const uint32_t kb = ks * 32;
        ull alo_h = *(const ull*)(smem + SM_AH + aoff_lo + kb);
        ull ahi_h = *(const ull*)(smem + SM_AH + aoff_hi + kb);
        ull alo_l = *(const ull*)(smem + SM_AL + aoff_lo + kb);
        ull ahi_l = *(const ull*)(smem + SM_AL + aoff_hi + kb);
        uint32_t a0h = (uint32_t)alo_h, a2h = (uint32_t)(alo_h >> 32);
        uint32_t a1h = (uint32_t)ahi_h, a3h = (uint32_t)(ahi_h >> 32);
        uint32_t a0l = (uint32_t)alo_l, a2l = (uint32_t)(alo_l >> 32);
        uint32_t a1l = (uint32_t)ahi_l, a3l = (uint32_t)(ahi_l >> 32);
#pragma unroll
        for (int nt = 0; nt < 8; nt++) {
            uint32_t boff = (uint32_t)(cbase + nt * 8 + grp) * K1_ROWB + kb + tig * 8;
            ull bh = *(const ull*)(smem + SM_BH + boff);
            ull bl = *(const ull*)(smem + SM_BL + boff);
            uint32_t b0h = (uint32_t)bh, b1h = (uint32_t)(bh >> 32);
            uint32_t b0l = (uint32_t)bl, b1l = (uint32_t)(bl >> 32);
            mma_bf16(acc[nt], a0h, a1h, a2h, a3h, b0h, b1h);
            mma_bf16(acc[nt], a0h, a1h, a2h, a3h, b0l, b1l);
            mma_bf16(acc[nt], a0l, a1l, a2l, a3l, b0h, b1h);
        }
    }
    __syncthreads();

    {
        float* ks_s = (float*)(smem + SM_KS);
        const float4* par = (const float4*)(smem + SM_PAR);
        const int r0 = rbase + grp, r1 = r0 + 8;
#pragma unroll
        for (int nt = 0; nt < 8; nt++) {
            int col = cbase + nt * 8 + tig * 2;
            float4 p0 = par[col], p1 = par[col + 1];
            float2 lo, hi;
            lo.x = fmaxf(fmaf(acc[nt][0] + p0.x, p0.y, p0.z), 0.f);
            lo.y = fmaxf(fmaf(acc[nt][1] + p1.x, p1.y, p1.z), 0.f);
            hi.x = fmaxf(fmaf(acc[nt][2] + p0.x, p0.y, p0.z), 0.f);
            hi.y = fmaxf(fmaf(acc[nt][3] + p1.x, p1.y, p1.z), 0.f);
            *(float2*)&ks_s[r0 * 130 + col] = lo;
            *(float2*)&ks_s[r1 * 130 + col] = hi;
        }
    }
    __syncthreads();

    {
        const float* ks_s = (const float*)(smem + SM_KS);
        const float* W1   = (const float*)(smem + SM_W1);
#pragma unroll
        for (int s2 = 0; s2 < 2; s2++) {
            int task = tid + s2 * 256;
            int row = task >> 3, g = task & 7;
            const float* kr = &ks_s[row * 130];
            float a0 = 0.f, a1 = 0.f, a2 = 0.f, a3 = 0.f;
#pragma unroll 8
            for (int c = 0; c < C_DIM; c += 4) {
                a0 = fmaf(kr[c],     W1[(c)     * G_DIM + g], a0);
                a1 = fmaf(kr[c + 1], W1[(c + 1) * G_DIM + g], a1);
                a2 = fmaf(kr[c + 2], W1[(c + 2) * G_DIM + g], a2);
                a3 = fmaf(kr[c + 3], W1[(c + 3) * G_DIM + g], a3);
            }
            dst[(size_t)(bm0 + row) * G_DIM + g] = (a0 + a1) + (a2 + a3);
        }
    }
}

// ---------------- K3: attention weights + U/H accumulation -------------------
struct S3 {
    float WpwT[G_DIM * 132];
    float ww2s[G_DIM * G_DIM];
    float hs[2][KNN * 132];
    float e_s[KNN * G_DIM];
    float psum[4 * G_DIM];
    float wpsum[4 * G_DIM];
    float pos[2][KNN * 4];
    float kwg[2][KNN * G_DIM];
    float qw[2][G_DIM];
    float msk[2][KNN];
    int   idx[2][KNN];
};

__device__ __forceinline__ void gatherK(S3* s, const int* __restrict__ knn,
                                        const float* __restrict__ qcoord,
                                        const float* __restrict__ ccoord,
                                        int m, int p, int k) {
    int id = knn[(size_t)m * KNN + k];
    float mk = id >= 0 ? 1.f : 0.f;
    int id0 = id >= 0 ? id : 0;
    s->idx[p][k] = id0;
    s->msk[p][k] = mk;
    float qx = qcoord[m * 3 + 0], qy = qcoord[m * 3 + 1], qz = qcoord[m * 3 + 2];
    s->pos[p][k * 4 + 0] = (ccoord[(size_t)id0 * 3 + 0] - qx) * mk;
    s->pos[p][k * 4 + 1] = (ccoord[(size_t)id0 * 3 + 1] - qy) * mk;
    s->pos[p][k * 4 + 2] = (ccoord[(size_t)id0 * 3 + 2] - qz) * mk;
    const float4* kwp = (const float4*)&g_kw[(size_t)id0 * G_DIM];
    float4 a = kwp[0], b = kwp[1];
    float* kd = &s->kwg[p][k * 8];
    kd[0] = a.x * mk; kd[1] = a.y * mk; kd[2] = a.z * mk; kd[3] = a.w * mk;
    kd[4] = b.x * mk; kd[5] = b.y * mk; kd[6] = b.z * mk; kd[7] = b.w * mk;
}

__launch_bounds__(128, 4)
__global__ void k3_attn(const float* __restrict__ qcoord, const float* __restrict__ ccoord,
                        const int*   __restrict__ knn, const float* __restrict__ cf,
                        const float* __restrict__ Wp1, const float* __restrict__ bp1,
                        const float* __restrict__ gp1, const float* __restrict__ betap1,
                        const float* __restrict__ bw1, const float* __restrict__ gw1,
                        const float* __restrict__ betaw1,
                        const float* __restrict__ Ww2, const float* __restrict__ bw2) {
    __shared__ S3 s;
    const int t = threadIdx.x;
    const int c = t, gc = t >> 4;
    const int kB = t >> 3, gB = t & 7;
    const int w4 = t >> 5;
    const int lane = t & 31;
    const int lbase = lane & ~7;

    for (int i = t; i < G_DIM * C_DIM; i += 128) {
        int r = i >> 7, cc2 = i & 127;
        s.WpwT[r * 132 + cc2] = g_WpwT[i];
    }
    if (t < G_DIM * G_DIM) s.ww2s[t] = Ww2[t];

    const float rs  = rsqrtf(1.f + EPS_BN);
    const float sp1 = gp1[c] * rs;
    const float wf0 = Wp1[c] * sp1, wf1 = Wp1[C_DIM + c] * sp1, wf2 = Wp1[2 * C_DIM + c] * sp1;
    const float hb  = fmaf(bp1[c], sp1, betap1[c]);
    const float sw1  = gw1[gB] * rs;
    const float wb1f = fmaf(bw1[gB], sw1, betaw1[gB]);
    const float pwbB = g_pwb[gB];
    const float bw2B = bw2[gB];

    const int mb = blockIdx.x * 8;
    float cfpre[KNN];

    if (t < KNN)   gatherK(&s, knn, qcoord, ccoord, mb, 0, t);
    if (t < G_DIM) s.qw[0][t] = g_qw[(size_t)mb * G_DIM + t];
    __syncthreads();

    for (int qi = 0; qi < 8; qi++) {
        const int b = qi & 1;
        const int m = mb + qi;

        {
#pragma unroll
            for (int k = 0; k < KNN; k++) {
                const float* pp = &s.pos[b][k * 4];
                s.hs[b][k * 132 + c] =
                    fmaxf(fmaf(wf0, pp[0], fmaf(wf1, pp[1], fmaf(wf2, pp[2], hb))), 0.f);
            }
            if (qi < 7) {
                if (t < KNN)   gatherK(&s, knn, qcoord, ccoord, m + 1, b ^ 1, t);
                if (t < G_DIM) s.qw[b ^ 1][t] = g_qw[(size_t)(m + 1) * G_DIM + t];
            }
            if (qi > 0) {
                const int bp = b ^ 1;
                const int mp = m - 1;
                float hh[G_DIM], uu[G_DIM];
#pragma unroll
                for (int g2 = 0; g2 < G_DIM; g2++) { hh[g2] = 0.f; uu[g2] = 0.f; }
#pragma unroll
                for (int k = 0; k < KNN; k++) {
                    float hk = s.hs[bp][k * 132 + c];
                    float cv = cfpre[k];
                    float4 ea = *(const float4*)&s.e_s[k * 8];
                    float4 eb = *(const float4*)&s.e_s[k * 8 + 4];
                    uu[0] = fmaf(cv, ea.x, uu[0]); hh[0] = fmaf(hk, ea.x, hh[0]);
                    uu[1] = fmaf(cv, ea.y, uu[1]); hh[1] = fmaf(hk, ea.y, hh[1]);
                    uu[2] = fmaf(cv, ea.z, uu[2]); hh[2] = fmaf(hk, ea.z, hh[2]);
                    uu[3] = fmaf(cv, ea.w, uu[3]); hh[3] = fmaf(hk, ea.w, hh[3]);
                    uu[4] = fmaf(cv, eb.x, uu[4]); hh[4] = fmaf(hk, eb.x, hh[4]);
                    uu[5] = fmaf(cv, eb.y, uu[5]); hh[5] = fmaf(hk, eb.y, hh[5]);
                    uu[6] = fmaf(cv, eb.z, uu[6]); hh[6] = fmaf(hk, eb.z, hh[6]);
                    uu[7] = fmaf(cv, eb.w, uu[7]); hh[7] = fmaf(hk, eb.w, hh[7]);
                }
                float* base = &g_Hs2[(size_t)mp * (G_DIM * 256)];
#pragma unroll
                for (int g2 = 0; g2 < G_DIM; g2++) {
                    base[g2 * 256 + c]       = uu[g2];
                    base[g2 * 256 + 128 + c] = hh[g2];
                }
                if (t < G_DIM) {
                    g_sums[(size_t)mp * G_DIM + t] =
                        s.psum[t] + s.psum[8 + t] + s.psum[16 + t] + s.psum[24 + t];
                    g_wsr[(size_t)mp * G_DIM + t] =
                        s.wpsum[t] + s.wpsum[8 + t] + s.wpsum[16 + t] + s.wpsum[24 + t];
                }
            }
        }
        __syncthreads();

        {
            float a0 = s.kwg[b][t] - s.qw[b][gB] + pwbB;
            float a1 = 0.f, a2 = 0.f, a3 = 0.f;
            const float4* hr = (const float4*)&s.hs[b][kB * 132];
            const float4* wr = (const float4*)&s.WpwT[gB * 132];
#pragma unroll
            for (int j = 0; j < 32; j += 4) {
                float4 h0 = hr[j],     w0 = wr[j];
                float4 h1 = hr[j + 1], w1 = wr[j + 1];
                float4 h2 = hr[j + 2], w2 = wr[j + 2];
                float4 h3 = hr[j + 3], w3 = wr[j + 3];
                a0 = fmaf(h0.x, w0.x, fmaf(h0.y, w0.y, fmaf(h0.z, w0.z, fmaf(h0.w, w0.w, a0))));
                a1 = fmaf(h1.x, w1.x, fmaf(h1.y, w1.y, fmaf(h1.z, w1.z, fmaf(h1.w, w1.w, a1))));
                a2 = fmaf(h2.x, w2.x, fmaf(h2.y, w2.y, fmaf(h2.z, w2.z, fmaf(h2.w, w2.w, a2))));
                a3 = fmaf(h3.x, w3.x, fmaf(h3.y, w3.y, fmaf(h3.z, w3.z, fmaf(h3.w, w3.w, a3))));
            }
            float ts = fmaxf(fmaf((a0 + a1) + (a2 + a3), sw1, wb1f), 0.f);

            float lg = bw2B;
#pragma unroll
            for (int g2 = 0; g2 < G_DIM; g2++)
                lg = fmaf(__shfl_sync(0xffffffffu, ts, lbase + g2), s.ww2s[g2 * G_DIM + gB], lg);

            float e  = __expf(lg);
            float mk = s.msk[b][kB];
            float em = e * mk;
            s.e_s[t] = em;
            float es = e;
            es += __shfl_xor_sync(0xffffffffu, es, 8);
            es += __shfl_xor_sync(0xffffffffu, es, 16);
            float esm = em;
            esm += __shfl_xor_sync(0xffffffffu, esm, 8);
            esm += __shfl_xor_sync(0xffffffffu, esm, 16);
            if (lane < 8) { s.psum[w4 * 8 + gB] = es; s.wpsum[w4 * 8 + gB] = esm; }

            const int* ix = s.idx[b];
#pragma unroll
            for (int k = 0; k < KNN; k++) cfpre[k] = cf[(size_t)ix[k] * C_DIM + c];
        }
        __syncthreads();
    }

    {
        const int bp = 1;
        const int mp = mb + 7;
        float hh[G_DIM], uu[G_DIM];
#pragma unroll
        for (int g2 = 0; g2 < G_DIM; g2++) { hh[g2] = 0.f; uu[g2] = 0.f; }
#pragma unroll
        for (int k = 0; k < KNN; k++) {
            float hk = s.hs[bp][k * 132 + c];
            float cv = cfpre[k];
            float4 ea = *(const float4*)&s.e_s[k * 8];
            float4 eb = *(const float4*)&s.e_s[k * 8 + 4];
            uu[0] = fmaf(cv, ea.x, uu[0]); hh[0] = fmaf(hk, ea.x, hh[0]);
            uu[1] = fmaf(cv, ea.y, uu[1]); hh[1] = fmaf(hk, ea.y, hh[1]);
            uu[2] = fmaf(cv, ea.z, uu[2]); hh[2] = fmaf(hk, ea.z, hh[2]);
            uu[3] = fmaf(cv, ea.w, uu[3]); hh[3] = fmaf(hk, ea.w, hh[3]);
            uu[4] = fmaf(cv, eb.x, uu[4]); hh[4] = fmaf(hk, eb.x, hh[4]);
            uu[5] = fmaf(cv, eb.y, uu[5]); hh[5] = fmaf(hk, eb.y, hh[5]);
            uu[6] = fmaf(cv, eb.z, uu[6]); hh[6] = fmaf(hk, eb.z, hh[6]);
            uu[7] = fmaf(cv, eb.w, uu[7]); hh[7] = fmaf(hk, eb.w, hh[7]);
        }
        float* base = &g_Hs2[(size_t)mp * (G_DIM * 256)];
#pragma unroll
        for (int g2 = 0; g2 < G_DIM; g2++) {
            base[g2 * 256 + c]       = uu[g2];
            base[g2 * 256 + 128 + c] = hh[g2];
        }
        if (t < G_DIM) {
            g_sums[(size_t)mp * G_DIM + t] =
                s.psum[t] + s.psum[8 + t] + s.psum[16 + t] + s.psum[24 + t];
            g_wsr[(size_t)mp * G_DIM + t] =
                s.wpsum[t] + s.wpsum[8 + t] + s.wpsum[16 + t] + s.wpsum[24 + t];
        }
    }
}

// ---------------- K4: grouped epilogue GEMM (register-tiled) ------------------
// Block: 64 m-rows x 16 cc for one g. Thread: 4 m x 1 cc.
#define SMEM_K4_TOTAL ((64 * 260 + 16 * 260) * 4)   // 83200 B
__launch_bounds__(256, 2)
__global__ void k4_out(const float* __restrict__ Wv, const float* __restrict__ Wp2,
                       const float* __restrict__ bv, const float* __restrict__ bp2,
                       float* __restrict__ out) {
    extern __shared__ float s4[];
    float* As  = s4;                 // [64][260]
    float* BsT = s4 + 64 * 260;      // [16][260]
    const int m0 = blockIdx.x * 64;
    const int g  = blockIdx.y;
    const int tid = threadIdx.x;

    for (int i = tid; i < 4096; i += 256) {
        int r = i >> 6, j4 = i & 63;
        *(float4*)&As[r * 260 + j4 * 4] =
            *(const float4*)&g_Hs2[(size_t)(m0 + r) * (G_DIM * 256) + g * 256 + j4 * 4];
    }
    for (int i = tid; i < 1024; i += 256) {
        int j = i >> 2, q = i & 3;
        const float* src = (j < 128) ? &Wv[(size_t)j * C_DIM + g * 16 + q * 4]
                                     : &Wp2[(size_t)(j - 128) * C_DIM + g * 16 + q * 4];
        float4 v = *(const float4*)src;
        BsT[(q * 4 + 0) * 260 + j] = v.x;
        BsT[(q * 4 + 1) * 260 + j] = v.y;
        BsT[(q * 4 + 2) * 260 + j] = v.z;
        BsT[(q * 4 + 3) * 260 + j] = v.w;
    }
    __syncthreads();

    const int tm = tid >> 4, cc = tid & 15;
    const float4* br  = (const float4*)&BsT[cc * 260];
    const float4* ar0 = (const float4*)&As[(tm)      * 260];
    const float4* ar1 = (const float4*)&As[(tm + 16) * 260];
    const float4* ar2 = (const float4*)&As[(tm + 32) * 260];
    const float4* ar3 = (const float4*)&As[(tm + 48) * 260];
    float a0 = 0.f, a1 = 0.f, a2 = 0.f, a3 = 0.f;
#pragma unroll
    for (int j = 0; j < 64; j++) {
        float4 b  = br[j];
        float4 x0 = ar0[j], x1 = ar1[j], x2 = ar2[j], x3 = ar3[j];
        a0 = fmaf(x0.x, b.x, fmaf(x0.y, b.y, fmaf(x0.z, b.z, fmaf(x0.w, b.w, a0))));
        a1 = fmaf(x1.x, b.x, fmaf(x1.y, b.y, fmaf(x1.z, b.z, fmaf(x1.w, b.w, a1))));
        a2 = fmaf(x2.x, b.x, fmaf(x2.y, b.y, fmaf(x2.z, b.z, fmaf(x2.w, b.w, a2))));
        a3 = fmaf(x3.x, b.x, fmaf(x3.y, b.y, fmaf(x3.z, b.z, fmaf(x3.w, b.w, a3))));
    }

    const int c = g * 16 + cc;
    const float bb = bv[c] + bp2[c];
    float accs[4] = {a0, a1, a2, a3};
#pragma unroll
    for (int u = 0; u < 4; u++) {
        const int m = m0 + tm + 16 * u;
        float inv = 1.f / g_sums[(size_t)m * G_DIM + g];
        float wsr = g_wsr[(size_t)m * G_DIM + g];
        out[(size_t)m * C_DIM + c] = (accs[u] + bb * wsr) * inv;
    }
}

// ---------------- launch -----------------------------------------------------
extern "C" void kernel_launch(void* const* d_in, const int* in_sizes, int n_in,
                              void* d_out, int out_size) {
    const float* qf     = (const float*)d_in[0];
    const float* cf     = (const float*)d_in[1];
    const float* qc     = (const float*)d_in[2];
    const float* cc     = (const float*)d_in[3];
    const float* Wq     = (const float*)d_in[4];
    const float* bq     = (const float*)d_in[5];
    const float* gq     = (const float*)d_in[6];
    const float* betaq  = (const float*)d_in[7];
    const float* Wk     = (const float*)d_in[8];
    const float* bk     = (const float*)d_in[9];
    const float* gk     = (const float*)d_in[10];
    const float* betak  = (const float*)d_in[11];
    const float* Wv     = (const float*)d_in[12];
    const float* bv     = (const float*)d_in[13];
    const float* Wp1    = (const float*)d_in[14];
    const float* bp1    = (const float*)d_in[15];
    const float* gp1    = (const float*)d_in[16];
    const float* betap1 = (const float*)d_in[17];
    const float* Wp2    = (const float*)d_in[18];
    const float* bp2    = (const float*)d_in[19];
    const float* Ww1    = (const float*)d_in[20];
    const float* bw1    = (const float*)d_in[21];
    const float* gw1    = (const float*)d_in[22];
    const float* betaw1 = (const float*)d_in[23];
    const float* Ww2    = (const float*)d_in[24];
    const float* bw2    = (const float*)d_in[25];
    const int*   knn    = (const int*)d_in[26];
    float* out = (float*)d_out;

    const int M = in_sizes[0] / C_DIM;
    const int N = in_sizes[1] / C_DIM;
    const int NB = N / 64, MB = M / 64;

    cudaFuncSetAttribute(k0_prep, cudaFuncAttributeMaxDynamicSharedMemorySize,
                         SMEM_K0_TOTAL);
    k0_prep<<<1, 256, SMEM_K0_TOTAL>>>(Wp2, Ww1, bp2);

    cudaFuncSetAttribute(k12_proj, cudaFuncAttributeMaxDynamicSharedMemorySize,
                         SMEM_K12_TOTAL);
    k12_proj<<<NB + MB, 256, SMEM_K12_TOTAL>>>(cf, qf, Wk, bk, gk, betak,
                                               Wq, bq, gq, betaq, Ww1, NB);

    k3_attn<<<M / 8, 128>>>(qc, cc, knn, cf, Wp1, bp1, gp1, betap1,
                            bw1, gw1, betaw1, Ww2, bw2);

    cudaFuncSetAttribute(k4_out, cudaFuncAttributeMaxDynamicSharedMemorySize,
                         SMEM_K4_TOTAL);
    dim3 g4(M / 64, G_DIM);
    k4_out<<<g4, 256, SMEM_K4_TOTAL>>>(Wv, Wp2, bv, bp2, out);
}

// round 9
// speedup vs baseline: 2.1004x; 1.3108x over previous
#include <cuda_runtime.h>
#include <cuda_bf16.h>
#include <cuda_fp16.h>
#include <cstdint>

#define C_DIM 128
#define G_DIM 8
#define KNN   16
#define EPS_BN 1e-5f
#define N_CTX_MAX 131072
#define M_Q_MAX   16384

// ---------------- scratch (static device memory; no runtime allocation) -----
__device__ float   g_kw  [(size_t)N_CTX_MAX * G_DIM];
__device__ float   g_qw  [(size_t)M_Q_MAX   * G_DIM];
__device__ float   g_WpwT[G_DIM * C_DIM];
__device__ float   g_pwb [G_DIM];
__device__ __align__(16) __half2 g_Hs2h[(size_t)M_Q_MAX * G_DIM * 128];  // (U,H), 64 MB
__device__ float   g_sums[(size_t)M_Q_MAX * G_DIM];
__device__ float   g_wsr [(size_t)M_Q_MAX * G_DIM];

typedef unsigned long long ull;

// bf16 HMMA m16n8k16
__device__ __forceinline__ void mma_bf16(float* d, uint32_t a0, uint32_t a1,
                                         uint32_t a2, uint32_t a3,
                                         uint32_t b0, uint32_t b1) {
    asm volatile(
        "mma.sync.aligned.m16n8k16.row.col.f32.bf16.bf16.f32 "
        "{%0,%1,%2,%3}, {%4,%5,%6,%7}, {%8,%9}, {%0,%1,%2,%3};"
        : "+f"(d[0]), "+f"(d[1]), "+f"(d[2]), "+f"(d[3])
        : "r"(a0), "r"(a1), "r"(a2), "r"(a3), "r"(b0), "r"(b1));
}
// fp16 HMMA m16n8k16, fp32 accum
__device__ __forceinline__ void mma_f16(float* d, uint32_t a0, uint32_t a1,
                                        uint32_t a2, uint32_t a3,
                                        uint32_t b0, uint32_t b1) {
    asm volatile(
        "mma.sync.aligned.m16n8k16.row.col.f32.f16.f16.f32 "
        "{%0,%1,%2,%3}, {%4,%5,%6,%7}, {%8,%9}, {%0,%1,%2,%3};"
        : "+f"(d[0]), "+f"(d[1]), "+f"(d[2]), "+f"(d[3])
        : "r"(a0), "r"(a1), "r"(a2), "r"(a3), "r"(b0), "r"(b1));
}

// ---------------- K0: tiny prep (coalesced, smem-staged) ---------------------
#define SMEM_K0_TOTAL ((128 * 132 + 1024) * 4)
__global__ void k0_prep(const float* __restrict__ Wp2,
                        const float* __restrict__ Ww1,
                        const float* __restrict__ bp2) {
    extern __shared__ float sp[];
    float* WpS = sp;
    float* W1s = sp + 128 * 132;
    const int tid = threadIdx.x;
    for (int i = tid; i < 4096; i += 256) {
        int r = i >> 5, q = i & 31;
        *(float4*)&WpS[r * 132 + q * 4] = *(const float4*)&Wp2[r * C_DIM + q * 4];
    }
    if (tid < 256) *(float4*)&W1s[tid * 4] = *(const float4*)&Ww1[tid * 4];
    __syncthreads();

    if (tid < 128) {
        const int c = tid;
        float acc[G_DIM];
#pragma unroll
        for (int g = 0; g < G_DIM; g++) acc[g] = 0.f;
        const float* wr = &WpS[c * 132];
#pragma unroll 8
        for (int c2 = 0; c2 < C_DIM; c2++) {
            float a = wr[c2];
#pragma unroll
            for (int g = 0; g < G_DIM; g++) acc[g] = fmaf(a, W1s[c2 * G_DIM + g], acc[g]);
        }
#pragma unroll
        for (int g = 0; g < G_DIM; g++) g_WpwT[g * C_DIM + c] = acc[g];
    } else if (tid < 128 + G_DIM) {
        const int g = tid - 128;
        float s = 0.f;
        for (int c2 = 0; c2 < C_DIM; c2++) s = fmaf(bp2[c2], W1s[c2 * G_DIM + g], s);
        g_pwb[g] = s;
    }
}

// ---------------- K12: fused context+query pass (bf16-split HMMA, occ 2) -----
#define K1_ROWB 272
__device__ __forceinline__ uint32_t k1_off(int row, int k) {
    int p = k >> 1;
    return (uint32_t)row * K1_ROWB + (uint32_t)(k >> 4) * 32
         + (uint32_t)(p & 3) * 8 + (uint32_t)((p >> 2) & 1) * 4;
}

#define SM_AH   0
#define SM_AL   17408
#define SM_BH   34816
#define SM_BL   69632
#define SM_PAR  104448
#define SM_W1   106496
#define SM_KS   0
#define SMEM_K12_TOTAL 110592

__launch_bounds__(256, 2)
__global__ void k12_proj(const float* __restrict__ cf, const float* __restrict__ qf,
                         const float* __restrict__ Wk, const float* __restrict__ bk,
                         const float* __restrict__ gk, const float* __restrict__ betak,
                         const float* __restrict__ Wq, const float* __restrict__ bq,
                         const float* __restrict__ gq, const float* __restrict__ betaq,
                         const float* __restrict__ Ww1, int NB) {
    extern __shared__ char smem[];
    const int tid = threadIdx.x;
    const int wid = tid >> 5;
    const int lane = tid & 31;
    const int grp = lane >> 2, tig = lane & 3;

    const bool ctx = (int)blockIdx.x < NB;
    const int bm0 = (ctx ? (int)blockIdx.x : (int)blockIdx.x - NB) * 64;
    const float* feat = ctx ? cf : qf;
    const float* W    = ctx ? Wk : Wq;
    const float* bb   = ctx ? bk : bq;
    const float* gg   = ctx ? gk : gq;
    const float* be   = ctx ? betak : betaq;
    float* dst        = ctx ? g_kw : g_qw;

    {
        const int row = tid >> 2, q = tid & 3;
        const float4* src = (const float4*)&feat[(size_t)(bm0 + row) * C_DIM + q * 32];
#pragma unroll
        for (int j = 0; j < 8; j++) {
            float4 x = src[j];
            int c0 = q * 32 + j * 4;
#pragma unroll
            for (int p = 0; p < 2; p++) {
                float a0 = (&x.x)[2 * p], a1 = (&x.x)[2 * p + 1];
                __nv_bfloat16 h0 = __float2bfloat16(a0), h1 = __float2bfloat16(a1);
                __nv_bfloat16 l0 = __float2bfloat16(a0 - __bfloat162float(h0));
                __nv_bfloat16 l1 = __float2bfloat16(a1 - __bfloat162float(h1));
                uint32_t off = k1_off(row, c0 + 2 * p);
                *(__nv_bfloat162*)(smem + SM_AH + off) = __nv_bfloat162(h0, h1);
                *(__nv_bfloat162*)(smem + SM_AL + off) = __nv_bfloat162(l0, l1);
            }
        }
    }
    for (int i = tid; i < 8192; i += 256) {
        int n = i & 127, p = i >> 7, k = 2 * p;
        float v0 = W[(size_t)k * C_DIM + n];
        float v1 = W[(size_t)(k + 1) * C_DIM + n];
        __nv_bfloat16 h0 = __float2bfloat16(v0), h1 = __float2bfloat16(v1);
        __nv_bfloat16 l0 = __float2bfloat16(v0 - __bfloat162float(h0));
        __nv_bfloat16 l1 = __float2bfloat16(v1 - __bfloat162float(h1));
        uint32_t off = k1_off(n, k);
        *(__nv_bfloat162*)(smem + SM_BH + off) = __nv_bfloat162(h0, h1);
        *(__nv_bfloat162*)(smem + SM_BL + off) = __nv_bfloat162(l0, l1);
    }
    const float rs = rsqrtf(1.f + EPS_BN);
    if (tid < C_DIM) {
        float4 pp; pp.x = bb[tid]; pp.y = gg[tid] * rs; pp.z = be[tid]; pp.w = 0.f;
        *(float4*)(smem + SM_PAR + tid * 16) = pp;
    }
    *(float4*)(smem + SM_W1 + tid * 16) = *(const float4*)&Ww1[tid * 4];
    __syncthreads();

    const int rbase = (wid & 3) * 16;
    const int cbase = (wid >> 2) * 64;
    float acc[8][4];
#pragma unroll
    for (int nt = 0; nt < 8; nt++)
#pragma unroll
        for (int q = 0; q < 4; q++) acc[nt][q] = 0.f;

    const uint32_t aoff_lo = k1_off(rbase + grp, 0) + tig * 8;
    const uint32_t aoff_hi = k1_off(rbase + grp + 8, 0) + tig * 8;

#pragma unroll
    for (int ks = 0; ks < 8; ks++) {
        const uint32_t kb = ks * 32;
        ull alo_h = *(const ull*)(smem + SM_AH + aoff_lo + kb);
        ull ahi_h = *(const ull*)(smem + SM_AH + aoff_hi + kb);
        ull alo_l = *(const ull*)(smem + SM_AL + aoff_lo + kb);
        ull ahi_l = *(const ull*)(smem + SM_AL + aoff_hi + kb);
        uint32_t a0h = (uint32_t)alo_h, a2h = (uint32_t)(alo_h >> 32);
        uint32_t a1h = (uint32_t)ahi_h, a3h = (uint32_t)(ahi_h >> 32);
        uint32_t a0l = (uint32_t)alo_l, a2l = (uint32_t)(alo_l >> 32);
        uint32_t a1l = (uint32_t)ahi_l, a3l = (uint32_t)(ahi_l >> 32);
#pragma unroll
        for (int nt = 0; nt < 8; nt++) {
            uint32_t boff = (uint32_t)(cbase + nt * 8 + grp) * K1_ROWB + kb + tig * 8;
            ull bh = *(const ull*)(smem + SM_BH + boff);
            ull bl = *(const ull*)(smem + SM_BL + boff);
            uint32_t b0h = (uint32_t)bh, b1h = (uint32_t)(bh >> 32);
            uint32_t b0l = (uint32_t)bl, b1l = (uint32_t)(bl >> 32);
            mma_bf16(acc[nt], a0h, a1h, a2h, a3h, b0h, b1h);
            mma_bf16(acc[nt], a0h, a1h, a2h, a3h, b0l, b1l);
            mma_bf16(acc[nt], a0l, a1l, a2l, a3l, b0h, b1h);
        }
    }
    __syncthreads();

    {
        float* ks_s = (float*)(smem + SM_KS);
        const float4* par = (const float4*)(smem + SM_PAR);
        const int r0 = rbase + grp, r1 = r0 + 8;
#pragma unroll
        for (int nt = 0; nt < 8; nt++) {
            int col = cbase + nt * 8 + tig * 2;
            float4 p0 = par[col], p1 = par[col + 1];
            float2 lo, hi;
            lo.x = fmaxf(fmaf(acc[nt][0] + p0.x, p0.y, p0.z), 0.f);
            lo.y = fmaxf(fmaf(acc[nt][1] + p1.x, p1.y, p1.z), 0.f);
            hi.x = fmaxf(fmaf(acc[nt][2] + p0.x, p0.y, p0.z), 0.f);
            hi.y = fmaxf(fmaf(acc[nt][3] + p1.x, p1.y, p1.z), 0.f);
            *(float2*)&ks_s[r0 * 130 + col] = lo;
            *(float2*)&ks_s[r1 * 130 + col] = hi;
        }
    }
    __syncthreads();

    {
        const float* ks_s = (const float*)(smem + SM_KS);
        const float* W1   = (const float*)(smem + SM_W1);
#pragma unroll
        for (int s2 = 0; s2 < 2; s2++) {
            int task = tid + s2 * 256;
            int row = task >> 3, g = task & 7;
            const float* kr = &ks_s[row * 130];
            float a0 = 0.f, a1 = 0.f, a2 = 0.f, a3 = 0.f;
#pragma unroll 8
            for (int c = 0; c < C_DIM; c += 4) {
                a0 = fmaf(kr[c],     W1[(c)     * G_DIM + g], a0);
                a1 = fmaf(kr[c + 1], W1[(c + 1) * G_DIM + g], a1);
                a2 = fmaf(kr[c + 2], W1[(c + 2) * G_DIM + g], a2);
                a3 = fmaf(kr[c + 3], W1[(c + 3) * G_DIM + g], a3);
            }
            dst[(size_t)(bm0 + row) * G_DIM + g] = (a0 + a1) + (a2 + a3);
        }
    }
}

// ---------------- K3: attention weights + U/H accumulation -------------------
struct S3 {
    float WpwT[G_DIM * 132];
    float ww2s[G_DIM * G_DIM];
    float hs[2][KNN * 132];
    float e_s[KNN * G_DIM];
    float psum[4 * G_DIM];
    float wpsum[4 * G_DIM];
    float pos[2][KNN * 4];
    float kwg[2][KNN * G_DIM];
    float qw[2][G_DIM];
    float msk[2][KNN];
    int   idx[2][KNN];
};

__device__ __forceinline__ void gatherK(S3* s, const int* __restrict__ knn,
                                        const float* __restrict__ qcoord,
                                        const float* __restrict__ ccoord,
                                        int m, int p, int k) {
    int id = knn[(size_t)m * KNN + k];
    float mk = id >= 0 ? 1.f : 0.f;
    int id0 = id >= 0 ? id : 0;
    s->idx[p][k] = id0;
    s->msk[p][k] = mk;
    float qx = qcoord[m * 3 + 0], qy = qcoord[m * 3 + 1], qz = qcoord[m * 3 + 2];
    s->pos[p][k * 4 + 0] = (ccoord[(size_t)id0 * 3 + 0] - qx) * mk;
    s->pos[p][k * 4 + 1] = (ccoord[(size_t)id0 * 3 + 1] - qy) * mk;
    s->pos[p][k * 4 + 2] = (ccoord[(size_t)id0 * 3 + 2] - qz) * mk;
    const float4* kwp = (const float4*)&g_kw[(size_t)id0 * G_DIM];
    float4 a = kwp[0], b = kwp[1];
    float* kd = &s->kwg[p][k * 8];
    kd[0] = a.x * mk; kd[1] = a.y * mk; kd[2] = a.z * mk; kd[3] = a.w * mk;
    kd[4] = b.x * mk; kd[5] = b.y * mk; kd[6] = b.z * mk; kd[7] = b.w * mk;
}

__launch_bounds__(128, 4)
__global__ void k3_attn(const float* __restrict__ qcoord, const float* __restrict__ ccoord,
                        const int*   __restrict__ knn, const float* __restrict__ cf,
                        const float* __restrict__ Wp1, const float* __restrict__ bp1,
                        const float* __restrict__ gp1, const float* __restrict__ betap1,
                        const float* __restrict__ bw1, const float* __restrict__ gw1,
                        const float* __restrict__ betaw1,
                        const float* __restrict__ Ww2, const float* __restrict__ bw2) {
    __shared__ S3 s;
    const int t = threadIdx.x;
    const int c = t;
    const int kB = t >> 3, gB = t & 7;
    const int w4 = t >> 5;
    const int lane = t & 31;
    const int lbase = lane & ~7;

    for (int i = t; i < G_DIM * C_DIM; i += 128) {
        int r = i >> 7, cc2 = i & 127;
        s.WpwT[r * 132 + cc2] = g_WpwT[i];
    }
    if (t < G_DIM * G_DIM) s.ww2s[t] = Ww2[t];

    const float rs  = rsqrtf(1.f + EPS_BN);
    const float sp1 = gp1[c] * rs;
    const float wf0 = Wp1[c] * sp1, wf1 = Wp1[C_DIM + c] * sp1, wf2 = Wp1[2 * C_DIM + c] * sp1;
    const float hb  = fmaf(bp1[c], sp1, betap1[c]);
    const float sw1  = gw1[gB] * rs;
    const float wb1f = fmaf(bw1[gB], sw1, betaw1[gB]);
    const float pwbB = g_pwb[gB];
    const float bw2B = bw2[gB];

    const int mb = blockIdx.x * 8;
    float cfpre[KNN];

    if (t < KNN)   gatherK(&s, knn, qcoord, ccoord, mb, 0, t);
    if (t < G_DIM) s.qw[0][t] = g_qw[(size_t)mb * G_DIM + t];
    __syncthreads();

    for (int qi = 0; qi < 8; qi++) {
        const int b = qi & 1;
        const int m = mb + qi;

        {
#pragma unroll
            for (int k = 0; k < KNN; k++) {
                const float* pp = &s.pos[b][k * 4];
                s.hs[b][k * 132 + c] =
                    fmaxf(fmaf(wf0, pp[0], fmaf(wf1, pp[1], fmaf(wf2, pp[2], hb))), 0.f);
            }
            if (qi < 7) {
                if (t < KNN)   gatherK(&s, knn, qcoord, ccoord, m + 1, b ^ 1, t);
                if (t < G_DIM) s.qw[b ^ 1][t] = g_qw[(size_t)(m + 1) * G_DIM + t];
            }
            if (qi > 0) {
                const int bp = b ^ 1;
                const int mp = m - 1;
                float hh[G_DIM], uu[G_DIM];
#pragma unroll
                for (int g2 = 0; g2 < G_DIM; g2++) { hh[g2] = 0.f; uu[g2] = 0.f; }
#pragma unroll
                for (int k = 0; k < KNN; k++) {
                    float hk = s.hs[bp][k * 132 + c];
                    float cv = cfpre[k];
                    float4 ea = *(const float4*)&s.e_s[k * 8];
                    float4 eb = *(const float4*)&s.e_s[k * 8 + 4];
                    uu[0] = fmaf(cv, ea.x, uu[0]); hh[0] = fmaf(hk, ea.x, hh[0]);
                    uu[1] = fmaf(cv, ea.y, uu[1]); hh[1] = fmaf(hk, ea.y, hh[1]);
                    uu[2] = fmaf(cv, ea.z, uu[2]); hh[2] = fmaf(hk, ea.z, hh[2]);
                    uu[3] = fmaf(cv, ea.w, uu[3]); hh[3] = fmaf(hk, ea.w, hh[3]);
                    uu[4] = fmaf(cv, eb.x, uu[4]); hh[4] = fmaf(hk, eb.x, hh[4]);
                    uu[5] = fmaf(cv, eb.y, uu[5]); hh[5] = fmaf(hk, eb.y, hh[5]);
                    uu[6] = fmaf(cv, eb.z, uu[6]); hh[6] = fmaf(hk, eb.z, hh[6]);
                    uu[7] = fmaf(cv, eb.w, uu[7]); hh[7] = fmaf(hk, eb.w, hh[7]);
                }
                __half2* baseh = &g_Hs2h[(size_t)mp * (G_DIM * 128)];
#pragma unroll
                for (int g2 = 0; g2 < G_DIM; g2++)
                    baseh[g2 * 128 + c] = __floats2half2_rn(uu[g2], hh[g2]);
                if (t < G_DIM) {
                    g_sums[(size_t)mp * G_DIM + t] =
                        s.psum[t] + s.psum[8 + t] + s.psum[16 + t] + s.psum[24 + t];
                    g_wsr[(size_t)mp * G_DIM + t] =
                        s.wpsum[t] + s.wpsum[8 + t] + s.wpsum[16 + t] + s.wpsum[24 + t];
                }
            }
        }
        __syncthreads();

        {
            float a0 = s.kwg[b][t] - s.qw[b][gB] + pwbB;
            float a1 = 0.f, a2 = 0.f, a3 = 0.f;
            const float4* hr = (const float4*)&s.hs[b][kB * 132];
            const float4* wr = (const float4*)&s.WpwT[gB * 132];
#pragma unroll
            for (int j = 0; j < 32; j += 4) {
                float4 h0 = hr[j],     w0 = wr[j];
                float4 h1 = hr[j + 1], w1 = wr[j + 1];
                float4 h2 = hr[j + 2], w2 = wr[j + 2];
                float4 h3 = hr[j + 3], w3 = wr[j + 3];
                a0 = fmaf(h0.x, w0.x, fmaf(h0.y, w0.y, fmaf(h0.z, w0.z, fmaf(h0.w, w0.w, a0))));
                a1 = fmaf(h1.x, w1.x, fmaf(h1.y, w1.y, fmaf(h1.z, w1.z, fmaf(h1.w, w1.w, a1))));
                a2 = fmaf(h2.x, w2.x, fmaf(h2.y, w2.y, fmaf(h2.z, w2.z, fmaf(h2.w, w2.w, a2))));
                a3 = fmaf(h3.x, w3.x, fmaf(h3.y, w3.y, fmaf(h3.z, w3.z, fmaf(h3.w, w3.w, a3))));
            }
            float ts = fmaxf(fmaf((a0 + a1) + (a2 + a3), sw1, wb1f), 0.f);

            float lg = bw2B;
#pragma unroll
            for (int g2 = 0; g2 < G_DIM; g2++)
                lg = fmaf(__shfl_sync(0xffffffffu, ts, lbase + g2), s.ww2s[g2 * G_DIM + gB], lg);

            float e  = __expf(lg);
            float mk = s.msk[b][kB];
            float em = e * mk;
            s.e_s[t] = em;
            float es = e;
            es += __shfl_xor_sync(0xffffffffu, es, 8);
            es += __shfl_xor_sync(0xffffffffu, es, 16);
            float esm = em;
            esm += __shfl_xor_sync(0xffffffffu, esm, 8);
            esm += __shfl_xor_sync(0xffffffffu, esm, 16);
            if (lane < 8) { s.psum[w4 * 8 + gB] = es; s.wpsum[w4 * 8 + gB] = esm; }

            const int* ix = s.idx[b];
#pragma unroll
            for (int k = 0; k < KNN; k++) cfpre[k] = cf[(size_t)ix[k] * C_DIM + c];
        }
        __syncthreads();
    }

    {
        const int bp = 1;
        const int mp = mb + 7;
        float hh[G_DIM], uu[G_DIM];
#pragma unroll
        for (int g2 = 0; g2 < G_DIM; g2++) { hh[g2] = 0.f; uu[g2] = 0.f; }
#pragma unroll
        for (int k = 0; k < KNN; k++) {
            float hk = s.hs[bp][k * 132 + c];
            float cv = cfpre[k];
            float4 ea = *(const float4*)&s.e_s[k * 8];
            float4 eb = *(const float4*)&s.e_s[k * 8 + 4];
            uu[0] = fmaf(cv, ea.x, uu[0]); hh[0] = fmaf(hk, ea.x, hh[0]);
            uu[1] = fmaf(cv, ea.y, uu[1]); hh[1] = fmaf(hk, ea.y, hh[1]);
            uu[2] = fmaf(cv, ea.z, uu[2]); hh[2] = fmaf(hk, ea.z, hh[2]);
            uu[3] = fmaf(cv, ea.w, uu[3]); hh[3] = fmaf(hk, ea.w, hh[3]);
            uu[4] = fmaf(cv, eb.x, uu[4]); hh[4] = fmaf(hk, eb.x, hh[4]);
            uu[5] = fmaf(cv, eb.y, uu[5]); hh[5] = fmaf(hk, eb.y, hh[5]);
            uu[6] = fmaf(cv, eb.z, uu[6]); hh[6] = fmaf(hk, eb.z, hh[6]);
            uu[7] = fmaf(cv, eb.w, uu[7]); hh[7] = fmaf(hk, eb.w, hh[7]);
        }
        __half2* baseh = &g_Hs2h[(size_t)mp * (G_DIM * 128)];
#pragma unroll
        for (int g2 = 0; g2 < G_DIM; g2++)
            baseh[g2 * 128 + c] = __floats2half2_rn(uu[g2], hh[g2]);
        if (t < G_DIM) {
            g_sums[(size_t)mp * G_DIM + t] =
                s.psum[t] + s.psum[8 + t] + s.psum[16 + t] + s.psum[24 + t];
            g_wsr[(size_t)mp * G_DIM + t] =
                s.wpsum[t] + s.wpsum[8 + t] + s.wpsum[16 + t] + s.wpsum[24 + t];
        }
    }
}

// ---------------- K4: epilogue via fp16 HMMA ---------------------------------
// Block: 64 m x 16 cc for one g. 8 warps: m-tile = wid&3 (4 x m16),
// n-tile = wid>>2 (2 x n8). A rows = (U,H) half2; B cols = (Wv,Wp2) half2.
#define K4_AS_OFF 0
#define K4_BS_OFF (64 * 132 * 4)
#define SMEM_K4_TOTAL (64 * 132 * 4 + 16 * 132 * 4)   // 42240 B
__launch_bounds__(256, 4)
__global__ void k4_out(const float* __restrict__ Wv, const float* __restrict__ Wp2,
                       const float* __restrict__ bv, const float* __restrict__ bp2,
                       float* __restrict__ out) {
    extern __shared__ char s4raw[];
    __half2* As = (__half2*)(s4raw + K4_AS_OFF);   // [64][132]
    __half2* Bs = (__half2*)(s4raw + K4_BS_OFF);   // [16][132]
    const int m0 = blockIdx.x * 64;
    const int g  = blockIdx.y;
    const int tid = threadIdx.x;

    for (int i = tid; i < 2048; i += 256) {
        int r = i >> 5, q = i & 31;
        *(uint4*)&As[r * 132 + q * 4] =
            *(const uint4*)&g_Hs2h[((size_t)(m0 + r) * G_DIM + g) * 128 + q * 4];
    }
    for (int i = tid; i < 2048; i += 256) {
        int c2 = i >> 4, cc = i & 15;
        float wv = Wv[(size_t)c2 * C_DIM + g * 16 + cc];
        float wp = Wp2[(size_t)c2 * C_DIM + g * 16 + cc];
        Bs[cc * 132 + c2] = __floats2half2_rn(wv, wp);
    }
    __syncthreads();

    const int wid = tid >> 5, lane = tid & 31;
    const int grp = lane >> 2, tig = lane & 3;
    const int mt = wid & 3, nt = wid >> 2;     // m16 tile, n8 tile
    const __half2* Ar0 = &As[(mt * 16 + grp) * 132];       // rows <= 3*16+7 = 55
    const __half2* Ar1 = &As[(mt * 16 + grp + 8) * 132];   // rows <= 63
    const __half2* Bc  = &Bs[(nt * 8 + grp) * 132];        // cols <= 15

    float acc[4] = {0.f, 0.f, 0.f, 0.f};
#pragma unroll
    for (int ks = 0; ks < 16; ks++) {
        const int cb = ks * 8;
        uint32_t a0 = *(const uint32_t*)&Ar0[cb + tig];
        uint32_t a1 = *(const uint32_t*)&Ar1[cb + tig];
        uint32_t a2 = *(const uint32_t*)&Ar0[cb + tig + 4];
        uint32_t a3 = *(const uint32_t*)&Ar1[cb + tig + 4];
        uint32_t b0 = *(const uint32_t*)&Bc[cb + tig];
        uint32_t b1 = *(const uint32_t*)&Bc[cb + tig + 4];
        mma_f16(acc, a0, a1, a2, a3, b0, b1);
    }

    const int mA = m0 + mt * 16 + grp;
    const int mB = mA + 8;
    const float invA = 1.f / g_sums[(size_t)mA * G_DIM + g];
    const float wsA  = g_wsr[(size_t)mA * G_DIM + g];
    const float invB = 1.f / g_sums[(size_t)mB * G_DIM + g];
    const float wsB  = g_wsr[(size_t)mB * G_DIM + g];
    const int c0 = g * 16 + nt * 8 + 2 * tig;
    const float bb0 = bv[c0] + bp2[c0];
    const float bb1 = bv[c0 + 1] + bp2[c0 + 1];
    float2 oA, oB;
    oA.x = (acc[0] + bb0 * wsA) * invA;
    oA.y = (acc[1] + bb1 * wsA) * invA;
    oB.x = (acc[2] + bb0 * wsB) * invB;
    oB.y = (acc[3] + bb1 * wsB) * invB;
    *(float2*)&out[(size_t)mA * C_DIM + c0] = oA;
    *(float2*)&out[(size_t)mB * C_DIM + c0] = oB;
}

// ---------------- launch -----------------------------------------------------
extern "C" void kernel_launch(void* const* d_in, const int* in_sizes, int n_in,
                              void* d_out, int out_size) {
    const float* qf     = (const float*)d_in[0];
    const float* cf     = (const float*)d_in[1];
    const float* qc     = (const float*)d_in[2];
    const float* cc     = (const float*)d_in[3];
    const float* Wq     = (const float*)d_in[4];
    const float* bq     = (const float*)d_in[5];
    const float* gq     = (const float*)d_in[6];
    const float* betaq  = (const float*)d_in[7];
    const float* Wk     = (const float*)d_in[8];
    const float* bk     = (const float*)d_in[9];
    const float* gk     = (const float*)d_in[10];
    const float* betak  = (const float*)d_in[11];
    const float* Wv     = (const float*)d_in[12];
    const float* bv     = (const float*)d_in[13];
    const float* Wp1    = (const float*)d_in[14];
    const float* bp1    = (const float*)d_in[15];
    const float* gp1    = (const float*)d_in[16];
    const float* betap1 = (const float*)d_in[17];
    const float* Wp2    = (const float*)d_in[18];
    const float* bp2    = (const float*)d_in[19];
    const float* Ww1    = (const float*)d_in[20];
    const float* bw1    = (const float*)d_in[21];
    const float* gw1    = (const float*)d_in[22];
    const float* betaw1 = (const float*)d_in[23];
    const float* Ww2    = (const float*)d_in[24];
    const float* bw2    = (const float*)d_in[25];
    const int*   knn    = (const int*)d_in[26];
    float* out = (float*)d_out;

    const int M = in_sizes[0] / C_DIM;
    const int N = in_sizes[1] / C_DIM;
    const int NB = N / 64, MB = M / 64;

    cudaFuncSetAttribute(k0_prep, cudaFuncAttributeMaxDynamicSharedMemorySize,
                         SMEM_K0_TOTAL);
    k0_prep<<<1, 256, SMEM_K0_TOTAL>>>(Wp2, Ww1, bp2);

    cudaFuncSetAttribute(k12_proj, cudaFuncAttributeMaxDynamicSharedMemorySize,
                         SMEM_K12_TOTAL);
    k12_proj<<<NB + MB, 256, SMEM_K12_TOTAL>>>(cf, qf, Wk, bk, gk, betak,
                                               Wq, bq, gq, betaq, Ww1, NB);

    k3_attn<<<M / 8, 128>>>(qc, cc, knn, cf, Wp1, bp1, gp1, betap1,
                            bw1, gw1, betaw1, Ww2, bw2);

    cudaFuncSetAttribute(k4_out, cudaFuncAttributeMaxDynamicSharedMemorySize,
                         SMEM_K4_TOTAL);
    dim3 g4(M / 64, G_DIM);
    k4_out<<<g4, 256, SMEM_K4_TOTAL>>>(Wv, Wp2, bv, bp2, out);
}

// round 10
// speedup vs baseline: 2.2302x; 1.0618x over previous
#include <cuda_runtime.h>
#include <cuda_bf16.h>
#include <cuda_fp16.h>
#include <cstdint>

#define C_DIM 128
#define G_DIM 8
#define KNN   16
#define EPS_BN 1e-5f
#define N_CTX_MAX 131072
#define M_Q_MAX   16384

// ---------------- scratch (static device memory; no runtime allocation) -----
__device__ float   g_kw  [(size_t)N_CTX_MAX * G_DIM];
__device__ float   g_qw  [(size_t)M_Q_MAX   * G_DIM];
__device__ float   g_WpwT[G_DIM * C_DIM];
__device__ float   g_pwb [G_DIM];
__device__ __align__(16) __half2 g_Hs2h[(size_t)M_Q_MAX * G_DIM * 128];  // (U,H), 64 MB
__device__ float   g_sums[(size_t)M_Q_MAX * G_DIM];
__device__ float   g_wsr [(size_t)M_Q_MAX * G_DIM];
// bf16 hi/lo split of Wk (mat 0) / Wq (mat 1), fragment-packed (k1_off layout)
__device__ __align__(16) uint4 g_Wsplit[2][2][2176];   // [mat][hi/lo][128*272/16]

typedef unsigned long long ull;

// bf16 HMMA m16n8k16
__device__ __forceinline__ void mma_bf16(float* d, uint32_t a0, uint32_t a1,
                                         uint32_t a2, uint32_t a3,
                                         uint32_t b0, uint32_t b1) {
    asm volatile(
        "mma.sync.aligned.m16n8k16.row.col.f32.bf16.bf16.f32 "
        "{%0,%1,%2,%3}, {%4,%5,%6,%7}, {%8,%9}, {%0,%1,%2,%3};"
        : "+f"(d[0]), "+f"(d[1]), "+f"(d[2]), "+f"(d[3])
        : "r"(a0), "r"(a1), "r"(a2), "r"(a3), "r"(b0), "r"(b1));
}
// fp16 HMMA m16n8k16, fp32 accum
__device__ __forceinline__ void mma_f16(float* d, uint32_t a0, uint32_t a1,
                                        uint32_t a2, uint32_t a3,
                                        uint32_t b0, uint32_t b1) {
    asm volatile(
        "mma.sync.aligned.m16n8k16.row.col.f32.f16.f16.f32 "
        "{%0,%1,%2,%3}, {%4,%5,%6,%7}, {%8,%9}, {%0,%1,%2,%3};"
        : "+f"(d[0]), "+f"(d[1]), "+f"(d[2]), "+f"(d[3])
        : "r"(a0), "r"(a1), "r"(a2), "r"(a3), "r"(b0), "r"(b1));
}

__device__ __forceinline__ uint32_t bf2_u32(__nv_bfloat162 h) {
    uint32_t u; __builtin_memcpy(&u, &h, 4); return u;
}
// split 16 floats into hi/lo bf16 pairs, fragment-packed into 2+2 uint4
__device__ __forceinline__ void split16(const float* v, uint4* outH, uint4* outL) {
    uint32_t hp[8], lp[8];
#pragma unroll
    for (int p = 0; p < 8; p++) {
        float a0 = v[2 * p], a1 = v[2 * p + 1];
        __nv_bfloat162 h = __floats2bfloat162_rn(a0, a1);
        float r0 = a0 - __bfloat162float(h.x);
        float r1 = a1 - __bfloat162float(h.y);
        __nv_bfloat162 l = __floats2bfloat162_rn(r0, r1);
        hp[p] = bf2_u32(h); lp[p] = bf2_u32(l);
    }
    outH[0] = make_uint4(hp[0], hp[4], hp[1], hp[5]);
    outH[1] = make_uint4(hp[2], hp[6], hp[3], hp[7]);
    outL[0] = make_uint4(lp[0], lp[4], lp[1], lp[5]);
    outL[1] = make_uint4(lp[2], lp[6], lp[3], lp[7]);
}

// ---------------- K0w: precompute bf16-split packed W tiles ------------------
__global__ void k0w_prep(const float* __restrict__ Wk, const float* __restrict__ Wq) {
    const int task = blockIdx.x * 256 + threadIdx.x;   // 0..2047
    const int mat = task >> 10, rem = task & 1023;
    const int n = rem >> 3, kg = rem & 7;
    const float* W = mat ? Wq : Wk;
    float v[16];
#pragma unroll
    for (int j = 0; j < 16; j++) v[j] = W[(size_t)(kg * 16 + j) * C_DIM + n];
    uint4 oh[2], ol[2];
    split16(v, oh, ol);
    const int base = n * 17 + kg * 2;
    g_Wsplit[mat][0][base]     = oh[0];
    g_Wsplit[mat][0][base + 1] = oh[1];
    g_Wsplit[mat][1][base]     = ol[0];
    g_Wsplit[mat][1][base + 1] = ol[1];
}

// ---------------- K0: tiny prep (coalesced, smem-staged) ---------------------
#define SMEM_K0_TOTAL ((128 * 132 + 1024) * 4)
__global__ void k0_prep(const float* __restrict__ Wp2,
                        const float* __restrict__ Ww1,
                        const float* __restrict__ bp2) {
    extern __shared__ float sp[];
    float* WpS = sp;
    float* W1s = sp + 128 * 132;
    const int tid = threadIdx.x;
    for (int i = tid; i < 4096; i += 256) {
        int r = i >> 5, q = i & 31;
        *(float4*)&WpS[r * 132 + q * 4] = *(const float4*)&Wp2[r * C_DIM + q * 4];
    }
    if (tid < 256) *(float4*)&W1s[tid * 4] = *(const float4*)&Ww1[tid * 4];
    __syncthreads();

    if (tid < 128) {
        const int c = tid;
        float acc[G_DIM];
#pragma unroll
        for (int g = 0; g < G_DIM; g++) acc[g] = 0.f;
        const float* wr = &WpS[c * 132];
#pragma unroll 8
        for (int c2 = 0; c2 < C_DIM; c2++) {
            float a = wr[c2];
#pragma unroll
            for (int g = 0; g < G_DIM; g++) acc[g] = fmaf(a, W1s[c2 * G_DIM + g], acc[g]);
        }
#pragma unroll
        for (int g = 0; g < G_DIM; g++) g_WpwT[g * C_DIM + c] = acc[g];
    } else if (tid < 128 + G_DIM) {
        const int g = tid - 128;
        float s = 0.f;
        for (int c2 = 0; c2 < C_DIM; c2++) s = fmaf(bp2[c2], W1s[c2 * G_DIM + g], s);
        g_pwb[g] = s;
    }
}

// ---------------- K12: fused context+query pass (bf16-split HMMA, occ 2) -----
#define K1_ROWB 272
__device__ __forceinline__ uint32_t k1_off(int row, int k) {
    int p = k >> 1;
    return (uint32_t)row * K1_ROWB + (uint32_t)(k >> 4) * 32
         + (uint32_t)(p & 3) * 8 + (uint32_t)((p >> 2) & 1) * 4;
}

#define SM_AH   0
#define SM_AL   17408
#define SM_BH   34816
#define SM_BL   69632
#define SM_PAR  104448
#define SM_W1   106496
#define SM_KS   0
#define SMEM_K12_TOTAL 110592

__launch_bounds__(256, 2)
__global__ void k12_proj(const float* __restrict__ cf, const float* __restrict__ qf,
                         const float* __restrict__ bk,
                         const float* __restrict__ gk, const float* __restrict__ betak,
                         const float* __restrict__ bq,
                         const float* __restrict__ gq, const float* __restrict__ betaq,
                         const float* __restrict__ Ww1, int NB) {
    extern __shared__ char smem[];
    const int tid = threadIdx.x;
    const int wid = tid >> 5;
    const int lane = tid & 31;
    const int grp = lane >> 2, tig = lane & 3;

    const bool ctx = (int)blockIdx.x < NB;
    const int bm0 = (ctx ? (int)blockIdx.x : (int)blockIdx.x - NB) * 64;
    const float* feat = ctx ? cf : qf;
    const float* bb   = ctx ? bk : bq;
    const float* gg   = ctx ? gk : gq;
    const float* be   = ctx ? betak : betaq;
    float* dst        = ctx ? g_kw : g_qw;
    const int mat     = ctx ? 0 : 1;

    // ---- A tile: 512 (row, k16-group) tasks, 2 per thread ----
#pragma unroll
    for (int s2 = 0; s2 < 2; s2++) {
        int task = tid + s2 * 256;
        int row = task >> 3, kg = task & 7;
        const float4* src = (const float4*)&feat[(size_t)(bm0 + row) * C_DIM + kg * 16];
        float v[16];
        float4 x0 = src[0], x1 = src[1], x2 = src[2], x3 = src[3];
        v[0]=x0.x; v[1]=x0.y; v[2]=x0.z; v[3]=x0.w;
        v[4]=x1.x; v[5]=x1.y; v[6]=x1.z; v[7]=x1.w;
        v[8]=x2.x; v[9]=x2.y; v[10]=x2.z; v[11]=x2.w;
        v[12]=x3.x; v[13]=x3.y; v[14]=x3.z; v[15]=x3.w;
        uint4 oh[2], ol[2];
        split16(v, oh, ol);
        uint4* dH = (uint4*)(smem + SM_AH + row * K1_ROWB + kg * 32);
        uint4* dL = (uint4*)(smem + SM_AL + row * K1_ROWB + kg * 32);
        dH[0] = oh[0]; dH[1] = oh[1];
        dL[0] = ol[0]; dL[1] = ol[1];
    }
    // ---- B tile: straight uint4 copy from precomputed split ----
    {
        const uint4* WH = g_Wsplit[mat][0];
        const uint4* WL = g_Wsplit[mat][1];
        uint4* BH = (uint4*)(smem + SM_BH);
        uint4* BL = (uint4*)(smem + SM_BL);
        for (int i = tid; i < 2176; i += 256) { BH[i] = WH[i]; BL[i] = WL[i]; }
    }
    const float rs = rsqrtf(1.f + EPS_BN);
    if (tid < C_DIM) {
        float4 pp; pp.x = bb[tid]; pp.y = gg[tid] * rs; pp.z = be[tid]; pp.w = 0.f;
        *(float4*)(smem + SM_PAR + tid * 16) = pp;
    }
    *(float4*)(smem + SM_W1 + tid * 16) = *(const float4*)&Ww1[tid * 4];
    __syncthreads();

    const int rbase = (wid & 3) * 16;
    const int cbase = (wid >> 2) * 64;
    float acc[8][4];
#pragma unroll
    for (int nt = 0; nt < 8; nt++)
#pragma unroll
        for (int q = 0; q < 4; q++) acc[nt][q] = 0.f;

    const uint32_t aoff_lo = k1_off(rbase + grp, 0) + tig * 8;
    const uint32_t aoff_hi = k1_off(rbase + grp + 8, 0) + tig * 8;

#pragma unroll
    for (int ks = 0; ks < 8; ks++) {
        const uint32_t kb = ks * 32;
        ull alo_h = *(const ull*)(smem + SM_AH + aoff_lo + kb);
        ull ahi_h = *(const ull*)(smem + SM_AH + aoff_hi + kb);
        ull alo_l = *(const ull*)(smem + SM_AL + aoff_lo + kb);
        ull ahi_l = *(const ull*)(smem + SM_AL + aoff_hi + kb);
        uint32_t a0h = (uint32_t)alo_h, a2h = (uint32_t)(alo_h >> 32);
        uint32_t a1h = (uint32_t)ahi_h, a3h = (uint32_t)(ahi_h >> 32);
        uint32_t a0l = (uint32_t)alo_l, a2l = (uint32_t)(alo_l >> 32);
        uint32_t a1l = (uint32_t)ahi_l, a3l = (uint32_t)(ahi_l >> 32);
#pragma unroll
        for (int nt = 0; nt < 8; nt++) {
            uint32_t boff = (uint32_t)(cbase + nt * 8 + grp) * K1_ROWB + kb + tig * 8;
            ull bh = *(const ull*)(smem + SM_BH + boff);
            ull bl = *(const ull*)(smem + SM_BL + boff);
            uint32_t b0h = (uint32_t)bh, b1h = (uint32_t)(bh >> 32);
            uint32_t b0l = (uint32_t)bl, b1l = (uint32_t)(bl >> 32);
            mma_bf16(acc[nt], a0h, a1h, a2h, a3h, b0h, b1h);
            mma_bf16(acc[nt], a0h, a1h, a2h, a3h, b0l, b1l);
            mma_bf16(acc[nt], a0l, a1l, a2l, a3l, b0h, b1h);
        }
    }
    __syncthreads();

    {
        float* ks_s = (float*)(smem + SM_KS);
        const float4* par = (const float4*)(smem + SM_PAR);
        const int r0 = rbase + grp, r1 = r0 + 8;
#pragma unroll
        for (int nt = 0; nt < 8; nt++) {
            int col = cbase + nt * 8 + tig * 2;
            float4 p0 = par[col], p1 = par[col + 1];
            float2 lo, hi;
            lo.x = fmaxf(fmaf(acc[nt][0] + p0.x, p0.y, p0.z), 0.f);
            lo.y = fmaxf(fmaf(acc[nt][1] + p1.x, p1.y, p1.z), 0.f);
            hi.x = fmaxf(fmaf(acc[nt][2] + p0.x, p0.y, p0.z), 0.f);
            hi.y = fmaxf(fmaf(acc[nt][3] + p1.x, p1.y, p1.z), 0.f);
            *(float2*)&ks_s[r0 * 130 + col] = lo;
            *(float2*)&ks_s[r1 * 130 + col] = hi;
        }
    }
    __syncthreads();

    {
        const float* ks_s = (const float*)(smem + SM_KS);
        const float* W1   = (const float*)(smem + SM_W1);
#pragma unroll
        for (int s2 = 0; s2 < 2; s2++) {
            int task = tid + s2 * 256;
            int row = task >> 3, g = task & 7;
            const float* kr = &ks_s[row * 130];
            float a0 = 0.f, a1 = 0.f, a2 = 0.f, a3 = 0.f;
#pragma unroll 8
            for (int c = 0; c < C_DIM; c += 4) {
                a0 = fmaf(kr[c],     W1[(c)     * G_DIM + g], a0);
                a1 = fmaf(kr[c + 1], W1[(c + 1) * G_DIM + g], a1);
                a2 = fmaf(kr[c + 2], W1[(c + 2) * G_DIM + g], a2);
                a3 = fmaf(kr[c + 3], W1[(c + 3) * G_DIM + g], a3);
            }
            dst[(size_t)(bm0 + row) * G_DIM + g] = (a0 + a1) + (a2 + a3);
        }
    }
}

// ---------------- K3: attention weights + U/H accumulation -------------------
struct S3 {
    float WpwT[G_DIM * 132];
    float ww2s[G_DIM * G_DIM];
    float hs[2][KNN * 132];
    float e_s[KNN * G_DIM];
    float psum[4 * G_DIM];
    float wpsum[4 * G_DIM];
    float pos[2][KNN * 4];
    float kwg[2][KNN * G_DIM];
    float qw[2][G_DIM];
    float msk[2][KNN];
    int   idx[2][KNN];
};

__device__ __forceinline__ void gatherK(S3* s, const int* __restrict__ knn,
                                        const float* __restrict__ qcoord,
                                        const float* __restrict__ ccoord,
                                        int m, int p, int k) {
    int id = knn[(size_t)m * KNN + k];
    float mk = id >= 0 ? 1.f : 0.f;
    int id0 = id >= 0 ? id : 0;
    s->idx[p][k] = id0;
    s->msk[p][k] = mk;
    float qx = qcoord[m * 3 + 0], qy = qcoord[m * 3 + 1], qz = qcoord[m * 3 + 2];
    s->pos[p][k * 4 + 0] = (ccoord[(size_t)id0 * 3 + 0] - qx) * mk;
    s->pos[p][k * 4 + 1] = (ccoord[(size_t)id0 * 3 + 1] - qy) * mk;
    s->pos[p][k * 4 + 2] = (ccoord[(size_t)id0 * 3 + 2] - qz) * mk;
    const float4* kwp = (const float4*)&g_kw[(size_t)id0 * G_DIM];
    float4 a = kwp[0], b = kwp[1];
    float* kd = &s->kwg[p][k * 8];
    kd[0] = a.x * mk; kd[1] = a.y * mk; kd[2] = a.z * mk; kd[3] = a.w * mk;
    kd[4] = b.x * mk; kd[5] = b.y * mk; kd[6] = b.z * mk; kd[7] = b.w * mk;
}

__launch_bounds__(128, 4)
__global__ void k3_attn(const float* __restrict__ qcoord, const float* __restrict__ ccoord,
                        const int*   __restrict__ knn, const float* __restrict__ cf,
                        const float* __restrict__ Wp1, const float* __restrict__ bp1,
                        const float* __restrict__ gp1, const float* __restrict__ betap1,
                        const float* __restrict__ bw1, const float* __restrict__ gw1,
                        const float* __restrict__ betaw1,
                        const float* __restrict__ Ww2, const float* __restrict__ bw2) {
    __shared__ S3 s;
    const int t = threadIdx.x;
    const int c = t;
    const int kB = t >> 3, gB = t & 7;
    const int w4 = t >> 5;
    const int lane = t & 31;
    const int lbase = lane & ~7;

    for (int i = t; i < G_DIM * C_DIM; i += 128) {
        int r = i >> 7, cc2 = i & 127;
        s.WpwT[r * 132 + cc2] = g_WpwT[i];
    }
    if (t < G_DIM * G_DIM) s.ww2s[t] = Ww2[t];

    const float rs  = rsqrtf(1.f + EPS_BN);
    const float sp1 = gp1[c] * rs;
    const float wf0 = Wp1[c] * sp1, wf1 = Wp1[C_DIM + c] * sp1, wf2 = Wp1[2 * C_DIM + c] * sp1;
    const float hb  = fmaf(bp1[c], sp1, betap1[c]);
    const float sw1  = gw1[gB] * rs;
    const float wb1f = fmaf(bw1[gB], sw1, betaw1[gB]);
    const float pwbB = g_pwb[gB];
    const float bw2B = bw2[gB];

    const int mb = blockIdx.x * 8;
    float cfpre[KNN];

    if (t < KNN)   gatherK(&s, knn, qcoord, ccoord, mb, 0, t);
    if (t < G_DIM) s.qw[0][t] = g_qw[(size_t)mb * G_DIM + t];
    __syncthreads();

    for (int qi = 0; qi < 8; qi++) {
        const int b = qi & 1;
        const int m = mb + qi;

        {
#pragma unroll
            for (int k = 0; k < KNN; k++) {
                const float* pp = &s.pos[b][k * 4];
                s.hs[b][k * 132 + c] =
                    fmaxf(fmaf(wf0, pp[0], fmaf(wf1, pp[1], fmaf(wf2, pp[2], hb))), 0.f);
            }
            if (qi < 7) {
                if (t < KNN)   gatherK(&s, knn, qcoord, ccoord, m + 1, b ^ 1, t);
                if (t < G_DIM) s.qw[b ^ 1][t] = g_qw[(size_t)(m + 1) * G_DIM + t];
            }
            if (qi > 0) {
                const int bp = b ^ 1;
                const int mp = m - 1;
                float hh[G_DIM], uu[G_DIM];
#pragma unroll
                for (int g2 = 0; g2 < G_DIM; g2++) { hh[g2] = 0.f; uu[g2] = 0.f; }
#pragma unroll
                for (int k = 0; k < KNN; k++) {
                    float hk = s.hs[bp][k * 132 + c];
                    float cv = cfpre[k];
                    float4 ea = *(const float4*)&s.e_s[k * 8];
                    float4 eb = *(const float4*)&s.e_s[k * 8 + 4];
                    uu[0] = fmaf(cv, ea.x, uu[0]); hh[0] = fmaf(hk, ea.x, hh[0]);
                    uu[1] = fmaf(cv, ea.y, uu[1]); hh[1] = fmaf(hk, ea.y, hh[1]);
                    uu[2] = fmaf(cv, ea.z, uu[2]); hh[2] = fmaf(hk, ea.z, hh[2]);
                    uu[3] = fmaf(cv, ea.w, uu[3]); hh[3] = fmaf(hk, ea.w, hh[3]);
                    uu[4] = fmaf(cv, eb.x, uu[4]); hh[4] = fmaf(hk, eb.x, hh[4]);
                    uu[5] = fmaf(cv, eb.y, uu[5]); hh[5] = fmaf(hk, eb.y, hh[5]);
                    uu[6] = fmaf(cv, eb.z, uu[6]); hh[6] = fmaf(hk, eb.z, hh[6]);
                    uu[7] = fmaf(cv, eb.w, uu[7]); hh[7] = fmaf(hk, eb.w, hh[7]);
                }
                __half2* baseh = &g_Hs2h[(size_t)mp * (G_DIM * 128)];
#pragma unroll
                for (int g2 = 0; g2 < G_DIM; g2++)
                    baseh[g2 * 128 + c] = __floats2half2_rn(uu[g2], hh[g2]);
                if (t < G_DIM) {
                    g_sums[(size_t)mp * G_DIM + t] =
                        s.psum[t] + s.psum[8 + t] + s.psum[16 + t] + s.psum[24 + t];
                    g_wsr[(size_t)mp * G_DIM + t] =
                        s.wpsum[t] + s.wpsum[8 + t] + s.wpsum[16 + t] + s.wpsum[24 + t];
                }
            }
        }
        __syncthreads();

        {
            float a0 = s.kwg[b][t] - s.qw[b][gB] + pwbB;
            float a1 = 0.f, a2 = 0.f, a3 = 0.f;
            const float4* hr = (const float4*)&s.hs[b][kB * 132];
            const float4* wr = (const float4*)&s.WpwT[gB * 132];
#pragma unroll
            for (int j = 0; j < 32; j += 4) {
                float4 h0 = hr[j],     w0 = wr[j];
                float4 h1 = hr[j + 1], w1 = wr[j + 1];
                float4 h2 = hr[j + 2], w2 = wr[j + 2];
                float4 h3 = hr[j + 3], w3 = wr[j + 3];
                a0 = fmaf(h0.x, w0.x, fmaf(h0.y, w0.y, fmaf(h0.z, w0.z, fmaf(h0.w, w0.w, a0))));
                a1 = fmaf(h1.x, w1.x, fmaf(h1.y, w1.y, fmaf(h1.z, w1.z, fmaf(h1.w, w1.w, a1))));
                a2 = fmaf(h2.x, w2.x, fmaf(h2.y, w2.y, fmaf(h2.z, w2.z, fmaf(h2.w, w2.w, a2))));
                a3 = fmaf(h3.x, w3.x, fmaf(h3.y, w3.y, fmaf(h3.z, w3.z, fmaf(h3.w, w3.w, a3))));
            }
            float ts = fmaxf(fmaf((a0 + a1) + (a2 + a3), sw1, wb1f), 0.f);

            float lg = bw2B;
#pragma unroll
            for (int g2 = 0; g2 < G_DIM; g2++)
                lg = fmaf(__shfl_sync(0xffffffffu, ts, lbase + g2), s.ww2s[g2 * G_DIM + gB], lg);

            float e  = __expf(lg);
            float mk = s.msk[b][kB];
            float em = e * mk;
            s.e_s[t] = em;
            float es = e;
            es += __shfl_xor_sync(0xffffffffu, es, 8);
            es += __shfl_xor_sync(0xffffffffu, es, 16);
            float esm = em;
            esm += __shfl_xor_sync(0xffffffffu, esm, 8);
            esm += __shfl_xor_sync(0xffffffffu, esm, 16);
            if (lane < 8) { s.psum[w4 * 8 + gB] = es; s.wpsum[w4 * 8 + gB] = esm; }

            const int* ix = s.idx[b];
#pragma unroll
            for (int k = 0; k < KNN; k++) cfpre[k] = cf[(size_t)ix[k] * C_DIM + c];
        }
        __syncthreads();
    }

    {
        const int bp = 1;
        const int mp = mb + 7;
        float hh[G_DIM], uu[G_DIM];
#pragma unroll
        for (int g2 = 0; g2 < G_DIM; g2++) { hh[g2] = 0.f; uu[g2] = 0.f; }
#pragma unroll
        for (int k = 0; k < KNN; k++) {
            float hk = s.hs[bp][k * 132 + c];
            float cv = cfpre[k];
            float4 ea = *(const float4*)&s.e_s[k * 8];
            float4 eb = *(const float4*)&s.e_s[k * 8 + 4];
            uu[0] = fmaf(cv, ea.x, uu[0]); hh[0] = fmaf(hk, ea.x, hh[0]);
            uu[1] = fmaf(cv, ea.y, uu[1]); hh[1] = fmaf(hk, ea.y, hh[1]);
            uu[2] = fmaf(cv, ea.z, uu[2]); hh[2] = fmaf(hk, ea.z, hh[2]);
            uu[3] = fmaf(cv, ea.w, uu[3]); hh[3] = fmaf(hk, ea.w, hh[3]);
            uu[4] = fmaf(cv, eb.x, uu[4]); hh[4] = fmaf(hk, eb.x, hh[4]);
            uu[5] = fmaf(cv, eb.y, uu[5]); hh[5] = fmaf(hk, eb.y, hh[5]);
            uu[6] = fmaf(cv, eb.z, uu[6]); hh[6] = fmaf(hk, eb.z, hh[6]);
            uu[7] = fmaf(cv, eb.w, uu[7]); hh[7] = fmaf(hk, eb.w, hh[7]);
        }
        __half2* baseh = &g_Hs2h[(size_t)mp * (G_DIM * 128)];
#pragma unroll
        for (int g2 = 0; g2 < G_DIM; g2++)
            baseh[g2 * 128 + c] = __floats2half2_rn(uu[g2], hh[g2]);
        if (t < G_DIM) {
            g_sums[(size_t)mp * G_DIM + t] =
                s.psum[t] + s.psum[8 + t] + s.psum[16 + t] + s.psum[24 + t];
            g_wsr[(size_t)mp * G_DIM + t] =
                s.wpsum[t] + s.wpsum[8 + t] + s.wpsum[16 + t] + s.wpsum[24 + t];
        }
    }
}

// ---------------- K4: epilogue via fp16 HMMA ---------------------------------
#define K4_AS_OFF 0
#define K4_BS_OFF (64 * 132 * 4)
#define SMEM_K4_TOTAL (64 * 132 * 4 + 16 * 132 * 4)   // 42240 B
__launch_bounds__(256, 4)
__global__ void k4_out(const float* __restrict__ Wv, const float* __restrict__ Wp2,
                       const float* __restrict__ bv, const float* __restrict__ bp2,
                       float* __restrict__ out) {
    extern __shared__ char s4raw[];
    __half2* As = (__half2*)(s4raw + K4_AS_OFF);   // [64][132]
    __half2* Bs = (__half2*)(s4raw + K4_BS_OFF);   // [16][132]
    const int m0 = blockIdx.x * 64;
    const int g  = blockIdx.y;
    const int tid = threadIdx.x;

    for (int i = tid; i < 2048; i += 256) {
        int r = i >> 5, q = i & 31;
        *(uint4*)&As[r * 132 + q * 4] =
            *(const uint4*)&g_Hs2h[((size_t)(m0 + r) * G_DIM + g) * 128 + q * 4];
    }
    for (int i = tid; i < 2048; i += 256) {
        int c2 = i >> 4, cc = i & 15;
        float wv = Wv[(size_t)c2 * C_DIM + g * 16 + cc];
        float wp = Wp2[(size_t)c2 * C_DIM + g * 16 + cc];
        Bs[cc * 132 + c2] = __floats2half2_rn(wv, wp);
    }
    __syncthreads();

    const int wid = tid >> 5, lane = tid & 31;
    const int grp = lane >> 2, tig = lane & 3;
    const int mt = wid & 3, nt = wid >> 2;
    const __half2* Ar0 = &As[(mt * 16 + grp) * 132];
    const __half2* Ar1 = &As[(mt * 16 + grp + 8) * 132];
    const __half2* Bc  = &Bs[(nt * 8 + grp) * 132];

    float acc[4] = {0.f, 0.f, 0.f, 0.f};
#pragma unroll
    for (int ks = 0; ks < 16; ks++) {
        const int cb = ks * 8;
        uint32_t a0 = *(const uint32_t*)&Ar0[cb + tig];
        uint32_t a1 = *(const uint32_t*)&Ar1[cb + tig];
        uint32_t a2 = *(const uint32_t*)&Ar0[cb + tig + 4];
        uint32_t a3 = *(const uint32_t*)&Ar1[cb + tig + 4];
        uint32_t b0 = *(const uint32_t*)&Bc[cb + tig];
        uint32_t b1 = *(const uint32_t*)&Bc[cb + tig + 4];
        mma_f16(acc, a0, a1, a2, a3, b0, b1);
    }

    const int mA = m0 + mt * 16 + grp;
    const int mB = mA + 8;
    const float invA = 1.f / g_sums[(size_t)mA * G_DIM + g];
    const float wsA  = g_wsr[(size_t)mA * G_DIM + g];
    const float invB = 1.f / g_sums[(size_t)mB * G_DIM + g];
    const float wsB  = g_wsr[(size_t)mB * G_DIM + g];
    const int c0 = g * 16 + nt * 8 + 2 * tig;
    const float bb0 = bv[c0] + bp2[c0];
    const float bb1 = bv[c0 + 1] + bp2[c0 + 1];
    float2 oA, oB;
    oA.x = (acc[0] + bb0 * wsA) * invA;
    oA.y = (acc[1] + bb1 * wsA) * invA;
    oB.x = (acc[2] + bb0 * wsB) * invB;
    oB.y = (acc[3] + bb1 * wsB) * invB;
    *(float2*)&out[(size_t)mA * C_DIM + c0] = oA;
    *(float2*)&out[(size_t)mB * C_DIM + c0] = oB;
}

// ---------------- launch -----------------------------------------------------
extern "C" void kernel_launch(void* const* d_in, const int* in_sizes, int n_in,
                              void* d_out, int out_size) {
    const float* qf     = (const float*)d_in[0];
    const float* cf     = (const float*)d_in[1];
    const float* qc     = (const float*)d_in[2];
    const float* cc     = (const float*)d_in[3];
    const float* Wq     = (const float*)d_in[4];
    const float* bq     = (const float*)d_in[5];
    const float* gq     = (const float*)d_in[6];
    const float* betaq  = (const float*)d_in[7];
    const float* Wk     = (const float*)d_in[8];
    const float* bk     = (const float*)d_in[9];
    const float* gk     = (const float*)d_in[10];
    const float* betak  = (const float*)d_in[11];
    const float* Wv     = (const float*)d_in[12];
    const float* bv     = (const float*)d_in[13];
    const float* Wp1    = (const float*)d_in[14];
    const float* bp1    = (const float*)d_in[15];
    const float* gp1    = (const float*)d_in[16];
    const float* betap1 = (const float*)d_in[17];
    const float* Wp2    = (const float*)d_in[18];
    const float* bp2    = (const float*)d_in[19];
    const float* Ww1    = (const float*)d_in[20];
    const float* bw1    = (const float*)d_in[21];
    const float* gw1    = (const float*)d_in[22];
    const float* betaw1 = (const float*)d_in[23];
    const float* Ww2    = (const float*)d_in[24];
    const float* bw2    = (const float*)d_in[25];
    const int*   knn    = (const int*)d_in[26];
    float* out = (float*)d_out;

    const int M = in_sizes[0] / C_DIM;
    const int N = in_sizes[1] / C_DIM;
    const int NB = N / 64, MB = M / 64;

    k0w_prep<<<8, 256>>>(Wk, Wq);

    cudaFuncSetAttribute(k0_prep, cudaFuncAttributeMaxDynamicSharedMemorySize,
                         SMEM_K0_TOTAL);
    k0_prep<<<1, 256, SMEM_K0_TOTAL>>>(Wp2, Ww1, bp2);

    cudaFuncSetAttribute(k12_proj, cudaFuncAttributeMaxDynamicSharedMemorySize,
                         SMEM_K12_TOTAL);
    k12_proj<<<NB + MB, 256, SMEM_K12_TOTAL>>>(cf, qf, bk, gk, betak,
                                               bq, gq, betaq, Ww1, NB);

    k3_attn<<<M / 8, 128>>>(qc, cc, knn, cf, Wp1, bp1, gp1, betap1,
                            bw1, gw1, betaw1, Ww2, bw2);

    cudaFuncSetAttribute(k4_out, cudaFuncAttributeMaxDynamicSharedMemorySize,
                         SMEM_K4_TOTAL);
    dim3 g4(M / 64, G_DIM);
    k4_out<<<g4, 256, SMEM_K4_TOTAL>>>(Wv, Wp2, bv, bp2, out);
}